// round 1
// baseline (speedup 1.0000x reference)
#include <cuda_runtime.h>
#include <math.h>

#define D 768
#define BATCH 2
#define SEQ 2048
#define NROWS (BATCH*SEQ)   // 4096
#define NHEADS 12
#define HDIM 64
#define EPS 1e-5f

// ---------------- scratch (static device globals; no allocation) ----------------
__device__ float g_xn[NROWS*D];    // LN1 out, reused as LN2 out
__device__ float g_q[NROWS*D];
__device__ float g_k[NROWS*D];
__device__ float g_v[NROWS*D];
__device__ float g_attn[NROWS*D];  // attention output, reused as MLP hidden
__device__ float g_xmid[NROWS*D];  // x + attn@wo + bo

// ---------------- LayerNorm: one block (256 thr) per row of 768 ----------------
__global__ void ln_kernel(const float* __restrict__ x, const float* __restrict__ w,
                          const float* __restrict__ b, float* __restrict__ y) {
    __shared__ float sh_s[8], sh_ss[8];
    __shared__ float mu_sh, rstd_sh;
    int row = blockIdx.x;
    const float* xr = x + (size_t)row * D;
    int t = threadIdx.x;
    float v0 = xr[t], v1 = xr[t + 256], v2 = xr[t + 512];
    float s  = v0 + v1 + v2;
    float ss = v0*v0 + v1*v1 + v2*v2;
    #pragma unroll
    for (int o = 16; o > 0; o >>= 1) {
        s  += __shfl_xor_sync(0xffffffffu, s,  o);
        ss += __shfl_xor_sync(0xffffffffu, ss, o);
    }
    int wid = t >> 5, lane = t & 31;
    if (lane == 0) { sh_s[wid] = s; sh_ss[wid] = ss; }
    __syncthreads();
    if (t == 0) {
        float S = 0.f, SS = 0.f;
        #pragma unroll
        for (int i = 0; i < 8; i++) { S += sh_s[i]; SS += sh_ss[i]; }
        float mu = S / (float)D;
        float var = SS / (float)D - mu * mu;
        mu_sh = mu; rstd_sh = rsqrtf(var + EPS);
    }
    __syncthreads();
    float mu = mu_sh, rs = rstd_sh;
    float* yr = y + (size_t)row * D;
    yr[t]       = (v0 - mu) * rs * w[t]       + b[t];
    yr[t + 256] = (v1 - mu) * rs * w[t + 256] + b[t + 256];
    yr[t + 512] = (v2 - mu) * rs * w[t + 512] + b[t + 512];
}

// ---------------- SGEMM: C[N,768] = A[N,768] @ W[768,768] + bias (+res)(relu) ----
// 128x128 block tile, BK=8, 256 threads, 8x8 per thread.
__global__ void __launch_bounds__(256, 2)
sgemm_kernel(const float* __restrict__ A, const float* __restrict__ W,
             const float* __restrict__ bias, const float* __restrict__ res,
             float* __restrict__ C, int relu) {
    __shared__ float As[8][128];
    __shared__ float Bs[8][128];
    int t = threadIdx.x;
    int brow = blockIdx.y * 128, bcol = blockIdx.x * 128;
    int a_row = t >> 1,  a_col = (t & 1) * 4;
    int b_row = t >> 5,  b_col = (t & 31) * 4;
    int trow = (t >> 4) * 8, tcol = (t & 15) * 8;
    float acc[8][8];
    #pragma unroll
    for (int i = 0; i < 8; i++)
        #pragma unroll
        for (int j = 0; j < 8; j++) acc[i][j] = 0.f;

    for (int k0 = 0; k0 < D; k0 += 8) {
        float4 av = *(const float4*)(A + (size_t)(brow + a_row) * D + k0 + a_col);
        As[a_col + 0][a_row] = av.x;
        As[a_col + 1][a_row] = av.y;
        As[a_col + 2][a_row] = av.z;
        As[a_col + 3][a_row] = av.w;
        *(float4*)&Bs[b_row][b_col] =
            *(const float4*)(W + (size_t)(k0 + b_row) * D + bcol + b_col);
        __syncthreads();
        #pragma unroll
        for (int kk = 0; kk < 8; kk++) {
            float ar[8], br[8];
            *(float4*)&ar[0] = *(const float4*)&As[kk][trow];
            *(float4*)&ar[4] = *(const float4*)&As[kk][trow + 4];
            *(float4*)&br[0] = *(const float4*)&Bs[kk][tcol];
            *(float4*)&br[4] = *(const float4*)&Bs[kk][tcol + 4];
            #pragma unroll
            for (int i = 0; i < 8; i++)
                #pragma unroll
                for (int j = 0; j < 8; j++)
                    acc[i][j] = fmaf(ar[i], br[j], acc[i][j]);
        }
        __syncthreads();
    }
    #pragma unroll
    for (int i = 0; i < 8; i++) {
        int r = brow + trow + i;
        #pragma unroll
        for (int j4 = 0; j4 < 8; j4 += 4) {
            int c = bcol + tcol + j4;
            float4 bb = *(const float4*)(bias + c);
            float4 o;
            o.x = acc[i][j4 + 0] + bb.x;
            o.y = acc[i][j4 + 1] + bb.y;
            o.z = acc[i][j4 + 2] + bb.z;
            o.w = acc[i][j4 + 3] + bb.w;
            if (res) {
                float4 rv = *(const float4*)(res + (size_t)r * D + c);
                o.x += rv.x; o.y += rv.y; o.z += rv.z; o.w += rv.w;
            }
            if (relu) {
                o.x = fmaxf(o.x, 0.f); o.y = fmaxf(o.y, 0.f);
                o.z = fmaxf(o.z, 0.f); o.w = fmaxf(o.w, 0.f);
            }
            *(float4*)(C + (size_t)r * D + c) = o;
        }
    }
}

// ---------------- Flash attention: 64q x 64k tiles, online softmax --------------
// q,k,v in [N,768] layout (head h occupies cols h*64..h*64+63).
// bias [H,B,Sq,Sk], mask [1,B,Sq,Sk]. Softmax over (qk + bias, masked)/8.
// SMEM: Qt[64][64] (d-major), KtP[64][64] (K d-major, reused as P row-major),
//       Vs[64][64] (token-major) -> 48KB dynamic.
__global__ void __launch_bounds__(256)
attn_kernel(const float* __restrict__ q, const float* __restrict__ k,
            const float* __restrict__ v, const float* __restrict__ bias,
            const int* __restrict__ mask, float* __restrict__ out) {
    extern __shared__ float sm[];
    float* Qt  = sm;                 // [64][64] d-major
    float* KtP = sm + 64 * 64;       // K d-major / P row-major
    float* Vs  = sm + 2 * 64 * 64;   // [64][64] token-major

    int qt = blockIdx.x;             // query tile 0..31
    int hb = blockIdx.y;             // 0..23
    int h = hb >> 1;
    int b = hb & 1;

    int t = threadIdx.x;
    int tx = t & 15, ty = t >> 4;
    int r0 = ty * 4, c0 = tx * 4;

    const float* qbase = q + ((size_t)(b * SEQ + qt * 64)) * D + h * HDIM;
    const float* kbase = k + ((size_t)b * SEQ) * D + h * HDIM;
    const float* vbase = v + ((size_t)b * SEQ) * D + h * HDIM;
    const float* biasbase = bias + ((size_t)(h * BATCH + b) * SEQ + qt * 64) * SEQ;
    const int*   maskbase = mask + ((size_t)b * SEQ + qt * 64) * SEQ;

    // load Q tile transposed (d-major)
    #pragma unroll
    for (int l = 0; l < 4; l++) {
        int fi = t + 256 * l;         // 0..1023 float4 index
        int row = fi >> 4;            // 0..63 (query token in tile)
        int col = (fi & 15) * 4;      // d offset
        float4 qv = *(const float4*)(qbase + (size_t)row * D + col);
        Qt[(col + 0) * 64 + row] = qv.x;
        Qt[(col + 1) * 64 + row] = qv.y;
        Qt[(col + 2) * 64 + row] = qv.z;
        Qt[(col + 3) * 64 + row] = qv.w;
    }

    float m[4], lsum[4], O[4][4];
    #pragma unroll
    for (int i = 0; i < 4; i++) {
        m[i] = -1e30f; lsum[i] = 0.f;
        #pragma unroll
        for (int j = 0; j < 4; j++) O[i][j] = 0.f;
    }

    for (int kt = 0; kt < SEQ / 64; ++kt) {
        __syncthreads();   // previous-iter readers done; also orders Qt stores on kt=0
        // load K (transposed) and V tiles
        #pragma unroll
        for (int l = 0; l < 4; l++) {
            int fi = t + 256 * l;
            int row = fi >> 4;
            int col = (fi & 15) * 4;
            float4 kv = *(const float4*)(kbase + (size_t)(kt * 64 + row) * D + col);
            KtP[(col + 0) * 64 + row] = kv.x;
            KtP[(col + 1) * 64 + row] = kv.y;
            KtP[(col + 2) * 64 + row] = kv.z;
            KtP[(col + 3) * 64 + row] = kv.w;
            float4 vv = *(const float4*)(vbase + (size_t)(kt * 64 + row) * D + col);
            *(float4*)(Vs + row * 64 + col) = vv;
        }
        __syncthreads();

        // S = Q @ K^T  (outer product over d, both d-major => float4 row reads)
        float s[4][4];
        #pragma unroll
        for (int i = 0; i < 4; i++)
            #pragma unroll
            for (int j = 0; j < 4; j++) s[i][j] = 0.f;
        #pragma unroll 8
        for (int d = 0; d < 64; ++d) {
            float4 qv = *(const float4*)(Qt + d * 64 + r0);
            float4 kv = *(const float4*)(KtP + d * 64 + c0);
            float qa[4] = {qv.x, qv.y, qv.z, qv.w};
            float ka[4] = {kv.x, kv.y, kv.z, kv.w};
            #pragma unroll
            for (int i = 0; i < 4; i++)
                #pragma unroll
                for (int j = 0; j < 4; j++)
                    s[i][j] = fmaf(qa[i], ka[j], s[i][j]);
        }
        __syncthreads();   // done reading Kt; KtP becomes P storage

        // bias + mask + scale, online softmax update, write P
        #pragma unroll
        for (int i = 0; i < 4; i++) {
            int qrow = r0 + i;
            float4 bv = *(const float4*)(biasbase + (size_t)qrow * SEQ + kt * 64 + c0);
            int4   mv = *(const int4*)(maskbase + (size_t)qrow * SEQ + kt * 64 + c0);
            float sv[4];
            sv[0] = mv.x ? (s[i][0] + bv.x) * 0.125f : -1e30f;
            sv[1] = mv.y ? (s[i][1] + bv.y) * 0.125f : -1e30f;
            sv[2] = mv.z ? (s[i][2] + bv.z) * 0.125f : -1e30f;
            sv[3] = mv.w ? (s[i][3] + bv.w) * 0.125f : -1e30f;
            float mx = fmaxf(fmaxf(sv[0], sv[1]), fmaxf(sv[2], sv[3]));
            #pragma unroll
            for (int o = 8; o > 0; o >>= 1)
                mx = fmaxf(mx, __shfl_xor_sync(0xffffffffu, mx, o));
            float mn = fmaxf(m[i], mx);
            float alpha = __expf(m[i] - mn);
            m[i] = mn;
            float p[4], rs = 0.f;
            #pragma unroll
            for (int j = 0; j < 4; j++) { p[j] = __expf(sv[j] - mn); rs += p[j]; }
            #pragma unroll
            for (int o = 8; o > 0; o >>= 1)
                rs += __shfl_xor_sync(0xffffffffu, rs, o);
            lsum[i] = lsum[i] * alpha + rs;
            #pragma unroll
            for (int j = 0; j < 4; j++) O[i][j] *= alpha;
            *(float4*)(KtP + qrow * 64 + c0) = make_float4(p[0], p[1], p[2], p[3]);
        }
        __syncthreads();

        // O += P @ V
        #pragma unroll 8
        for (int kk = 0; kk < 64; ++kk) {
            float4 vv = *(const float4*)(Vs + kk * 64 + c0);
            float va[4] = {vv.x, vv.y, vv.z, vv.w};
            float pr[4];
            #pragma unroll
            for (int i = 0; i < 4; i++) pr[i] = KtP[(r0 + i) * 64 + kk];
            #pragma unroll
            for (int i = 0; i < 4; i++)
                #pragma unroll
                for (int j = 0; j < 4; j++)
                    O[i][j] = fmaf(pr[i], va[j], O[i][j]);
        }
    }

    // write normalized output into [B,S,H*HDIM] layout
    #pragma unroll
    for (int i = 0; i < 4; i++) {
        float inv = 1.0f / lsum[i];
        int grow = b * SEQ + qt * 64 + r0 + i;
        float4 ov = make_float4(O[i][0] * inv, O[i][1] * inv,
                                O[i][2] * inv, O[i][3] * inv);
        *(float4*)(out + (size_t)grow * D + h * HDIM + c0) = ov;
    }
}

// ---------------- host launcher --------------------------------------------------
extern "C" void kernel_launch(void* const* d_in, const int* in_sizes, int n_in,
                              void* d_out, int out_size) {
    const float* x     = (const float*)d_in[0];
    const float* bias  = (const float*)d_in[1];
    const int*   mask  = (const int*)d_in[2];
    const float* ln1_w = (const float*)d_in[3];
    const float* ln1_b = (const float*)d_in[4];
    const float* wq    = (const float*)d_in[5];
    const float* bq    = (const float*)d_in[6];
    const float* wk    = (const float*)d_in[7];
    const float* bk    = (const float*)d_in[8];
    const float* wv    = (const float*)d_in[9];
    const float* bv    = (const float*)d_in[10];
    const float* wo    = (const float*)d_in[11];
    const float* bo    = (const float*)d_in[12];
    const float* ln2_w = (const float*)d_in[13];
    const float* ln2_b = (const float*)d_in[14];
    const float* w1    = (const float*)d_in[15];
    const float* b1    = (const float*)d_in[16];
    const float* w2    = (const float*)d_in[17];
    const float* b2    = (const float*)d_in[18];
    float* out = (float*)d_out;

    float *xn, *qb, *kb, *vb, *attn, *xmid;
    cudaGetSymbolAddress((void**)&xn,   g_xn);
    cudaGetSymbolAddress((void**)&qb,   g_q);
    cudaGetSymbolAddress((void**)&kb,   g_k);
    cudaGetSymbolAddress((void**)&vb,   g_v);
    cudaGetSymbolAddress((void**)&attn, g_attn);
    cudaGetSymbolAddress((void**)&xmid, g_xmid);

    dim3 gemm_grid(D / 128, NROWS / 128);  // (6, 32)
    dim3 gemm_blk(256);

    // 1. LN1
    ln_kernel<<<NROWS, 256>>>(x, ln1_w, ln1_b, xn);
    // 2-4. Q,K,V projections
    sgemm_kernel<<<gemm_grid, gemm_blk>>>(xn, wq, bq, nullptr, qb, 0);
    sgemm_kernel<<<gemm_grid, gemm_blk>>>(xn, wk, bk, nullptr, kb, 0);
    sgemm_kernel<<<gemm_grid, gemm_blk>>>(xn, wv, bv, nullptr, vb, 0);
    // 5. attention (flash, bias+mask streamed)
    cudaFuncSetAttribute(attn_kernel, cudaFuncAttributeMaxDynamicSharedMemorySize,
                         3 * 64 * 64 * 4);
    dim3 attn_grid(SEQ / 64, NHEADS * BATCH);  // (32, 24)
    attn_kernel<<<attn_grid, 256, 3 * 64 * 64 * 4>>>(qb, kb, vb, bias, mask, attn);
    // 6. out-proj + residual(x)
    sgemm_kernel<<<gemm_grid, gemm_blk>>>(attn, wo, bo, x, xmid, 0);
    // 7. LN2 (reuse xn)
    ln_kernel<<<NROWS, 256>>>(xmid, ln2_w, ln2_b, xn);
    // 8. MLP up + ReLU (reuse attn as hidden)
    sgemm_kernel<<<gemm_grid, gemm_blk>>>(xn, w1, b1, nullptr, attn, 1);
    // 9. MLP down + residual(xmid) -> out
    sgemm_kernel<<<gemm_grid, gemm_blk>>>(attn, w2, b2, xmid, out, 0);
}

// round 3
// speedup vs baseline: 1.0150x; 1.0150x over previous
#include <cuda_runtime.h>
#include <stdint.h>
#include <math.h>

#define D 768
#define BATCH 2
#define SEQ 2048
#define NROWS (BATCH*SEQ)   // 4096
#define NHEADS 12
#define HDIM 64
#define EPS 1e-5f

// ---------------- scratch (static device globals; no allocation) ----------------
__device__ float g_xn[NROWS*D];    // LN1 out, reused as LN2 out
__device__ float g_q[NROWS*D];
__device__ float g_k[NROWS*D];
__device__ float g_v[NROWS*D];
__device__ float g_attn[NROWS*D];  // attention output, reused as MLP hidden
__device__ float g_xmid[NROWS*D];  // x + attn@wo + bo

// ---------------- cp.async helpers ----------------
__device__ __forceinline__ void cp_async16(uint32_t dst_smem, const void* src) {
    asm volatile("cp.async.ca.shared.global [%0], [%1], 16;\n" :: "r"(dst_smem), "l"(src));
}
__device__ __forceinline__ void cp_commit() {
    asm volatile("cp.async.commit_group;\n");
}
__device__ __forceinline__ void cp_wait0() {
    asm volatile("cp.async.wait_group 0;\n" ::: "memory");
}

// ---------------- LayerNorm: one block (256 thr) per row of 768 ----------------
__global__ void ln_kernel(const float* __restrict__ x, const float* __restrict__ w,
                          const float* __restrict__ b, float* __restrict__ y) {
    __shared__ float sh_s[8], sh_ss[8];
    __shared__ float mu_sh, rstd_sh;
    int row = blockIdx.x;
    const float* xr = x + (size_t)row * D;
    int t = threadIdx.x;
    float v0 = xr[t], v1 = xr[t + 256], v2 = xr[t + 512];
    float s  = v0 + v1 + v2;
    float ss = v0*v0 + v1*v1 + v2*v2;
    #pragma unroll
    for (int o = 16; o > 0; o >>= 1) {
        s  += __shfl_xor_sync(0xffffffffu, s,  o);
        ss += __shfl_xor_sync(0xffffffffu, ss, o);
    }
    int wid = t >> 5, lane = t & 31;
    if (lane == 0) { sh_s[wid] = s; sh_ss[wid] = ss; }
    __syncthreads();
    if (t == 0) {
        float S = 0.f, SS = 0.f;
        #pragma unroll
        for (int i = 0; i < 8; i++) { S += sh_s[i]; SS += sh_ss[i]; }
        float mu = S / (float)D;
        float var = SS / (float)D - mu * mu;
        mu_sh = mu; rstd_sh = rsqrtf(var + EPS);
    }
    __syncthreads();
    float mu = mu_sh, rs = rstd_sh;
    float* yr = y + (size_t)row * D;
    yr[t]       = (v0 - mu) * rs * w[t]       + b[t];
    yr[t + 256] = (v1 - mu) * rs * w[t + 256] + b[t + 256];
    yr[t + 512] = (v2 - mu) * rs * w[t + 512] + b[t + 512];
}

// ---------------- SGEMM core: 64x128 tile, BK=16, double-buffered -----------------
// 256 threads, 4x8 per thread. A [N,768] row-major, W [768,768] row-major.
__device__ __forceinline__ void gemm_tile(
    const float* __restrict__ A, const float* __restrict__ W,
    const float* __restrict__ bias, const float* __restrict__ res,
    float* __restrict__ C, int relu, int brow, int bcol,
    float (*As)[16][64], float (*Bs)[16][128])
{
    int t = threadIdx.x;
    int a_row = t >> 2,  a_col = (t & 3) * 4;     // A tile 64x16: 1 float4/thread
    int b_row = t >> 5,  b_col = (t & 31) * 4;    // B tile 16x128: 2 float4/thread
    int trow = (t >> 4) * 4, tcol = (t & 15) * 8;

    float acc[4][8];
    #pragma unroll
    for (int i = 0; i < 4; i++)
        #pragma unroll
        for (int j = 0; j < 8; j++) acc[i][j] = 0.f;

    const float* Abase = A + (size_t)(brow + a_row) * D + a_col;
    const float* Wb0 = W + (size_t)b_row * D + bcol + b_col;
    const float* Wb1 = W + (size_t)(b_row + 8) * D + bcol + b_col;

    // prologue: load chunk 0
    float4 a_st  = *(const float4*)(Abase);
    float4 b_st0 = *(const float4*)(Wb0);
    float4 b_st1 = *(const float4*)(Wb1);
    As[0][a_col + 0][a_row] = a_st.x;
    As[0][a_col + 1][a_row] = a_st.y;
    As[0][a_col + 2][a_row] = a_st.z;
    As[0][a_col + 3][a_row] = a_st.w;
    *(float4*)&Bs[0][b_row][b_col]     = b_st0;
    *(float4*)&Bs[0][b_row + 8][b_col] = b_st1;
    __syncthreads();

    #pragma unroll 1
    for (int chunk = 0; chunk < 48; chunk++) {
        int buf = chunk & 1;
        if (chunk < 47) {
            int kn = (chunk + 1) * 16;
            a_st  = *(const float4*)(Abase + kn);
            b_st0 = *(const float4*)(Wb0 + (size_t)kn * D);
            b_st1 = *(const float4*)(Wb1 + (size_t)kn * D);
        }
        #pragma unroll
        for (int kk = 0; kk < 16; kk++) {
            float4 av  = *(const float4*)&As[buf][kk][trow];
            float4 bv0 = *(const float4*)&Bs[buf][kk][tcol];
            float4 bv1 = *(const float4*)&Bs[buf][kk][tcol + 4];
            float ar[4] = {av.x, av.y, av.z, av.w};
            float br[8] = {bv0.x, bv0.y, bv0.z, bv0.w, bv1.x, bv1.y, bv1.z, bv1.w};
            #pragma unroll
            for (int i = 0; i < 4; i++)
                #pragma unroll
                for (int j = 0; j < 8; j++)
                    acc[i][j] = fmaf(ar[i], br[j], acc[i][j]);
        }
        if (chunk < 47) {
            int nb = buf ^ 1;
            As[nb][a_col + 0][a_row] = a_st.x;
            As[nb][a_col + 1][a_row] = a_st.y;
            As[nb][a_col + 2][a_row] = a_st.z;
            As[nb][a_col + 3][a_row] = a_st.w;
            *(float4*)&Bs[nb][b_row][b_col]     = b_st0;
            *(float4*)&Bs[nb][b_row + 8][b_col] = b_st1;
            __syncthreads();
        }
    }

    #pragma unroll
    for (int i = 0; i < 4; i++) {
        int r = brow + trow + i;
        #pragma unroll
        for (int j4 = 0; j4 < 8; j4 += 4) {
            int c = bcol + tcol + j4;
            float4 bb = *(const float4*)(bias + c);
            float4 o;
            o.x = acc[i][j4 + 0] + bb.x;
            o.y = acc[i][j4 + 1] + bb.y;
            o.z = acc[i][j4 + 2] + bb.z;
            o.w = acc[i][j4 + 3] + bb.w;
            if (res) {
                float4 rv = *(const float4*)(res + (size_t)r * D + c);
                o.x += rv.x; o.y += rv.y; o.z += rv.z; o.w += rv.w;
            }
            if (relu) {
                o.x = fmaxf(o.x, 0.f); o.y = fmaxf(o.y, 0.f);
                o.z = fmaxf(o.z, 0.f); o.w = fmaxf(o.w, 0.f);
            }
            *(float4*)(C + (size_t)r * D + c) = o;
        }
    }
}

__global__ void __launch_bounds__(256, 3)
sgemm_kernel(const float* __restrict__ A, const float* __restrict__ W,
             const float* __restrict__ bias, const float* __restrict__ res,
             float* __restrict__ C, int relu) {
    __shared__ float As[2][16][64];
    __shared__ float Bs[2][16][128];
    gemm_tile(A, W, bias, res, C, relu, blockIdx.y * 64, blockIdx.x * 128, As, Bs);
}

// Merged Q/K/V projection: grid.x = 18 (sel = x/6, col-tile = x%6)
__global__ void __launch_bounds__(256, 3)
qkv_kernel(const float* __restrict__ A,
           const float* __restrict__ wq, const float* __restrict__ wk, const float* __restrict__ wv,
           const float* __restrict__ bq, const float* __restrict__ bk, const float* __restrict__ bv,
           float* __restrict__ oq, float* __restrict__ ok, float* __restrict__ ov) {
    __shared__ float As[2][16][64];
    __shared__ float Bs[2][16][128];
    int sel = blockIdx.x / 6;
    int bcol = (blockIdx.x % 6) * 128;
    const float* W = (sel == 0) ? wq : (sel == 1) ? wk : wv;
    const float* bb = (sel == 0) ? bq : (sel == 1) ? bk : bv;
    float* C = (sel == 0) ? oq : (sel == 1) ? ok : ov;
    gemm_tile(A, W, bb, nullptr, C, 0, blockIdx.y * 64, bcol, As, Bs);
}

// ---------------- Flash attention: 64q x 64k tiles, online softmax --------------
// bias/mask prefetched into registers before S-compute; V via cp.async.
__global__ void __launch_bounds__(256, 2)
attn_kernel(const float* __restrict__ q, const float* __restrict__ k,
            const float* __restrict__ v, const float* __restrict__ bias,
            const int* __restrict__ mask, float* __restrict__ out) {
    __shared__ float Qt[64 * 64];    // d-major
    __shared__ float KtP[64 * 64];   // K d-major, reused as P row-major
    __shared__ float Vs[64 * 64];    // token-major

    int qt = blockIdx.x;             // query tile 0..31
    int hb = blockIdx.y;             // 0..23
    int h = hb >> 1;
    int b = hb & 1;

    int t = threadIdx.x;
    int tx = t & 15, ty = t >> 4;
    int r0 = ty * 4, c0 = tx * 4;

    const float* qbase = q + ((size_t)(b * SEQ + qt * 64)) * D + h * HDIM;
    const float* kbase = k + ((size_t)b * SEQ) * D + h * HDIM;
    const float* vbase = v + ((size_t)b * SEQ) * D + h * HDIM;
    const float* biasbase = bias + ((size_t)(h * BATCH + b) * SEQ + qt * 64) * SEQ;
    const int*   maskbase = mask + ((size_t)b * SEQ + qt * 64) * SEQ;

    uint32_t vs_smem = (uint32_t)__cvta_generic_to_shared(Vs);

    // load Q tile transposed (d-major)
    #pragma unroll
    for (int l = 0; l < 4; l++) {
        int fi = t + 256 * l;
        int row = fi >> 4;
        int col = (fi & 15) * 4;
        float4 qv = *(const float4*)(qbase + (size_t)row * D + col);
        Qt[(col + 0) * 64 + row] = qv.x;
        Qt[(col + 1) * 64 + row] = qv.y;
        Qt[(col + 2) * 64 + row] = qv.z;
        Qt[(col + 3) * 64 + row] = qv.w;
    }

    float m[4], lsum[4], O[4][4];
    #pragma unroll
    for (int i = 0; i < 4; i++) {
        m[i] = -1e30f; lsum[i] = 0.f;
        #pragma unroll
        for (int j = 0; j < 4; j++) O[i][j] = 0.f;
    }

    for (int kt = 0; kt < SEQ / 64; ++kt) {
        __syncthreads();   // prev-iter readers of KtP/Vs done; orders Qt stores on kt=0

        // V tile via cp.async (no transpose needed)
        #pragma unroll
        for (int l = 0; l < 4; l++) {
            int fi = t + 256 * l;
            int row = fi >> 4;
            int col = (fi & 15) * 4;
            cp_async16(vs_smem + (uint32_t)(row * 64 + col) * 4,
                       vbase + (size_t)(kt * 64 + row) * D + col);
        }
        cp_commit();

        // K tile: LDG -> transposed STS
        #pragma unroll
        for (int l = 0; l < 4; l++) {
            int fi = t + 256 * l;
            int row = fi >> 4;
            int col = (fi & 15) * 4;
            float4 kv = *(const float4*)(kbase + (size_t)(kt * 64 + row) * D + col);
            KtP[(col + 0) * 64 + row] = kv.x;
            KtP[(col + 1) * 64 + row] = kv.y;
            KtP[(col + 2) * 64 + row] = kv.z;
            KtP[(col + 3) * 64 + row] = kv.w;
        }

        // prefetch bias/mask for this tile into registers (hidden under S compute)
        float4 breg[4];
        int4   mreg[4];
        #pragma unroll
        for (int i = 0; i < 4; i++) {
            int qrow = r0 + i;
            breg[i] = *(const float4*)(biasbase + (size_t)qrow * SEQ + kt * 64 + c0);
            mreg[i] = *(const int4*)(maskbase + (size_t)qrow * SEQ + kt * 64 + c0);
        }

        cp_wait0();
        __syncthreads();

        // S = Q @ K^T
        float s[4][4];
        #pragma unroll
        for (int i = 0; i < 4; i++)
            #pragma unroll
            for (int j = 0; j < 4; j++) s[i][j] = 0.f;
        #pragma unroll 8
        for (int d = 0; d < 64; ++d) {
            float4 qv = *(const float4*)(Qt + d * 64 + r0);
            float4 kv = *(const float4*)(KtP + d * 64 + c0);
            float qa[4] = {qv.x, qv.y, qv.z, qv.w};
            float ka[4] = {kv.x, kv.y, kv.z, kv.w};
            #pragma unroll
            for (int i = 0; i < 4; i++)
                #pragma unroll
                for (int j = 0; j < 4; j++)
                    s[i][j] = fmaf(qa[i], ka[j], s[i][j]);
        }
        __syncthreads();   // done reading Kt; KtP becomes P storage

        // bias + mask + scale, online softmax update, write P
        #pragma unroll
        for (int i = 0; i < 4; i++) {
            int qrow = r0 + i;
            float sv[4];
            sv[0] = mreg[i].x ? (s[i][0] + breg[i].x) * 0.125f : -1e30f;
            sv[1] = mreg[i].y ? (s[i][1] + breg[i].y) * 0.125f : -1e30f;
            sv[2] = mreg[i].z ? (s[i][2] + breg[i].z) * 0.125f : -1e30f;
            sv[3] = mreg[i].w ? (s[i][3] + breg[i].w) * 0.125f : -1e30f;
            float mx = fmaxf(fmaxf(sv[0], sv[1]), fmaxf(sv[2], sv[3]));
            #pragma unroll
            for (int o = 8; o > 0; o >>= 1)
                mx = fmaxf(mx, __shfl_xor_sync(0xffffffffu, mx, o));
            float mn = fmaxf(m[i], mx);
            float alpha = __expf(m[i] - mn);
            m[i] = mn;
            float p[4], rs = 0.f;
            #pragma unroll
            for (int j = 0; j < 4; j++) { p[j] = __expf(sv[j] - mn); rs += p[j]; }
            #pragma unroll
            for (int o = 8; o > 0; o >>= 1)
                rs += __shfl_xor_sync(0xffffffffu, rs, o);
            lsum[i] = lsum[i] * alpha + rs;
            #pragma unroll
            for (int j = 0; j < 4; j++) O[i][j] *= alpha;
            *(float4*)(KtP + qrow * 64 + c0) = make_float4(p[0], p[1], p[2], p[3]);
        }
        __syncthreads();

        // O += P @ V
        #pragma unroll 8
        for (int kk = 0; kk < 64; ++kk) {
            float4 vv = *(const float4*)(Vs + kk * 64 + c0);
            float va[4] = {vv.x, vv.y, vv.z, vv.w};
            float pr[4];
            #pragma unroll
            for (int i = 0; i < 4; i++) pr[i] = KtP[(r0 + i) * 64 + kk];
            #pragma unroll
            for (int i = 0; i < 4; i++)
                #pragma unroll
                for (int j = 0; j < 4; j++)
                    O[i][j] = fmaf(pr[i], va[j], O[i][j]);
        }
    }

    // write normalized output into [B,S,H*HDIM] layout
    #pragma unroll
    for (int i = 0; i < 4; i++) {
        float inv = 1.0f / lsum[i];
        int grow = b * SEQ + qt * 64 + r0 + i;
        float4 ov = make_float4(O[i][0] * inv, O[i][1] * inv,
                                O[i][2] * inv, O[i][3] * inv);
        *(float4*)(out + (size_t)grow * D + h * HDIM + c0) = ov;
    }
}

// ---------------- host launcher --------------------------------------------------
extern "C" void kernel_launch(void* const* d_in, const int* in_sizes, int n_in,
                              void* d_out, int out_size) {
    const float* x     = (const float*)d_in[0];
    const float* bias  = (const float*)d_in[1];
    const int*   mask  = (const int*)d_in[2];
    const float* ln1_w = (const float*)d_in[3];
    const float* ln1_b = (const float*)d_in[4];
    const float* wq    = (const float*)d_in[5];
    const float* bq    = (const float*)d_in[6];
    const float* wk    = (const float*)d_in[7];
    const float* bk    = (const float*)d_in[8];
    const float* wv    = (const float*)d_in[9];
    const float* bv    = (const float*)d_in[10];
    const float* wo    = (const float*)d_in[11];
    const float* bo    = (const float*)d_in[12];
    const float* ln2_w = (const float*)d_in[13];
    const float* ln2_b = (const float*)d_in[14];
    const float* w1    = (const float*)d_in[15];
    const float* b1    = (const float*)d_in[16];
    const float* w2    = (const float*)d_in[17];
    const float* b2    = (const float*)d_in[18];
    float* out = (float*)d_out;

    float *xn, *qb, *kb, *vb, *attn, *xmid;
    cudaGetSymbolAddress((void**)&xn,   g_xn);
    cudaGetSymbolAddress((void**)&qb,   g_q);
    cudaGetSymbolAddress((void**)&kb,   g_k);
    cudaGetSymbolAddress((void**)&vb,   g_v);
    cudaGetSymbolAddress((void**)&attn, g_attn);
    cudaGetSymbolAddress((void**)&xmid, g_xmid);

    dim3 gemm_grid(D / 128, NROWS / 64);   // (6, 64) = 384 CTAs
    dim3 qkv_grid(3 * D / 128, NROWS / 64); // (18, 64) = 1152 CTAs
    dim3 blk(256);

    // 1. LN1
    ln_kernel<<<NROWS, 256>>>(x, ln1_w, ln1_b, xn);
    // 2. merged Q,K,V projections
    qkv_kernel<<<qkv_grid, blk>>>(xn, wq, wk, wv, bq, bk, bv, qb, kb, vb);
    // 3. attention (flash, bias+mask streamed, prefetched)
    dim3 attn_grid(SEQ / 64, NHEADS * BATCH);  // (32, 24)
    attn_kernel<<<attn_grid, 256>>>(qb, kb, vb, bias, mask, attn);
    // 4. out-proj + residual(x)
    sgemm_kernel<<<gemm_grid, blk>>>(attn, wo, bo, x, xmid, 0);
    // 5. LN2 (reuse xn)
    ln_kernel<<<NROWS, 256>>>(xmid, ln2_w, ln2_b, xn);
    // 6. MLP up + ReLU (reuse attn as hidden)
    sgemm_kernel<<<gemm_grid, blk>>>(xn, w1, b1, nullptr, attn, 1);
    // 7. MLP down + residual(xmid) -> out
    sgemm_kernel<<<gemm_grid, blk>>>(attn, w2, b2, xmid, out, 0);
}

// round 5
// speedup vs baseline: 1.5796x; 1.5562x over previous
#include <cuda_runtime.h>
#include <cuda_bf16.h>
#include <stdint.h>
#include <math.h>

#define D 768
#define BATCH 2
#define SEQ 2048
#define NROWS (BATCH*SEQ)   // 4096
#define NHEADS 12
#define HDIM 64
#define EPS 1e-5f

#define MT 128              // CTA M tile
#define NT 64               // CTA N tile
#define BK 32
#define KSTAGES (D/BK)      // 24

// ---------------- scratch ----------------
__device__ float g_q[NROWS*D];
__device__ float g_k[NROWS*D];
__device__ float g_v[NROWS*D];
__device__ float g_xmid[NROWS*D];
__device__ __nv_bfloat16 g_xnh[NROWS*D], g_xnl[NROWS*D];
__device__ __nv_bfloat16 g_ah[NROWS*D],  g_al[NROWS*D];
__device__ __nv_bfloat16 g_hh[NROWS*D],  g_hl[NROWS*D];
__device__ __nv_bfloat16 g_wth[6*D*D], g_wtl[6*D*D];

// ---------------- PTX helpers ----------------
__device__ __forceinline__ uint32_t smem_u32(const void* p) {
    uint32_t a;
    asm("{ .reg .u64 t; cvta.to.shared.u64 t, %1; cvt.u32.u64 %0, t; }" : "=r"(a) : "l"(p));
    return a;
}
__device__ __forceinline__ void cp_async16(uint32_t dst, const void* src) {
    asm volatile("cp.async.ca.shared.global [%0], [%1], 16;\n" :: "r"(dst), "l"(src));
}
__device__ __forceinline__ void cp_commit() { asm volatile("cp.async.commit_group;\n"); }
__device__ __forceinline__ void cp_wait0()  { asm volatile("cp.async.wait_group 0;\n" ::: "memory"); }
__device__ __forceinline__ void cp_wait1()  { asm volatile("cp.async.wait_group 1;\n" ::: "memory"); }

__device__ __forceinline__ void ldsm_x4(uint32_t addr, uint32_t& r0, uint32_t& r1,
                                        uint32_t& r2, uint32_t& r3) {
    asm volatile("ldmatrix.sync.aligned.m8n8.x4.shared.b16 {%0,%1,%2,%3}, [%4];"
                 : "=r"(r0), "=r"(r1), "=r"(r2), "=r"(r3) : "r"(addr));
}
__device__ __forceinline__ void mma_bf16(float* c, const uint32_t* a, uint32_t b0, uint32_t b1) {
    asm volatile("mma.sync.aligned.m16n8k16.row.col.f32.bf16.bf16.f32 "
                 "{%0,%1,%2,%3},{%4,%5,%6,%7},{%8,%9},{%0,%1,%2,%3};"
                 : "+f"(c[0]), "+f"(c[1]), "+f"(c[2]), "+f"(c[3])
                 : "r"(a[0]), "r"(a[1]), "r"(a[2]), "r"(a[3]), "r"(b0), "r"(b1));
}

// ---------------- split helpers ----------------
__device__ __forceinline__ void split_bf16(float v, __nv_bfloat16& h, __nv_bfloat16& l) {
    h = __float2bfloat16(v);
    l = __float2bfloat16(v - __bfloat162float(h));
}

// ---------------- weight transpose + split ----------------
__global__ void transpose_split(const float* __restrict__ W,
                                __nv_bfloat16* __restrict__ Th,
                                __nv_bfloat16* __restrict__ Tl) {
    __shared__ float tile[32][33];
    int bx = blockIdx.x * 32, by = blockIdx.y * 32;
    int tx = threadIdx.x, ty = threadIdx.y;
    #pragma unroll
    for (int i = 0; i < 4; i++)
        tile[ty + 8*i][tx] = W[(size_t)(by + ty + 8*i) * D + bx + tx];
    __syncthreads();
    #pragma unroll
    for (int i = 0; i < 4; i++) {
        float v = tile[tx][ty + 8*i];
        __nv_bfloat16 h, l; split_bf16(v, h, l);
        size_t idx = (size_t)(bx + ty + 8*i) * D + by + tx;
        Th[idx] = h; Tl[idx] = l;
    }
}

// ---------------- LayerNorm -> bf16 hi/lo ----------------
__global__ void ln_split(const float* __restrict__ x, const float* __restrict__ w,
                         const float* __restrict__ b,
                         __nv_bfloat16* __restrict__ yh, __nv_bfloat16* __restrict__ yl) {
    __shared__ float sh_s[8], sh_ss[8];
    __shared__ float mu_sh, rstd_sh;
    int row = blockIdx.x;
    const float* xr = x + (size_t)row * D;
    int t = threadIdx.x;
    float v0 = xr[t], v1 = xr[t + 256], v2 = xr[t + 512];
    float s  = v0 + v1 + v2;
    float ss = v0*v0 + v1*v1 + v2*v2;
    #pragma unroll
    for (int o = 16; o > 0; o >>= 1) {
        s  += __shfl_xor_sync(0xffffffffu, s,  o);
        ss += __shfl_xor_sync(0xffffffffu, ss, o);
    }
    int wid = t >> 5, lane = t & 31;
    if (lane == 0) { sh_s[wid] = s; sh_ss[wid] = ss; }
    __syncthreads();
    if (t == 0) {
        float S = 0.f, SS = 0.f;
        #pragma unroll
        for (int i = 0; i < 8; i++) { S += sh_s[i]; SS += sh_ss[i]; }
        float mu = S / (float)D;
        float var = SS / (float)D - mu * mu;
        mu_sh = mu; rstd_sh = rsqrtf(var + EPS);
    }
    __syncthreads();
    float mu = mu_sh, rs = rstd_sh;
    size_t base = (size_t)row * D;
    #pragma unroll
    for (int i = 0; i < 3; i++) {
        int c = t + 256 * i;
        float v = (i == 0) ? v0 : (i == 1) ? v1 : v2;
        float o = (v - mu) * rs * w[c] + b[c];
        __nv_bfloat16 h, l; split_bf16(o, h, l);
        yh[base + c] = h; yl[base + c] = l;
    }
}

// ---------------- HMMA split-precision GEMM ----------------
// C[4096,768] = (Ah+Al) @ (Bh+Bl)^T + bias (+res)(relu); Bt[n][k].
// CTA 128x64, 8 warps (4Mx2N), warp 32x32, BK=32, 2-stage cp.async pipeline.
// SMEM stage: Ah/Al 128x32 bf16 (8KB each), Bh/Bl 64x32 (4KB each) = 24KB; x2 = 48KB.
#define STG 24576
#define OFF_AH 0
#define OFF_AL 8192
#define OFF_BH 16384
#define OFF_BL 20480
#define GSMEM  (2*STG)

__global__ void __launch_bounds__(256, 2)
hmma_gemm(const __nv_bfloat16* __restrict__ Ah, const __nv_bfloat16* __restrict__ Al,
          const __nv_bfloat16* __restrict__ Bh, const __nv_bfloat16* __restrict__ Bl,
          const float* __restrict__ bias, const float* __restrict__ res,
          float* __restrict__ Cf, __nv_bfloat16* __restrict__ Ch,
          __nv_bfloat16* __restrict__ Cl, int relu)
{
    extern __shared__ char smem[];
    uint32_t sb = smem_u32(smem);
    int t = threadIdx.x;
    int wid = t >> 5, lane = t & 31;
    int wm = wid & 3, wn = wid >> 2;
    int brow = blockIdx.y * MT;
    int bcol = blockIdx.x * NT;

    float acc[2][4][4];
    #pragma unroll
    for (int i = 0; i < 2; i++)
        #pragma unroll
        for (int j = 0; j < 4; j++)
            #pragma unroll
            for (int c = 0; c < 4; c++) acc[i][j][c] = 0.f;

    // ---- stage loader (cp.async) ----
    auto load_stage = [&](int s) {
        uint32_t base = sb + (uint32_t)((s & 1) * STG);
        int k0 = s * BK;
        // A: 128x32 -> 512 chunks of 16B, 2 per thread (hi & lo)
        #pragma unroll
        for (int i = 0; i < 2; i++) {
            int id = t + i * 256;
            int r = id >> 2, c = id & 3;
            uint32_t so = (uint32_t)(r * 64 + ((c ^ ((r >> 1) & 3)) * 16));
            size_t g = (size_t)(brow + r) * D + k0 + c * 8;
            cp_async16(base + OFF_AH + so, Ah + g);
            cp_async16(base + OFF_AL + so, Al + g);
        }
        // B: 64x32 -> 256 chunks, 1 per thread (hi & lo)
        {
            int r = t >> 2, c = t & 3;
            uint32_t so = (uint32_t)(r * 64 + ((c ^ ((r >> 1) & 3)) * 16));
            size_t g = (size_t)(bcol + r) * D + k0 + c * 8;
            cp_async16(base + OFF_BH + so, Bh + g);
            cp_async16(base + OFF_BL + so, Bl + g);
        }
        cp_commit();
    };

    load_stage(0);

    for (int s = 0; s < KSTAGES; s++) {
        if (s < KSTAGES - 1) load_stage(s + 1);
        if (s < KSTAGES - 1) cp_wait1(); else cp_wait0();
        __syncthreads();

        uint32_t base = sb + (uint32_t)((s & 1) * STG);
        #pragma unroll
        for (int kstep = 0; kstep < 2; kstep++) {
            // A fragments: 2 m16 tiles, hi & lo
            uint32_t ah[2][4], al_[2][4];
            #pragma unroll
            for (int mt = 0; mt < 2; mt++) {
                int row = wm * 32 + mt * 16 + (lane & 15);
                int chunk = kstep * 2 + (lane >> 4);
                uint32_t so = (uint32_t)(row * 64 + ((chunk ^ ((row >> 1) & 3)) * 16));
                ldsm_x4(base + OFF_AH + so, ah[mt][0],  ah[mt][1],  ah[mt][2],  ah[mt][3]);
                ldsm_x4(base + OFF_AL + so, al_[mt][0], al_[mt][1], al_[mt][2], al_[mt][3]);
            }
            // B fragments: 2 x4 loads cover n32, hi & lo
            uint32_t bh[2][4], bl[2][4];
            #pragma unroll
            for (int nt2 = 0; nt2 < 2; nt2++) {
                int row = wn * 32 + nt2 * 16 + (lane & 7) + ((lane & 16) ? 8 : 0);
                int chunk = kstep * 2 + ((lane >> 3) & 1);
                uint32_t so = (uint32_t)(row * 64 + ((chunk ^ ((row >> 1) & 3)) * 16));
                ldsm_x4(base + OFF_BH + so, bh[nt2][0], bh[nt2][1], bh[nt2][2], bh[nt2][3]);
                ldsm_x4(base + OFF_BL + so, bl[nt2][0], bl[nt2][1], bl[nt2][2], bl[nt2][3]);
            }
            #pragma unroll
            for (int mt = 0; mt < 2; mt++)
                #pragma unroll
                for (int nt = 0; nt < 4; nt++) {
                    float* c = acc[mt][nt];
                    uint32_t b0h = bh[nt >> 1][(nt & 1) * 2], b1h = bh[nt >> 1][(nt & 1) * 2 + 1];
                    uint32_t b0l = bl[nt >> 1][(nt & 1) * 2], b1l = bl[nt >> 1][(nt & 1) * 2 + 1];
                    mma_bf16(c, ah[mt],  b0h, b1h);
                    mma_bf16(c, ah[mt],  b0l, b1l);
                    mma_bf16(c, al_[mt], b0h, b1h);
                }
        }
        __syncthreads();
    }

    // ---- epilogue ----
    #pragma unroll
    for (int mt = 0; mt < 2; mt++) {
        #pragma unroll
        for (int nt = 0; nt < 4; nt++) {
            float* c = acc[mt][nt];
            int col = bcol + wn * 32 + nt * 8 + (lane & 3) * 2;
            #pragma unroll
            for (int half = 0; half < 2; half++) {
                int row = brow + wm * 32 + mt * 16 + (lane >> 2) + half * 8;
                float2 o;
                o.x = c[half * 2 + 0];
                o.y = c[half * 2 + 1];
                const float2 bb = *(const float2*)(bias + col);
                o.x += bb.x; o.y += bb.y;
                size_t gidx = (size_t)row * D + col;
                if (res) {
                    float2 rv = *(const float2*)(res + gidx);
                    o.x += rv.x; o.y += rv.y;
                }
                if (relu) { o.x = fmaxf(o.x, 0.f); o.y = fmaxf(o.y, 0.f); }
                if (Cf) *(float2*)(Cf + gidx) = o;
                if (Ch) {
                    __nv_bfloat16 h0, l0, h1, l1;
                    split_bf16(o.x, h0, l0);
                    split_bf16(o.y, h1, l1);
                    __nv_bfloat162 hp; hp.x = h0; hp.y = h1;
                    __nv_bfloat162 lp; lp.x = l0; lp.y = l1;
                    *(__nv_bfloat162*)(Ch + gidx) = hp;
                    *(__nv_bfloat162*)(Cl + gidx) = lp;
                }
            }
        }
    }
}

// ---------------- Flash attention (fp32 SIMT), outputs bf16 hi/lo ----------------
__global__ void __launch_bounds__(256, 2)
attn_kernel(const float* __restrict__ q, const float* __restrict__ k,
            const float* __restrict__ v, const float* __restrict__ bias,
            const int* __restrict__ mask,
            __nv_bfloat16* __restrict__ outh, __nv_bfloat16* __restrict__ outl) {
    __shared__ float Qt[64 * 64];
    __shared__ float KtP[64 * 64];
    __shared__ float Vs[64 * 64];

    int qt = blockIdx.x;
    int hb = blockIdx.y;
    int h = hb >> 1;
    int b = hb & 1;

    int t = threadIdx.x;
    int tx = t & 15, ty = t >> 4;
    int r0 = ty * 4, c0 = tx * 4;

    const float* qbase = q + ((size_t)(b * SEQ + qt * 64)) * D + h * HDIM;
    const float* kbase = k + ((size_t)b * SEQ) * D + h * HDIM;
    const float* vbase = v + ((size_t)b * SEQ) * D + h * HDIM;
    const float* biasbase = bias + ((size_t)(h * BATCH + b) * SEQ + qt * 64) * SEQ;
    const int*   maskbase = mask + ((size_t)b * SEQ + qt * 64) * SEQ;

    uint32_t vs_smem = smem_u32(Vs);

    #pragma unroll
    for (int l = 0; l < 4; l++) {
        int fi = t + 256 * l;
        int row = fi >> 4;
        int col = (fi & 15) * 4;
        float4 qv = *(const float4*)(qbase + (size_t)row * D + col);
        Qt[(col + 0) * 64 + row] = qv.x;
        Qt[(col + 1) * 64 + row] = qv.y;
        Qt[(col + 2) * 64 + row] = qv.z;
        Qt[(col + 3) * 64 + row] = qv.w;
    }

    float m[4], lsum[4], O[4][4];
    #pragma unroll
    for (int i = 0; i < 4; i++) {
        m[i] = -1e30f; lsum[i] = 0.f;
        #pragma unroll
        for (int j = 0; j < 4; j++) O[i][j] = 0.f;
    }

    for (int kt = 0; kt < SEQ / 64; ++kt) {
        __syncthreads();
        #pragma unroll
        for (int l = 0; l < 4; l++) {
            int fi = t + 256 * l;
            int row = fi >> 4;
            int col = (fi & 15) * 4;
            cp_async16(vs_smem + (uint32_t)(row * 64 + col) * 4,
                       vbase + (size_t)(kt * 64 + row) * D + col);
        }
        cp_commit();
        #pragma unroll
        for (int l = 0; l < 4; l++) {
            int fi = t + 256 * l;
            int row = fi >> 4;
            int col = (fi & 15) * 4;
            float4 kv = *(const float4*)(kbase + (size_t)(kt * 64 + row) * D + col);
            KtP[(col + 0) * 64 + row] = kv.x;
            KtP[(col + 1) * 64 + row] = kv.y;
            KtP[(col + 2) * 64 + row] = kv.z;
            KtP[(col + 3) * 64 + row] = kv.w;
        }
        float4 breg[4];
        int4   mreg[4];
        #pragma unroll
        for (int i = 0; i < 4; i++) {
            int qrow = r0 + i;
            breg[i] = *(const float4*)(biasbase + (size_t)qrow * SEQ + kt * 64 + c0);
            mreg[i] = *(const int4*)(maskbase + (size_t)qrow * SEQ + kt * 64 + c0);
        }
        cp_wait0();
        __syncthreads();

        float s[4][4];
        #pragma unroll
        for (int i = 0; i < 4; i++)
            #pragma unroll
            for (int j = 0; j < 4; j++) s[i][j] = 0.f;
        #pragma unroll 8
        for (int d = 0; d < 64; ++d) {
            float4 qv = *(const float4*)(Qt + d * 64 + r0);
            float4 kv = *(const float4*)(KtP + d * 64 + c0);
            float qa[4] = {qv.x, qv.y, qv.z, qv.w};
            float ka[4] = {kv.x, kv.y, kv.z, kv.w};
            #pragma unroll
            for (int i = 0; i < 4; i++)
                #pragma unroll
                for (int j = 0; j < 4; j++)
                    s[i][j] = fmaf(qa[i], ka[j], s[i][j]);
        }
        __syncthreads();

        #pragma unroll
        for (int i = 0; i < 4; i++) {
            int qrow = r0 + i;
            float sv[4];
            sv[0] = mreg[i].x ? (s[i][0] + breg[i].x) * 0.125f : -1e30f;
            sv[1] = mreg[i].y ? (s[i][1] + breg[i].y) * 0.125f : -1e30f;
            sv[2] = mreg[i].z ? (s[i][2] + breg[i].z) * 0.125f : -1e30f;
            sv[3] = mreg[i].w ? (s[i][3] + breg[i].w) * 0.125f : -1e30f;
            float mx = fmaxf(fmaxf(sv[0], sv[1]), fmaxf(sv[2], sv[3]));
            #pragma unroll
            for (int o = 8; o > 0; o >>= 1)
                mx = fmaxf(mx, __shfl_xor_sync(0xffffffffu, mx, o));
            float mn = fmaxf(m[i], mx);
            float alpha = __expf(m[i] - mn);
            m[i] = mn;
            float p[4], rs = 0.f;
            #pragma unroll
            for (int j = 0; j < 4; j++) { p[j] = __expf(sv[j] - mn); rs += p[j]; }
            #pragma unroll
            for (int o = 8; o > 0; o >>= 1)
                rs += __shfl_xor_sync(0xffffffffu, rs, o);
            lsum[i] = lsum[i] * alpha + rs;
            #pragma unroll
            for (int j = 0; j < 4; j++) O[i][j] *= alpha;
            *(float4*)(KtP + qrow * 64 + c0) = make_float4(p[0], p[1], p[2], p[3]);
        }
        __syncthreads();

        #pragma unroll 8
        for (int kk = 0; kk < 64; ++kk) {
            float4 vv = *(const float4*)(Vs + kk * 64 + c0);
            float va[4] = {vv.x, vv.y, vv.z, vv.w};
            float pr[4];
            #pragma unroll
            for (int i = 0; i < 4; i++) pr[i] = KtP[(r0 + i) * 64 + kk];
            #pragma unroll
            for (int i = 0; i < 4; i++)
                #pragma unroll
                for (int j = 0; j < 4; j++)
                    O[i][j] = fmaf(pr[i], va[j], O[i][j]);
        }
    }

    #pragma unroll
    for (int i = 0; i < 4; i++) {
        float inv = 1.0f / lsum[i];
        int grow = b * SEQ + qt * 64 + r0 + i;
        size_t base = (size_t)grow * D + h * HDIM + c0;
        #pragma unroll
        for (int j = 0; j < 4; j += 2) {
            float v0 = O[i][j] * inv, v1 = O[i][j + 1] * inv;
            __nv_bfloat16 h0, l0, h1, l1;
            split_bf16(v0, h0, l0);
            split_bf16(v1, h1, l1);
            __nv_bfloat162 hp; hp.x = h0; hp.y = h1;
            __nv_bfloat162 lp; lp.x = l0; lp.y = l1;
            *(__nv_bfloat162*)(outh + base + j) = hp;
            *(__nv_bfloat162*)(outl + base + j) = lp;
        }
    }
}

// ---------------- host launcher --------------------------------------------------
extern "C" void kernel_launch(void* const* d_in, const int* in_sizes, int n_in,
                              void* d_out, int out_size) {
    const float* x     = (const float*)d_in[0];
    const float* bias  = (const float*)d_in[1];
    const int*   mask  = (const int*)d_in[2];
    const float* ln1_w = (const float*)d_in[3];
    const float* ln1_b = (const float*)d_in[4];
    const float* wq    = (const float*)d_in[5];
    const float* bq    = (const float*)d_in[6];
    const float* wk    = (const float*)d_in[7];
    const float* bk    = (const float*)d_in[8];
    const float* wv    = (const float*)d_in[9];
    const float* bv    = (const float*)d_in[10];
    const float* wo    = (const float*)d_in[11];
    const float* bo    = (const float*)d_in[12];
    const float* ln2_w = (const float*)d_in[13];
    const float* ln2_b = (const float*)d_in[14];
    const float* w1    = (const float*)d_in[15];
    const float* b1    = (const float*)d_in[16];
    const float* w2    = (const float*)d_in[17];
    const float* b2    = (const float*)d_in[18];
    float* out = (float*)d_out;

    float *qf, *kf, *vf, *xmid;
    __nv_bfloat16 *xnh, *xnl, *ah, *al, *hh, *hl, *wth, *wtl;
    cudaGetSymbolAddress((void**)&qf,   g_q);
    cudaGetSymbolAddress((void**)&kf,   g_k);
    cudaGetSymbolAddress((void**)&vf,   g_v);
    cudaGetSymbolAddress((void**)&xmid, g_xmid);
    cudaGetSymbolAddress((void**)&xnh,  g_xnh);
    cudaGetSymbolAddress((void**)&xnl,  g_xnl);
    cudaGetSymbolAddress((void**)&ah,   g_ah);
    cudaGetSymbolAddress((void**)&al,   g_al);
    cudaGetSymbolAddress((void**)&hh,   g_hh);
    cudaGetSymbolAddress((void**)&hl,   g_hl);
    cudaGetSymbolAddress((void**)&wth,  g_wth);
    cudaGetSymbolAddress((void**)&wtl,  g_wtl);

    cudaFuncSetAttribute(hmma_gemm, cudaFuncAttributeMaxDynamicSharedMemorySize, GSMEM);

    dim3 tgrid(24, 24), tblk(32, 8);
    const float* ws[6] = {wq, wk, wv, wo, w1, w2};
    for (int i = 0; i < 6; i++)
        transpose_split<<<tgrid, tblk>>>(ws[i], wth + (size_t)i * D * D, wtl + (size_t)i * D * D);

    dim3 ggrid(D / NT, NROWS / MT);   // (12, 32)

    // LN1 -> split
    ln_split<<<NROWS, 256>>>(x, ln1_w, ln1_b, xnh, xnl);
    // QKV projections (fp32 out)
    hmma_gemm<<<ggrid, 256, GSMEM>>>(xnh, xnl, wth + 0*(size_t)D*D, wtl + 0*(size_t)D*D,
                                     bq, nullptr, qf, nullptr, nullptr, 0);
    hmma_gemm<<<ggrid, 256, GSMEM>>>(xnh, xnl, wth + 1*(size_t)D*D, wtl + 1*(size_t)D*D,
                                     bk, nullptr, kf, nullptr, nullptr, 0);
    hmma_gemm<<<ggrid, 256, GSMEM>>>(xnh, xnl, wth + 2*(size_t)D*D, wtl + 2*(size_t)D*D,
                                     bv, nullptr, vf, nullptr, nullptr, 0);
    // attention -> bf16 split out
    dim3 attn_grid(SEQ / 64, NHEADS * BATCH);
    attn_kernel<<<attn_grid, 256>>>(qf, kf, vf, bias, mask, ah, al);
    // out-proj + residual(x) -> xmid (fp32)
    hmma_gemm<<<ggrid, 256, GSMEM>>>(ah, al, wth + 3*(size_t)D*D, wtl + 3*(size_t)D*D,
                                     bo, x, xmid, nullptr, nullptr, 0);
    // LN2 -> split
    ln_split<<<NROWS, 256>>>(xmid, ln2_w, ln2_b, xnh, xnl);
    // MLP up + ReLU -> bf16 split hidden
    hmma_gemm<<<ggrid, 256, GSMEM>>>(xnh, xnl, wth + 4*(size_t)D*D, wtl + 4*(size_t)D*D,
                                     b1, nullptr, nullptr, hh, hl, 1);
    // MLP down + residual(xmid) -> out (fp32)
    hmma_gemm<<<ggrid, 256, GSMEM>>>(hh, hl, wth + 5*(size_t)D*D, wtl + 5*(size_t)D*D,
                                     b2, xmid, out, nullptr, nullptr, 0);
}

// round 6
// speedup vs baseline: 2.8833x; 1.8254x over previous
#include <cuda_runtime.h>
#include <cuda_bf16.h>
#include <stdint.h>
#include <math.h>

#define D 768
#define BATCH 2
#define SEQ 2048
#define NROWS (BATCH*SEQ)   // 4096
#define NHEADS 12
#define HDIM 64
#define EPS 1e-5f

#define MT 128              // GEMM CTA M tile
#define NT 64               // GEMM CTA N tile
#define BK 32
#define KSTAGES (D/BK)      // 24

// ---------------- scratch ----------------
__device__ float g_xmid[NROWS*D];
__device__ __nv_bfloat16 g_xnh[NROWS*D], g_xnl[NROWS*D];
__device__ __nv_bfloat16 g_qh[NROWS*D],  g_ql[NROWS*D];
__device__ __nv_bfloat16 g_kh[NROWS*D],  g_kl[NROWS*D];
__device__ __nv_bfloat16 g_vh[NROWS*D],  g_vl[NROWS*D];
__device__ __nv_bfloat16 g_ah[NROWS*D],  g_al[NROWS*D];
__device__ __nv_bfloat16 g_hh[NROWS*D],  g_hl[NROWS*D];
__device__ __nv_bfloat16 g_wth[6*D*D], g_wtl[6*D*D];
__device__ unsigned char g_mask8[(size_t)BATCH*SEQ*SEQ];

// ---------------- PTX helpers ----------------
__device__ __forceinline__ uint32_t smem_u32(const void* p) {
    uint32_t a;
    asm("{ .reg .u64 t; cvta.to.shared.u64 t, %1; cvt.u32.u64 %0, t; }" : "=r"(a) : "l"(p));
    return a;
}
__device__ __forceinline__ void cp_async16(uint32_t dst, const void* src) {
    asm volatile("cp.async.ca.shared.global [%0], [%1], 16;\n" :: "r"(dst), "l"(src));
}
__device__ __forceinline__ void cp_commit() { asm volatile("cp.async.commit_group;\n"); }
__device__ __forceinline__ void cp_wait0()  { asm volatile("cp.async.wait_group 0;\n" ::: "memory"); }
__device__ __forceinline__ void cp_wait1()  { asm volatile("cp.async.wait_group 1;\n" ::: "memory"); }

__device__ __forceinline__ void ldsm_x4(uint32_t addr, uint32_t* r) {
    asm volatile("ldmatrix.sync.aligned.m8n8.x4.shared.b16 {%0,%1,%2,%3}, [%4];"
                 : "=r"(r[0]), "=r"(r[1]), "=r"(r[2]), "=r"(r[3]) : "r"(addr));
}
__device__ __forceinline__ void ldsm_x4t(uint32_t addr, uint32_t* r) {
    asm volatile("ldmatrix.sync.aligned.m8n8.x4.trans.shared.b16 {%0,%1,%2,%3}, [%4];"
                 : "=r"(r[0]), "=r"(r[1]), "=r"(r[2]), "=r"(r[3]) : "r"(addr));
}
__device__ __forceinline__ void mma_bf16(float* c, const uint32_t* a, uint32_t b0, uint32_t b1) {
    asm volatile("mma.sync.aligned.m16n8k16.row.col.f32.bf16.bf16.f32 "
                 "{%0,%1,%2,%3},{%4,%5,%6,%7},{%8,%9},{%0,%1,%2,%3};"
                 : "+f"(c[0]), "+f"(c[1]), "+f"(c[2]), "+f"(c[3])
                 : "r"(a[0]), "r"(a[1]), "r"(a[2]), "r"(a[3]), "r"(b0), "r"(b1));
}

// ---------------- split helpers ----------------
__device__ __forceinline__ void split_bf16(float v, __nv_bfloat16& h, __nv_bfloat16& l) {
    h = __float2bfloat16(v);
    l = __float2bfloat16(v - __bfloat162float(h));
}
__device__ __forceinline__ uint32_t pack_bf16x2(__nv_bfloat16 a, __nv_bfloat16 b) {
    __nv_bfloat162 p; p.x = a; p.y = b;
    return *(uint32_t*)&p;
}

// ---------------- weight transpose + split ----------------
__global__ void transpose_split(const float* __restrict__ W,
                                __nv_bfloat16* __restrict__ Th,
                                __nv_bfloat16* __restrict__ Tl) {
    __shared__ float tile[32][33];
    int bx = blockIdx.x * 32, by = blockIdx.y * 32;
    int tx = threadIdx.x, ty = threadIdx.y;
    #pragma unroll
    for (int i = 0; i < 4; i++)
        tile[ty + 8*i][tx] = W[(size_t)(by + ty + 8*i) * D + bx + tx];
    __syncthreads();
    #pragma unroll
    for (int i = 0; i < 4; i++) {
        float v = tile[tx][ty + 8*i];
        __nv_bfloat16 h, l; split_bf16(v, h, l);
        size_t idx = (size_t)(bx + ty + 8*i) * D + by + tx;
        Th[idx] = h; Tl[idx] = l;
    }
}

// ---------------- mask int32 -> int8 ----------------
__global__ void mask_pack(const int* __restrict__ m, unsigned char* __restrict__ m8, int n4) {
    int i = blockIdx.x * blockDim.x + threadIdx.x;
    if (i < n4) {
        int4 v = *(const int4*)(m + (size_t)i * 4);
        uchar4 o;
        o.x = (unsigned char)v.x; o.y = (unsigned char)v.y;
        o.z = (unsigned char)v.z; o.w = (unsigned char)v.w;
        *(uchar4*)(m8 + (size_t)i * 4) = o;
    }
}

// ---------------- LayerNorm -> bf16 hi/lo ----------------
__global__ void ln_split(const float* __restrict__ x, const float* __restrict__ w,
                         const float* __restrict__ b,
                         __nv_bfloat16* __restrict__ yh, __nv_bfloat16* __restrict__ yl) {
    __shared__ float sh_s[8], sh_ss[8];
    __shared__ float mu_sh, rstd_sh;
    int row = blockIdx.x;
    const float* xr = x + (size_t)row * D;
    int t = threadIdx.x;
    float v0 = xr[t], v1 = xr[t + 256], v2 = xr[t + 512];
    float s  = v0 + v1 + v2;
    float ss = v0*v0 + v1*v1 + v2*v2;
    #pragma unroll
    for (int o = 16; o > 0; o >>= 1) {
        s  += __shfl_xor_sync(0xffffffffu, s,  o);
        ss += __shfl_xor_sync(0xffffffffu, ss, o);
    }
    int wid = t >> 5, lane = t & 31;
    if (lane == 0) { sh_s[wid] = s; sh_ss[wid] = ss; }
    __syncthreads();
    if (t == 0) {
        float S = 0.f, SS = 0.f;
        #pragma unroll
        for (int i = 0; i < 8; i++) { S += sh_s[i]; SS += sh_ss[i]; }
        float mu = S / (float)D;
        float var = SS / (float)D - mu * mu;
        mu_sh = mu; rstd_sh = rsqrtf(var + EPS);
    }
    __syncthreads();
    float mu = mu_sh, rs = rstd_sh;
    size_t base = (size_t)row * D;
    #pragma unroll
    for (int i = 0; i < 3; i++) {
        int c = t + 256 * i;
        float v = (i == 0) ? v0 : (i == 1) ? v1 : v2;
        float o = (v - mu) * rs * w[c] + b[c];
        __nv_bfloat16 h, l; split_bf16(o, h, l);
        yh[base + c] = h; yl[base + c] = l;
    }
}

// ---------------- HMMA split-precision GEMM (validated R5) ----------------
#define STG 24576
#define OFF_AH 0
#define OFF_AL 8192
#define OFF_BH 16384
#define OFF_BL 20480
#define GSMEM  (2*STG)

__global__ void __launch_bounds__(256, 2)
hmma_gemm(const __nv_bfloat16* __restrict__ Ah, const __nv_bfloat16* __restrict__ Al,
          const __nv_bfloat16* __restrict__ Bh, const __nv_bfloat16* __restrict__ Bl,
          const float* __restrict__ bias, const float* __restrict__ res,
          float* __restrict__ Cf, __nv_bfloat16* __restrict__ Ch,
          __nv_bfloat16* __restrict__ Cl, int relu)
{
    extern __shared__ char smem[];
    uint32_t sb = smem_u32(smem);
    int t = threadIdx.x;
    int wid = t >> 5, lane = t & 31;
    int wm = wid & 3, wn = wid >> 2;
    int brow = blockIdx.y * MT;
    int bcol = blockIdx.x * NT;

    float acc[2][4][4];
    #pragma unroll
    for (int i = 0; i < 2; i++)
        #pragma unroll
        for (int j = 0; j < 4; j++)
            #pragma unroll
            for (int c = 0; c < 4; c++) acc[i][j][c] = 0.f;

    auto load_stage = [&](int s) {
        uint32_t base = sb + (uint32_t)((s & 1) * STG);
        int k0 = s * BK;
        #pragma unroll
        for (int i = 0; i < 2; i++) {
            int id = t + i * 256;
            int r = id >> 2, c = id & 3;
            uint32_t so = (uint32_t)(r * 64 + ((c ^ ((r >> 1) & 3)) * 16));
            size_t g = (size_t)(brow + r) * D + k0 + c * 8;
            cp_async16(base + OFF_AH + so, Ah + g);
            cp_async16(base + OFF_AL + so, Al + g);
        }
        {
            int r = t >> 2, c = t & 3;
            uint32_t so = (uint32_t)(r * 64 + ((c ^ ((r >> 1) & 3)) * 16));
            size_t g = (size_t)(bcol + r) * D + k0 + c * 8;
            cp_async16(base + OFF_BH + so, Bh + g);
            cp_async16(base + OFF_BL + so, Bl + g);
        }
        cp_commit();
    };

    load_stage(0);

    for (int s = 0; s < KSTAGES; s++) {
        if (s < KSTAGES - 1) load_stage(s + 1);
        if (s < KSTAGES - 1) cp_wait1(); else cp_wait0();
        __syncthreads();

        uint32_t base = sb + (uint32_t)((s & 1) * STG);
        #pragma unroll
        for (int kstep = 0; kstep < 2; kstep++) {
            uint32_t ah[2][4], al_[2][4];
            #pragma unroll
            for (int mt = 0; mt < 2; mt++) {
                int row = wm * 32 + mt * 16 + (lane & 15);
                int chunk = kstep * 2 + (lane >> 4);
                uint32_t so = (uint32_t)(row * 64 + ((chunk ^ ((row >> 1) & 3)) * 16));
                ldsm_x4(base + OFF_AH + so, ah[mt]);
                ldsm_x4(base + OFF_AL + so, al_[mt]);
            }
            uint32_t bh[2][4], bl[2][4];
            #pragma unroll
            for (int nt2 = 0; nt2 < 2; nt2++) {
                int row = wn * 32 + nt2 * 16 + (lane & 7) + ((lane & 16) ? 8 : 0);
                int chunk = kstep * 2 + ((lane >> 3) & 1);
                uint32_t so = (uint32_t)(row * 64 + ((chunk ^ ((row >> 1) & 3)) * 16));
                ldsm_x4(base + OFF_BH + so, bh[nt2]);
                ldsm_x4(base + OFF_BL + so, bl[nt2]);
            }
            #pragma unroll
            for (int mt = 0; mt < 2; mt++)
                #pragma unroll
                for (int nt = 0; nt < 4; nt++) {
                    float* c = acc[mt][nt];
                    uint32_t b0h = bh[nt >> 1][(nt & 1) * 2], b1h = bh[nt >> 1][(nt & 1) * 2 + 1];
                    uint32_t b0l = bl[nt >> 1][(nt & 1) * 2], b1l = bl[nt >> 1][(nt & 1) * 2 + 1];
                    mma_bf16(c, ah[mt],  b0h, b1h);
                    mma_bf16(c, ah[mt],  b0l, b1l);
                    mma_bf16(c, al_[mt], b0h, b1h);
                }
        }
        __syncthreads();
    }

    #pragma unroll
    for (int mt = 0; mt < 2; mt++) {
        #pragma unroll
        for (int nt = 0; nt < 4; nt++) {
            float* c = acc[mt][nt];
            int col = bcol + wn * 32 + nt * 8 + (lane & 3) * 2;
            #pragma unroll
            for (int half = 0; half < 2; half++) {
                int row = brow + wm * 32 + mt * 16 + (lane >> 2) + half * 8;
                float2 o;
                o.x = c[half * 2 + 0];
                o.y = c[half * 2 + 1];
                const float2 bb = *(const float2*)(bias + col);
                o.x += bb.x; o.y += bb.y;
                size_t gidx = (size_t)row * D + col;
                if (res) {
                    float2 rv = *(const float2*)(res + gidx);
                    o.x += rv.x; o.y += rv.y;
                }
                if (relu) { o.x = fmaxf(o.x, 0.f); o.y = fmaxf(o.y, 0.f); }
                if (Cf) *(float2*)(Cf + gidx) = o;
                if (Ch) {
                    __nv_bfloat16 h0, l0, h1, l1;
                    split_bf16(o.x, h0, l0);
                    split_bf16(o.y, h1, l1);
                    *(uint32_t*)(Ch + gidx) = pack_bf16x2(h0, h1);
                    *(uint32_t*)(Cl + gidx) = pack_bf16x2(l0, l1);
                }
            }
        }
    }
}

// ---------------- Tensor-core flash attention ----------------
// 128q x 64k tiles, 8 warps (each m16). Split-precision QK^T and PV.
#define AOFF_QH 0
#define AOFF_QL 16384
#define AOFF_KV 32768        // + buf*32768 : Kh(8K) Kl(8K) Vh(8K) Vl(8K)
#define ASMEM   (32768 + 2*32768)   // 98304

__global__ void __launch_bounds__(256)
attn_mma(const __nv_bfloat16* __restrict__ qh, const __nv_bfloat16* __restrict__ ql,
         const __nv_bfloat16* __restrict__ kh, const __nv_bfloat16* __restrict__ kl,
         const __nv_bfloat16* __restrict__ vh, const __nv_bfloat16* __restrict__ vl,
         const float* __restrict__ bias, const unsigned char* __restrict__ mask8,
         __nv_bfloat16* __restrict__ outh, __nv_bfloat16* __restrict__ outl)
{
    extern __shared__ char smem[];
    uint32_t sb = smem_u32(smem);
    int t = threadIdx.x;
    int w = t >> 5, lane = t & 31;

    int qt = blockIdx.x;          // 0..15
    int hb = blockIdx.y;          // 0..23
    int hd = hb >> 1;
    int b  = hb & 1;

    size_t qrow0 = (size_t)b * SEQ + qt * 128;
    const __nv_bfloat16* qhg = qh + qrow0 * D + hd * HDIM;
    const __nv_bfloat16* qlg = ql + qrow0 * D + hd * HDIM;
    const __nv_bfloat16* khg = kh + (size_t)b * SEQ * D + hd * HDIM;
    const __nv_bfloat16* klg = kl + (size_t)b * SEQ * D + hd * HDIM;
    const __nv_bfloat16* vhg = vh + (size_t)b * SEQ * D + hd * HDIM;
    const __nv_bfloat16* vlg = vl + (size_t)b * SEQ * D + hd * HDIM;
    const float* biasbase = bias + ((size_t)(hd * BATCH + b) * SEQ + qt * 128) * SEQ;
    const unsigned char* maskbase = mask8 + ((size_t)b * SEQ + qt * 128) * SEQ;

    // load Q tiles (hi & lo), swizzled rows of 8x16B chunks
    #pragma unroll
    for (int i = 0; i < 4; i++) {
        int id = t + i * 256;
        int row = id >> 3, c = id & 7;
        uint32_t so = (uint32_t)(row * 128 + ((c ^ (row & 7)) * 16));
        cp_async16(sb + AOFF_QH + so, qhg + (size_t)row * D + c * 8);
        cp_async16(sb + AOFF_QL + so, qlg + (size_t)row * D + c * 8);
    }
    cp_commit();

    auto load_kv = [&](int kt) {
        uint32_t base = sb + AOFF_KV + (uint32_t)((kt & 1) * 32768);
        #pragma unroll
        for (int i = 0; i < 2; i++) {
            int id = t + i * 256;
            int row = id >> 3, c = id & 7;
            uint32_t so = (uint32_t)(row * 128 + ((c ^ (row & 7)) * 16));
            size_t g = (size_t)(kt * 64 + row) * D + c * 8;
            cp_async16(base + so,         khg + g);
            cp_async16(base + 8192 + so,  klg + g);
            cp_async16(base + 16384 + so, vhg + g);
            cp_async16(base + 24576 + so, vlg + g);
        }
        cp_commit();
    };

    load_kv(0);

    float accO[8][4];
    #pragma unroll
    for (int j = 0; j < 8; j++)
        #pragma unroll
        for (int c = 0; c < 4; c++) accO[j][c] = 0.f;
    float m[2] = {-1e30f, -1e30f}, lsum[2] = {0.f, 0.f};

    const int NKT = SEQ / 64;   // 32
    for (int kt = 0; kt < NKT; kt++) {
        if (kt < NKT - 1) load_kv(kt + 1);
        if (kt < NKT - 1) cp_wait1(); else cp_wait0();
        __syncthreads();

        // prefetch bias/mask for this tile
        float2 brg[2][8];
        uchar2 mrg[2][8];
        #pragma unroll
        for (int hh = 0; hh < 2; hh++) {
            int row = w * 16 + (lane >> 2) + hh * 8;
            const float* bp = biasbase + (size_t)row * SEQ + kt * 64 + (lane & 3) * 2;
            const unsigned char* mp = maskbase + (size_t)row * SEQ + kt * 64 + (lane & 3) * 2;
            #pragma unroll
            for (int j = 0; j < 8; j++) {
                brg[hh][j] = *(const float2*)(bp + j * 8);
                mrg[hh][j] = *(const uchar2*)(mp + j * 8);
            }
        }

        uint32_t base = sb + AOFF_KV + (uint32_t)((kt & 1) * 32768);

        // ---- S = Qh@Kh^T + Qh@Kl^T + Ql@Kh^T ----
        float s[8][4];
        #pragma unroll
        for (int j = 0; j < 8; j++)
            #pragma unroll
            for (int c = 0; c < 4; c++) s[j][c] = 0.f;

        #pragma unroll
        for (int kk = 0; kk < 4; kk++) {
            uint32_t qa_h[4], qa_l[4];
            {
                int row = w * 16 + (lane & 15);
                int ch = kk * 2 + (lane >> 4);
                uint32_t so = (uint32_t)(row * 128 + ((ch ^ (row & 7)) * 16));
                ldsm_x4(sb + AOFF_QH + so, qa_h);
                ldsm_x4(sb + AOFF_QL + so, qa_l);
            }
            uint32_t kb_h[4][4], kb_l[4][4];
            #pragma unroll
            for (int np = 0; np < 4; np++) {
                int row = np * 16 + (lane & 7) + ((lane & 16) ? 8 : 0);
                int ch = kk * 2 + ((lane >> 3) & 1);
                uint32_t so = (uint32_t)(row * 128 + ((ch ^ (row & 7)) * 16));
                ldsm_x4(base + so,        kb_h[np]);
                ldsm_x4(base + 8192 + so, kb_l[np]);
            }
            #pragma unroll
            for (int j = 0; j < 8; j++) {
                uint32_t b0h = kb_h[j >> 1][(j & 1) * 2], b1h = kb_h[j >> 1][(j & 1) * 2 + 1];
                uint32_t b0l = kb_l[j >> 1][(j & 1) * 2], b1l = kb_l[j >> 1][(j & 1) * 2 + 1];
                mma_bf16(s[j], qa_h, b0h, b1h);
                mma_bf16(s[j], qa_h, b0l, b1l);
                mma_bf16(s[j], qa_l, b0h, b1h);
            }
        }

        // ---- softmax (registers; quad-lane row reductions) ----
        float p[2][16];
        #pragma unroll
        for (int hh = 0; hh < 2; hh++) {
            float mx = -1e30f;
            #pragma unroll
            for (int j = 0; j < 8; j++) {
                float v0 = mrg[hh][j].x ? (s[j][hh*2+0] + brg[hh][j].x) * 0.125f : -1e30f;
                float v1 = mrg[hh][j].y ? (s[j][hh*2+1] + brg[hh][j].y) * 0.125f : -1e30f;
                p[hh][j*2+0] = v0; p[hh][j*2+1] = v1;
                mx = fmaxf(mx, fmaxf(v0, v1));
            }
            mx = fmaxf(mx, __shfl_xor_sync(0xffffffffu, mx, 1));
            mx = fmaxf(mx, __shfl_xor_sync(0xffffffffu, mx, 2));
            float mn = fmaxf(m[hh], mx);
            float alpha = __expf(m[hh] - mn);
            m[hh] = mn;
            float rs = 0.f;
            #pragma unroll
            for (int e = 0; e < 16; e++) {
                float pe = __expf(p[hh][e] - mn);
                p[hh][e] = pe;
                rs += pe;
            }
            rs += __shfl_xor_sync(0xffffffffu, rs, 1);
            rs += __shfl_xor_sync(0xffffffffu, rs, 2);
            lsum[hh] = lsum[hh] * alpha + rs;
            #pragma unroll
            for (int j = 0; j < 8; j++) {
                accO[j][hh*2+0] *= alpha;
                accO[j][hh*2+1] *= alpha;
            }
        }

        // ---- O += Ph@Vh + Ph@Vl + Pl@Vh ----
        #pragma unroll
        for (int kk = 0; kk < 4; kk++) {
            int j0 = kk * 2, j1 = kk * 2 + 1;
            uint32_t pa_h[4], pa_l[4];
            {
                __nv_bfloat16 h00, l00, h01, l01, h10, l10, h11, l11;
                split_bf16(p[0][j0*2+0], h00, l00); split_bf16(p[0][j0*2+1], h01, l01);
                split_bf16(p[1][j0*2+0], h10, l10); split_bf16(p[1][j0*2+1], h11, l11);
                pa_h[0] = pack_bf16x2(h00, h01); pa_l[0] = pack_bf16x2(l00, l01);
                pa_h[1] = pack_bf16x2(h10, h11); pa_l[1] = pack_bf16x2(l10, l11);
                split_bf16(p[0][j1*2+0], h00, l00); split_bf16(p[0][j1*2+1], h01, l01);
                split_bf16(p[1][j1*2+0], h10, l10); split_bf16(p[1][j1*2+1], h11, l11);
                pa_h[2] = pack_bf16x2(h00, h01); pa_l[2] = pack_bf16x2(l00, l01);
                pa_h[3] = pack_bf16x2(h10, h11); pa_l[3] = pack_bf16x2(l10, l11);
            }
            uint32_t vb_h[4][4], vb_l[4][4];
            #pragma unroll
            for (int np = 0; np < 4; np++) {
                int i = lane >> 3, jj = lane & 7;
                int tok = kk * 16 + (i & 1) * 8 + jj;
                int ch = np * 2 + (i >> 1);
                uint32_t so = (uint32_t)(tok * 128 + ((ch ^ (tok & 7)) * 16));
                ldsm_x4t(base + 16384 + so, vb_h[np]);
                ldsm_x4t(base + 24576 + so, vb_l[np]);
            }
            #pragma unroll
            for (int j = 0; j < 8; j++) {
                uint32_t b0h = vb_h[j >> 1][(j & 1) * 2], b1h = vb_h[j >> 1][(j & 1) * 2 + 1];
                uint32_t b0l = vb_l[j >> 1][(j & 1) * 2], b1l = vb_l[j >> 1][(j & 1) * 2 + 1];
                mma_bf16(accO[j], pa_h, b0h, b1h);
                mma_bf16(accO[j], pa_h, b0l, b1l);
                mma_bf16(accO[j], pa_l, b0h, b1h);
            }
        }
        __syncthreads();
    }

    // ---- epilogue: normalize + split-write ----
    #pragma unroll
    for (int hh = 0; hh < 2; hh++) {
        float inv = 1.0f / lsum[hh];
        size_t row = qrow0 + w * 16 + (lane >> 2) + hh * 8;
        #pragma unroll
        for (int j = 0; j < 8; j++) {
            int col = hd * HDIM + j * 8 + (lane & 3) * 2;
            float v0 = accO[j][hh*2+0] * inv;
            float v1 = accO[j][hh*2+1] * inv;
            __nv_bfloat16 h0, l0, h1, l1;
            split_bf16(v0, h0, l0);
            split_bf16(v1, h1, l1);
            *(uint32_t*)(outh + row * D + col) = pack_bf16x2(h0, h1);
            *(uint32_t*)(outl + row * D + col) = pack_bf16x2(l0, l1);
        }
    }
}

// ---------------- host launcher --------------------------------------------------
extern "C" void kernel_launch(void* const* d_in, const int* in_sizes, int n_in,
                              void* d_out, int out_size) {
    const float* x     = (const float*)d_in[0];
    const float* bias  = (const float*)d_in[1];
    const int*   mask  = (const int*)d_in[2];
    const float* ln1_w = (const float*)d_in[3];
    const float* ln1_b = (const float*)d_in[4];
    const float* wq    = (const float*)d_in[5];
    const float* bq    = (const float*)d_in[6];
    const float* wk    = (const float*)d_in[7];
    const float* bk    = (const float*)d_in[8];
    const float* wv    = (const float*)d_in[9];
    const float* bv    = (const float*)d_in[10];
    const float* wo    = (const float*)d_in[11];
    const float* bo    = (const float*)d_in[12];
    const float* ln2_w = (const float*)d_in[13];
    const float* ln2_b = (const float*)d_in[14];
    const float* w1    = (const float*)d_in[15];
    const float* b1    = (const float*)d_in[16];
    const float* w2    = (const float*)d_in[17];
    const float* b2    = (const float*)d_in[18];
    float* out = (float*)d_out;

    float *xmid;
    __nv_bfloat16 *xnh, *xnl, *qh, *ql, *kh, *kl, *vh, *vl, *ah, *al, *hh, *hl, *wth, *wtl;
    unsigned char* mask8;
    cudaGetSymbolAddress((void**)&xmid, g_xmid);
    cudaGetSymbolAddress((void**)&xnh,  g_xnh);
    cudaGetSymbolAddress((void**)&xnl,  g_xnl);
    cudaGetSymbolAddress((void**)&qh,   g_qh);
    cudaGetSymbolAddress((void**)&ql,   g_ql);
    cudaGetSymbolAddress((void**)&kh,   g_kh);
    cudaGetSymbolAddress((void**)&kl,   g_kl);
    cudaGetSymbolAddress((void**)&vh,   g_vh);
    cudaGetSymbolAddress((void**)&vl,   g_vl);
    cudaGetSymbolAddress((void**)&ah,   g_ah);
    cudaGetSymbolAddress((void**)&al,   g_al);
    cudaGetSymbolAddress((void**)&hh,   g_hh);
    cudaGetSymbolAddress((void**)&hl,   g_hl);
    cudaGetSymbolAddress((void**)&wth,  g_wth);
    cudaGetSymbolAddress((void**)&wtl,  g_wtl);
    cudaGetSymbolAddress((void**)&mask8, g_mask8);

    cudaFuncSetAttribute(hmma_gemm, cudaFuncAttributeMaxDynamicSharedMemorySize, GSMEM);
    cudaFuncSetAttribute(attn_mma,  cudaFuncAttributeMaxDynamicSharedMemorySize, ASMEM);

    dim3 tgrid(24, 24), tblk(32, 8);
    const float* ws[6] = {wq, wk, wv, wo, w1, w2};
    for (int i = 0; i < 6; i++)
        transpose_split<<<tgrid, tblk>>>(ws[i], wth + (size_t)i * D * D, wtl + (size_t)i * D * D);
    mask_pack<<<(BATCH*SEQ*SEQ/4 + 255)/256, 256>>>(mask, mask8, BATCH*SEQ*SEQ/4);

    dim3 ggrid(D / NT, NROWS / MT);   // (12, 32)

    // LN1 -> split
    ln_split<<<NROWS, 256>>>(x, ln1_w, ln1_b, xnh, xnl);
    // QKV projections (split bf16 out)
    hmma_gemm<<<ggrid, 256, GSMEM>>>(xnh, xnl, wth + 0*(size_t)D*D, wtl + 0*(size_t)D*D,
                                     bq, nullptr, nullptr, qh, ql, 0);
    hmma_gemm<<<ggrid, 256, GSMEM>>>(xnh, xnl, wth + 1*(size_t)D*D, wtl + 1*(size_t)D*D,
                                     bk, nullptr, nullptr, kh, kl, 0);
    hmma_gemm<<<ggrid, 256, GSMEM>>>(xnh, xnl, wth + 2*(size_t)D*D, wtl + 2*(size_t)D*D,
                                     bv, nullptr, nullptr, vh, vl, 0);
    // attention (tensor-core flash) -> split bf16 out
    dim3 attn_grid(SEQ / 128, NHEADS * BATCH);  // (16, 24)
    attn_mma<<<attn_grid, 256, ASMEM>>>(qh, ql, kh, kl, vh, vl, bias, mask8, ah, al);
    // out-proj + residual(x) -> xmid (fp32)
    hmma_gemm<<<ggrid, 256, GSMEM>>>(ah, al, wth + 3*(size_t)D*D, wtl + 3*(size_t)D*D,
                                     bo, x, xmid, nullptr, nullptr, 0);
    // LN2 -> split
    ln_split<<<NROWS, 256>>>(xmid, ln2_w, ln2_b, xnh, xnl);
    // MLP up + ReLU -> split hidden
    hmma_gemm<<<ggrid, 256, GSMEM>>>(xnh, xnl, wth + 4*(size_t)D*D, wtl + 4*(size_t)D*D,
                                     b1, nullptr, nullptr, hh, hl, 1);
    // MLP down + residual(xmid) -> out (fp32)
    hmma_gemm<<<ggrid, 256, GSMEM>>>(hh, hl, wth + 5*(size_t)D*D, wtl + 5*(size_t)D*D,
                                     b2, xmid, out, nullptr, nullptr, 0);
}

// round 7
// speedup vs baseline: 2.9774x; 1.0326x over previous
#include <cuda_runtime.h>
#include <cuda_bf16.h>
#include <stdint.h>
#include <math.h>

#define D 768
#define BATCH 2
#define SEQ 2048
#define NROWS (BATCH*SEQ)   // 4096
#define NHEADS 12
#define HDIM 64
#define EPS 1e-5f

#define MT 128              // GEMM CTA M tile
#define NT 64               // GEMM CTA N tile
#define BK 32
#define KSTAGES (D/BK)      // 24

// ---------------- scratch ----------------
__device__ float g_xmid[NROWS*D];
__device__ __nv_bfloat16 g_xnh[NROWS*D], g_xnl[NROWS*D];
__device__ __nv_bfloat16 g_qh[NROWS*D],  g_ql[NROWS*D];
__device__ __nv_bfloat16 g_kh[NROWS*D],  g_kl[NROWS*D];
__device__ __nv_bfloat16 g_vh[NROWS*D],  g_vl[NROWS*D];
__device__ __nv_bfloat16 g_ah[NROWS*D],  g_al[NROWS*D];
__device__ __nv_bfloat16 g_hh[NROWS*D],  g_hl[NROWS*D];
__device__ __nv_bfloat16 g_wth[6*D*D], g_wtl[6*D*D];
__device__ unsigned char g_mask8[(size_t)BATCH*SEQ*SEQ];

// ---------------- PTX helpers ----------------
__device__ __forceinline__ uint32_t smem_u32(const void* p) {
    uint32_t a;
    asm("{ .reg .u64 t; cvta.to.shared.u64 t, %1; cvt.u32.u64 %0, t; }" : "=r"(a) : "l"(p));
    return a;
}
__device__ __forceinline__ void cp_async16(uint32_t dst, const void* src) {
    asm volatile("cp.async.ca.shared.global [%0], [%1], 16;\n" :: "r"(dst), "l"(src));
}
__device__ __forceinline__ void cp_commit() { asm volatile("cp.async.commit_group;\n"); }
__device__ __forceinline__ void cp_wait0()  { asm volatile("cp.async.wait_group 0;\n" ::: "memory"); }
__device__ __forceinline__ void cp_wait1()  { asm volatile("cp.async.wait_group 1;\n" ::: "memory"); }

__device__ __forceinline__ void ldsm_x4(uint32_t addr, uint32_t* r) {
    asm volatile("ldmatrix.sync.aligned.m8n8.x4.shared.b16 {%0,%1,%2,%3}, [%4];"
                 : "=r"(r[0]), "=r"(r[1]), "=r"(r[2]), "=r"(r[3]) : "r"(addr));
}
__device__ __forceinline__ void ldsm_x4t(uint32_t addr, uint32_t* r) {
    asm volatile("ldmatrix.sync.aligned.m8n8.x4.trans.shared.b16 {%0,%1,%2,%3}, [%4];"
                 : "=r"(r[0]), "=r"(r[1]), "=r"(r[2]), "=r"(r[3]) : "r"(addr));
}
__device__ __forceinline__ void mma_bf16(float* c, const uint32_t* a, uint32_t b0, uint32_t b1) {
    asm volatile("mma.sync.aligned.m16n8k16.row.col.f32.bf16.bf16.f32 "
                 "{%0,%1,%2,%3},{%4,%5,%6,%7},{%8,%9},{%0,%1,%2,%3};"
                 : "+f"(c[0]), "+f"(c[1]), "+f"(c[2]), "+f"(c[3])
                 : "r"(a[0]), "r"(a[1]), "r"(a[2]), "r"(a[3]), "r"(b0), "r"(b1));
}

// ---------------- split helpers ----------------
__device__ __forceinline__ void split_bf16(float v, __nv_bfloat16& h, __nv_bfloat16& l) {
    h = __float2bfloat16(v);
    l = __float2bfloat16(v - __bfloat162float(h));
}
__device__ __forceinline__ uint32_t pack_bf16x2(__nv_bfloat16 a, __nv_bfloat16 b) {
    __nv_bfloat162 p; p.x = a; p.y = b;
    return *(uint32_t*)&p;
}

// ---------------- weight transpose + split (all 6 in one launch) ----------------
__global__ void transpose_split6(const float* __restrict__ w0, const float* __restrict__ w1,
                                 const float* __restrict__ w2, const float* __restrict__ w3,
                                 const float* __restrict__ w4, const float* __restrict__ w5,
                                 __nv_bfloat16* __restrict__ Th, __nv_bfloat16* __restrict__ Tl) {
    __shared__ float tile[32][33];
    int z = blockIdx.z;
    const float* W = (z == 0) ? w0 : (z == 1) ? w1 : (z == 2) ? w2
                   : (z == 3) ? w3 : (z == 4) ? w4 : w5;
    __nv_bfloat16* th = Th + (size_t)z * D * D;
    __nv_bfloat16* tl = Tl + (size_t)z * D * D;
    int bx = blockIdx.x * 32, by = blockIdx.y * 32;
    int tx = threadIdx.x, ty = threadIdx.y;
    #pragma unroll
    for (int i = 0; i < 4; i++)
        tile[ty + 8*i][tx] = W[(size_t)(by + ty + 8*i) * D + bx + tx];
    __syncthreads();
    #pragma unroll
    for (int i = 0; i < 4; i++) {
        float v = tile[tx][ty + 8*i];
        __nv_bfloat16 h, l; split_bf16(v, h, l);
        size_t idx = (size_t)(bx + ty + 8*i) * D + by + tx;
        th[idx] = h; tl[idx] = l;
    }
}

// ---------------- mask int32 -> int8 ----------------
__global__ void mask_pack(const int* __restrict__ m, unsigned char* __restrict__ m8, int n4) {
    int i = blockIdx.x * blockDim.x + threadIdx.x;
    if (i < n4) {
        int4 v = *(const int4*)(m + (size_t)i * 4);
        uchar4 o;
        o.x = (unsigned char)v.x; o.y = (unsigned char)v.y;
        o.z = (unsigned char)v.z; o.w = (unsigned char)v.w;
        *(uchar4*)(m8 + (size_t)i * 4) = o;
    }
}

// ---------------- LayerNorm -> bf16 hi/lo ----------------
__global__ void ln_split(const float* __restrict__ x, const float* __restrict__ w,
                         const float* __restrict__ b,
                         __nv_bfloat16* __restrict__ yh, __nv_bfloat16* __restrict__ yl) {
    __shared__ float sh_s[8], sh_ss[8];
    __shared__ float mu_sh, rstd_sh;
    int row = blockIdx.x;
    const float* xr = x + (size_t)row * D;
    int t = threadIdx.x;
    float v0 = xr[t], v1 = xr[t + 256], v2 = xr[t + 512];
    float s  = v0 + v1 + v2;
    float ss = v0*v0 + v1*v1 + v2*v2;
    #pragma unroll
    for (int o = 16; o > 0; o >>= 1) {
        s  += __shfl_xor_sync(0xffffffffu, s,  o);
        ss += __shfl_xor_sync(0xffffffffu, ss, o);
    }
    int wid = t >> 5, lane = t & 31;
    if (lane == 0) { sh_s[wid] = s; sh_ss[wid] = ss; }
    __syncthreads();
    if (t == 0) {
        float S = 0.f, SS = 0.f;
        #pragma unroll
        for (int i = 0; i < 8; i++) { S += sh_s[i]; SS += sh_ss[i]; }
        float mu = S / (float)D;
        float var = SS / (float)D - mu * mu;
        mu_sh = mu; rstd_sh = rsqrtf(var + EPS);
    }
    __syncthreads();
    float mu = mu_sh, rs = rstd_sh;
    size_t base = (size_t)row * D;
    #pragma unroll
    for (int i = 0; i < 3; i++) {
        int c = t + 256 * i;
        float v = (i == 0) ? v0 : (i == 1) ? v1 : v2;
        float o = (v - mu) * rs * w[c] + b[c];
        __nv_bfloat16 h, l; split_bf16(o, h, l);
        yh[base + c] = h; yl[base + c] = l;
    }
}

// ---------------- HMMA split-precision GEMM core ----------------
#define STG 24576
#define OFF_AH 0
#define OFF_AL 8192
#define OFF_BH 16384
#define OFF_BL 20480
#define GSMEM  (2*STG)

__device__ __forceinline__ void gemm_core(
    const __nv_bfloat16* __restrict__ Ah, const __nv_bfloat16* __restrict__ Al,
    const __nv_bfloat16* __restrict__ Bh, const __nv_bfloat16* __restrict__ Bl,
    const float* __restrict__ bias, const float* __restrict__ res,
    float* __restrict__ Cf, __nv_bfloat16* __restrict__ Ch,
    __nv_bfloat16* __restrict__ Cl, int relu, int brow, int bcol, uint32_t sb)
{
    int t = threadIdx.x;
    int wid = t >> 5, lane = t & 31;
    int wm = wid & 3, wn = wid >> 2;

    float acc[2][4][4];
    #pragma unroll
    for (int i = 0; i < 2; i++)
        #pragma unroll
        for (int j = 0; j < 4; j++)
            #pragma unroll
            for (int c = 0; c < 4; c++) acc[i][j][c] = 0.f;

    auto load_stage = [&](int s) {
        uint32_t base = sb + (uint32_t)((s & 1) * STG);
        int k0 = s * BK;
        #pragma unroll
        for (int i = 0; i < 2; i++) {
            int id = t + i * 256;
            int r = id >> 2, c = id & 3;
            uint32_t so = (uint32_t)(r * 64 + ((c ^ ((r >> 1) & 3)) * 16));
            size_t g = (size_t)(brow + r) * D + k0 + c * 8;
            cp_async16(base + OFF_AH + so, Ah + g);
            cp_async16(base + OFF_AL + so, Al + g);
        }
        {
            int r = t >> 2, c = t & 3;
            uint32_t so = (uint32_t)(r * 64 + ((c ^ ((r >> 1) & 3)) * 16));
            size_t g = (size_t)(bcol + r) * D + k0 + c * 8;
            cp_async16(base + OFF_BH + so, Bh + g);
            cp_async16(base + OFF_BL + so, Bl + g);
        }
        cp_commit();
    };

    load_stage(0);

    for (int s = 0; s < KSTAGES; s++) {
        if (s < KSTAGES - 1) load_stage(s + 1);
        if (s < KSTAGES - 1) cp_wait1(); else cp_wait0();
        __syncthreads();

        uint32_t base = sb + (uint32_t)((s & 1) * STG);
        #pragma unroll
        for (int kstep = 0; kstep < 2; kstep++) {
            uint32_t ah[2][4], al_[2][4];
            #pragma unroll
            for (int mt = 0; mt < 2; mt++) {
                int row = wm * 32 + mt * 16 + (lane & 15);
                int chunk = kstep * 2 + (lane >> 4);
                uint32_t so = (uint32_t)(row * 64 + ((chunk ^ ((row >> 1) & 3)) * 16));
                ldsm_x4(base + OFF_AH + so, ah[mt]);
                ldsm_x4(base + OFF_AL + so, al_[mt]);
            }
            uint32_t bh[2][4], bl[2][4];
            #pragma unroll
            for (int nt2 = 0; nt2 < 2; nt2++) {
                int row = wn * 32 + nt2 * 16 + (lane & 7) + ((lane & 16) ? 8 : 0);
                int chunk = kstep * 2 + ((lane >> 3) & 1);
                uint32_t so = (uint32_t)(row * 64 + ((chunk ^ ((row >> 1) & 3)) * 16));
                ldsm_x4(base + OFF_BH + so, bh[nt2]);
                ldsm_x4(base + OFF_BL + so, bl[nt2]);
            }
            #pragma unroll
            for (int mt = 0; mt < 2; mt++)
                #pragma unroll
                for (int nt = 0; nt < 4; nt++) {
                    float* c = acc[mt][nt];
                    uint32_t b0h = bh[nt >> 1][(nt & 1) * 2], b1h = bh[nt >> 1][(nt & 1) * 2 + 1];
                    uint32_t b0l = bl[nt >> 1][(nt & 1) * 2], b1l = bl[nt >> 1][(nt & 1) * 2 + 1];
                    mma_bf16(c, ah[mt],  b0h, b1h);
                    mma_bf16(c, ah[mt],  b0l, b1l);
                    mma_bf16(c, al_[mt], b0h, b1h);
                }
        }
        __syncthreads();
    }

    #pragma unroll
    for (int mt = 0; mt < 2; mt++) {
        #pragma unroll
        for (int nt = 0; nt < 4; nt++) {
            float* c = acc[mt][nt];
            int col = bcol + wn * 32 + nt * 8 + (lane & 3) * 2;
            #pragma unroll
            for (int half = 0; half < 2; half++) {
                int row = brow + wm * 32 + mt * 16 + (lane >> 2) + half * 8;
                float2 o;
                o.x = c[half * 2 + 0];
                o.y = c[half * 2 + 1];
                const float2 bb = *(const float2*)(bias + col);
                o.x += bb.x; o.y += bb.y;
                size_t gidx = (size_t)row * D + col;
                if (res) {
                    float2 rv = *(const float2*)(res + gidx);
                    o.x += rv.x; o.y += rv.y;
                }
                if (relu) { o.x = fmaxf(o.x, 0.f); o.y = fmaxf(o.y, 0.f); }
                if (Cf) *(float2*)(Cf + gidx) = o;
                if (Ch) {
                    __nv_bfloat16 h0, l0, h1, l1;
                    split_bf16(o.x, h0, l0);
                    split_bf16(o.y, h1, l1);
                    *(uint32_t*)(Ch + gidx) = pack_bf16x2(h0, h1);
                    *(uint32_t*)(Cl + gidx) = pack_bf16x2(l0, l1);
                }
            }
        }
    }
}

__global__ void __launch_bounds__(256, 2)
hmma_gemm(const __nv_bfloat16* __restrict__ Ah, const __nv_bfloat16* __restrict__ Al,
          const __nv_bfloat16* __restrict__ Bh, const __nv_bfloat16* __restrict__ Bl,
          const float* __restrict__ bias, const float* __restrict__ res,
          float* __restrict__ Cf, __nv_bfloat16* __restrict__ Ch,
          __nv_bfloat16* __restrict__ Cl, int relu)
{
    extern __shared__ char smem[];
    gemm_core(Ah, Al, Bh, Bl, bias, res, Cf, Ch, Cl, relu,
              blockIdx.y * MT, blockIdx.x * NT, smem_u32(smem));
}

// Merged QKV: grid.x = 36 (sel = x/12, col tile = x%12)
__global__ void __launch_bounds__(256, 2)
qkv_gemm(const __nv_bfloat16* __restrict__ Ah, const __nv_bfloat16* __restrict__ Al,
         const __nv_bfloat16* __restrict__ Wth, const __nv_bfloat16* __restrict__ Wtl,
         const float* __restrict__ bq, const float* __restrict__ bk, const float* __restrict__ bv,
         __nv_bfloat16* __restrict__ qh, __nv_bfloat16* __restrict__ ql,
         __nv_bfloat16* __restrict__ kh, __nv_bfloat16* __restrict__ kl,
         __nv_bfloat16* __restrict__ vh, __nv_bfloat16* __restrict__ vl)
{
    extern __shared__ char smem[];
    int sel = blockIdx.x / 12;
    int bcol = (blockIdx.x % 12) * NT;
    const __nv_bfloat16* Bh = Wth + (size_t)sel * D * D;
    const __nv_bfloat16* Bl = Wtl + (size_t)sel * D * D;
    const float* bias = (sel == 0) ? bq : (sel == 1) ? bk : bv;
    __nv_bfloat16* Ch = (sel == 0) ? qh : (sel == 1) ? kh : vh;
    __nv_bfloat16* Cl = (sel == 0) ? ql : (sel == 1) ? kl : vl;
    gemm_core(Ah, Al, Bh, Bl, bias, nullptr, nullptr, Ch, Cl, 0,
              blockIdx.y * MT, bcol, smem_u32(smem));
}

// ---------------- Tensor-core flash attention ----------------
// 128q x 64k tiles, 8 warps (each m16). Split-precision QK^T and PV.
// Register-dieted for 2 CTAs/SM: softmax in place in S accs, inline bias/mask loads.
#define AOFF_QH 0
#define AOFF_QL 16384
#define AOFF_KV 32768        // + buf*32768 : Kh(8K) Kl(8K) Vh(8K) Vl(8K)
#define ASMEM   (32768 + 2*32768)   // 98304

__global__ void __launch_bounds__(256, 2)
attn_mma(const __nv_bfloat16* __restrict__ qh, const __nv_bfloat16* __restrict__ ql,
         const __nv_bfloat16* __restrict__ kh, const __nv_bfloat16* __restrict__ kl,
         const __nv_bfloat16* __restrict__ vh, const __nv_bfloat16* __restrict__ vl,
         const float* __restrict__ bias, const unsigned char* __restrict__ mask8,
         __nv_bfloat16* __restrict__ outh, __nv_bfloat16* __restrict__ outl)
{
    extern __shared__ char smem[];
    uint32_t sb = smem_u32(smem);
    int t = threadIdx.x;
    int w = t >> 5, lane = t & 31;

    int qt = blockIdx.x;          // 0..15
    int hb = blockIdx.y;          // 0..23
    int hd = hb >> 1;
    int b  = hb & 1;

    size_t qrow0 = (size_t)b * SEQ + qt * 128;
    const __nv_bfloat16* qhg = qh + qrow0 * D + hd * HDIM;
    const __nv_bfloat16* qlg = ql + qrow0 * D + hd * HDIM;
    const __nv_bfloat16* khg = kh + (size_t)b * SEQ * D + hd * HDIM;
    const __nv_bfloat16* klg = kl + (size_t)b * SEQ * D + hd * HDIM;
    const __nv_bfloat16* vhg = vh + (size_t)b * SEQ * D + hd * HDIM;
    const __nv_bfloat16* vlg = vl + (size_t)b * SEQ * D + hd * HDIM;
    const float* biasbase = bias + ((size_t)(hd * BATCH + b) * SEQ + qt * 128) * SEQ;
    const unsigned char* maskbase = mask8 + ((size_t)b * SEQ + qt * 128) * SEQ;

    // load Q tiles (hi & lo), swizzled rows of 8x16B chunks
    #pragma unroll
    for (int i = 0; i < 4; i++) {
        int id = t + i * 256;
        int row = id >> 3, c = id & 7;
        uint32_t so = (uint32_t)(row * 128 + ((c ^ (row & 7)) * 16));
        cp_async16(sb + AOFF_QH + so, qhg + (size_t)row * D + c * 8);
        cp_async16(sb + AOFF_QL + so, qlg + (size_t)row * D + c * 8);
    }
    cp_commit();

    auto load_kv = [&](int kt) {
        uint32_t base = sb + AOFF_KV + (uint32_t)((kt & 1) * 32768);
        #pragma unroll
        for (int i = 0; i < 2; i++) {
            int id = t + i * 256;
            int row = id >> 3, c = id & 7;
            uint32_t so = (uint32_t)(row * 128 + ((c ^ (row & 7)) * 16));
            size_t g = (size_t)(kt * 64 + row) * D + c * 8;
            cp_async16(base + so,         khg + g);
            cp_async16(base + 8192 + so,  klg + g);
            cp_async16(base + 16384 + so, vhg + g);
            cp_async16(base + 24576 + so, vlg + g);
        }
        cp_commit();
    };

    load_kv(0);

    float accO[8][4];
    #pragma unroll
    for (int j = 0; j < 8; j++)
        #pragma unroll
        for (int c = 0; c < 4; c++) accO[j][c] = 0.f;
    float m[2] = {-1e30f, -1e30f}, lsum[2] = {0.f, 0.f};

    const int NKT = SEQ / 64;   // 32
    for (int kt = 0; kt < NKT; kt++) {
        if (kt < NKT - 1) load_kv(kt + 1);
        if (kt < NKT - 1) cp_wait1(); else cp_wait0();
        __syncthreads();

        uint32_t base = sb + AOFF_KV + (uint32_t)((kt & 1) * 32768);

        // ---- S = Qh@Kh^T + Qh@Kl^T + Ql@Kh^T ----
        float s[8][4];
        #pragma unroll
        for (int j = 0; j < 8; j++)
            #pragma unroll
            for (int c = 0; c < 4; c++) s[j][c] = 0.f;

        #pragma unroll
        for (int kk = 0; kk < 4; kk++) {
            uint32_t qa_h[4], qa_l[4];
            {
                int row = w * 16 + (lane & 15);
                int ch = kk * 2 + (lane >> 4);
                uint32_t so = (uint32_t)(row * 128 + ((ch ^ (row & 7)) * 16));
                ldsm_x4(sb + AOFF_QH + so, qa_h);
                ldsm_x4(sb + AOFF_QL + so, qa_l);
            }
            uint32_t kb_h[4][4], kb_l[4][4];
            #pragma unroll
            for (int np = 0; np < 4; np++) {
                int row = np * 16 + (lane & 7) + ((lane & 16) ? 8 : 0);
                int ch = kk * 2 + ((lane >> 3) & 1);
                uint32_t so = (uint32_t)(row * 128 + ((ch ^ (row & 7)) * 16));
                ldsm_x4(base + so,        kb_h[np]);
                ldsm_x4(base + 8192 + so, kb_l[np]);
            }
            #pragma unroll
            for (int j = 0; j < 8; j++) {
                uint32_t b0h = kb_h[j >> 1][(j & 1) * 2], b1h = kb_h[j >> 1][(j & 1) * 2 + 1];
                uint32_t b0l = kb_l[j >> 1][(j & 1) * 2], b1l = kb_l[j >> 1][(j & 1) * 2 + 1];
                mma_bf16(s[j], qa_h, b0h, b1h);
                mma_bf16(s[j], qa_h, b0l, b1l);
                mma_bf16(s[j], qa_l, b0h, b1h);
            }
        }

        // ---- softmax in place (bias/mask loaded inline; quad-lane reductions) ----
        #pragma unroll
        for (int hh = 0; hh < 2; hh++) {
            int row = w * 16 + (lane >> 2) + hh * 8;
            const float* bp = biasbase + (size_t)row * SEQ + kt * 64 + (lane & 3) * 2;
            const unsigned char* mp = maskbase + (size_t)row * SEQ + kt * 64 + (lane & 3) * 2;
            float mx = -1e30f;
            #pragma unroll
            for (int j = 0; j < 8; j++) {
                float2 bb = *(const float2*)(bp + j * 8);
                uchar2 mm = *(const uchar2*)(mp + j * 8);
                float v0 = mm.x ? (s[j][hh*2+0] + bb.x) * 0.125f : -1e30f;
                float v1 = mm.y ? (s[j][hh*2+1] + bb.y) * 0.125f : -1e30f;
                s[j][hh*2+0] = v0; s[j][hh*2+1] = v1;
                mx = fmaxf(mx, fmaxf(v0, v1));
            }
            mx = fmaxf(mx, __shfl_xor_sync(0xffffffffu, mx, 1));
            mx = fmaxf(mx, __shfl_xor_sync(0xffffffffu, mx, 2));
            float mn = fmaxf(m[hh], mx);
            float alpha = __expf(m[hh] - mn);
            m[hh] = mn;
            float rs = 0.f;
            #pragma unroll
            for (int j = 0; j < 8; j++) {
                float e0 = __expf(s[j][hh*2+0] - mn);
                float e1 = __expf(s[j][hh*2+1] - mn);
                s[j][hh*2+0] = e0; s[j][hh*2+1] = e1;
                rs += e0 + e1;
            }
            rs += __shfl_xor_sync(0xffffffffu, rs, 1);
            rs += __shfl_xor_sync(0xffffffffu, rs, 2);
            lsum[hh] = lsum[hh] * alpha + rs;
            #pragma unroll
            for (int j = 0; j < 8; j++) {
                accO[j][hh*2+0] *= alpha;
                accO[j][hh*2+1] *= alpha;
            }
        }

        // ---- O += Ph@Vh + Ph@Vl + Pl@Vh ----
        #pragma unroll
        for (int kk = 0; kk < 4; kk++) {
            int j0 = kk * 2, j1 = kk * 2 + 1;
            uint32_t pa_h[4], pa_l[4];
            {
                __nv_bfloat16 h0, l0, h1, l1;
                split_bf16(s[j0][0], h0, l0); split_bf16(s[j0][1], h1, l1);
                pa_h[0] = pack_bf16x2(h0, h1); pa_l[0] = pack_bf16x2(l0, l1);
                split_bf16(s[j0][2], h0, l0); split_bf16(s[j0][3], h1, l1);
                pa_h[1] = pack_bf16x2(h0, h1); pa_l[1] = pack_bf16x2(l0, l1);
                split_bf16(s[j1][0], h0, l0); split_bf16(s[j1][1], h1, l1);
                pa_h[2] = pack_bf16x2(h0, h1); pa_l[2] = pack_bf16x2(l0, l1);
                split_bf16(s[j1][2], h0, l0); split_bf16(s[j1][3], h1, l1);
                pa_h[3] = pack_bf16x2(h0, h1); pa_l[3] = pack_bf16x2(l0, l1);
            }
            uint32_t vb_h[4][4], vb_l[4][4];
            #pragma unroll
            for (int np = 0; np < 4; np++) {
                int i = lane >> 3, jj = lane & 7;
                int tok = kk * 16 + (i & 1) * 8 + jj;
                int ch = np * 2 + (i >> 1);
                uint32_t so = (uint32_t)(tok * 128 + ((ch ^ (tok & 7)) * 16));
                ldsm_x4t(base + 16384 + so, vb_h[np]);
                ldsm_x4t(base + 24576 + so, vb_l[np]);
            }
            #pragma unroll
            for (int j = 0; j < 8; j++) {
                uint32_t b0h = vb_h[j >> 1][(j & 1) * 2], b1h = vb_h[j >> 1][(j & 1) * 2 + 1];
                uint32_t b0l = vb_l[j >> 1][(j & 1) * 2], b1l = vb_l[j >> 1][(j & 1) * 2 + 1];
                mma_bf16(accO[j], pa_h, b0h, b1h);
                mma_bf16(accO[j], pa_h, b0l, b1l);
                mma_bf16(accO[j], pa_l, b0h, b1h);
            }
        }
        __syncthreads();
    }

    // ---- epilogue: normalize + split-write ----
    #pragma unroll
    for (int hh = 0; hh < 2; hh++) {
        float inv = 1.0f / lsum[hh];
        size_t row = qrow0 + w * 16 + (lane >> 2) + hh * 8;
        #pragma unroll
        for (int j = 0; j < 8; j++) {
            int col = hd * HDIM + j * 8 + (lane & 3) * 2;
            float v0 = accO[j][hh*2+0] * inv;
            float v1 = accO[j][hh*2+1] * inv;
            __nv_bfloat16 h0, l0, h1, l1;
            split_bf16(v0, h0, l0);
            split_bf16(v1, h1, l1);
            *(uint32_t*)(outh + row * D + col) = pack_bf16x2(h0, h1);
            *(uint32_t*)(outl + row * D + col) = pack_bf16x2(l0, l1);
        }
    }
}

// ---------------- host launcher --------------------------------------------------
extern "C" void kernel_launch(void* const* d_in, const int* in_sizes, int n_in,
                              void* d_out, int out_size) {
    const float* x     = (const float*)d_in[0];
    const float* bias  = (const float*)d_in[1];
    const int*   mask  = (const int*)d_in[2];
    const float* ln1_w = (const float*)d_in[3];
    const float* ln1_b = (const float*)d_in[4];
    const float* wq    = (const float*)d_in[5];
    const float* bq    = (const float*)d_in[6];
    const float* wk    = (const float*)d_in[7];
    const float* bk    = (const float*)d_in[8];
    const float* wv    = (const float*)d_in[9];
    const float* bv    = (const float*)d_in[10];
    const float* wo    = (const float*)d_in[11];
    const float* bo    = (const float*)d_in[12];
    const float* ln2_w = (const float*)d_in[13];
    const float* ln2_b = (const float*)d_in[14];
    const float* w1    = (const float*)d_in[15];
    const float* b1    = (const float*)d_in[16];
    const float* w2    = (const float*)d_in[17];
    const float* b2    = (const float*)d_in[18];
    float* out = (float*)d_out;

    float *xmid;
    __nv_bfloat16 *xnh, *xnl, *qh, *ql, *kh, *kl, *vh, *vl, *ah, *al, *hh, *hl, *wth, *wtl;
    unsigned char* mask8;
    cudaGetSymbolAddress((void**)&xmid, g_xmid);
    cudaGetSymbolAddress((void**)&xnh,  g_xnh);
    cudaGetSymbolAddress((void**)&xnl,  g_xnl);
    cudaGetSymbolAddress((void**)&qh,   g_qh);
    cudaGetSymbolAddress((void**)&ql,   g_ql);
    cudaGetSymbolAddress((void**)&kh,   g_kh);
    cudaGetSymbolAddress((void**)&kl,   g_kl);
    cudaGetSymbolAddress((void**)&vh,   g_vh);
    cudaGetSymbolAddress((void**)&vl,   g_vl);
    cudaGetSymbolAddress((void**)&ah,   g_ah);
    cudaGetSymbolAddress((void**)&al,   g_al);
    cudaGetSymbolAddress((void**)&hh,   g_hh);
    cudaGetSymbolAddress((void**)&hl,   g_hl);
    cudaGetSymbolAddress((void**)&wth,  g_wth);
    cudaGetSymbolAddress((void**)&wtl,  g_wtl);
    cudaGetSymbolAddress((void**)&mask8, g_mask8);

    cudaFuncSetAttribute(hmma_gemm, cudaFuncAttributeMaxDynamicSharedMemorySize, GSMEM);
    cudaFuncSetAttribute(qkv_gemm,  cudaFuncAttributeMaxDynamicSharedMemorySize, GSMEM);
    cudaFuncSetAttribute(attn_mma,  cudaFuncAttributeMaxDynamicSharedMemorySize, ASMEM);

    dim3 tgrid(24, 24, 6), tblk(32, 8);
    transpose_split6<<<tgrid, tblk>>>(wq, wk, wv, wo, w1, w2, wth, wtl);
    mask_pack<<<(BATCH*SEQ*SEQ/4 + 255)/256, 256>>>(mask, mask8, BATCH*SEQ*SEQ/4);

    dim3 ggrid(D / NT, NROWS / MT);     // (12, 32)
    dim3 qgrid(3 * D / NT, NROWS / MT); // (36, 32)

    // LN1 -> split
    ln_split<<<NROWS, 256>>>(x, ln1_w, ln1_b, xnh, xnl);
    // merged QKV projections (split bf16 out)
    qkv_gemm<<<qgrid, 256, GSMEM>>>(xnh, xnl, wth, wtl, bq, bk, bv,
                                    qh, ql, kh, kl, vh, vl);
    // attention (tensor-core flash) -> split bf16 out
    dim3 attn_grid(SEQ / 128, NHEADS * BATCH);  // (16, 24)
    attn_mma<<<attn_grid, 256, ASMEM>>>(qh, ql, kh, kl, vh, vl, bias, mask8, ah, al);
    // out-proj + residual(x) -> xmid (fp32)
    hmma_gemm<<<ggrid, 256, GSMEM>>>(ah, al, wth + 3*(size_t)D*D, wtl + 3*(size_t)D*D,
                                     bo, x, xmid, nullptr, nullptr, 0);
    // LN2 -> split
    ln_split<<<NROWS, 256>>>(xmid, ln2_w, ln2_b, xnh, xnl);
    // MLP up + ReLU -> split hidden
    hmma_gemm<<<ggrid, 256, GSMEM>>>(xnh, xnl, wth + 4*(size_t)D*D, wtl + 4*(size_t)D*D,
                                     b1, nullptr, nullptr, hh, hl, 1);
    // MLP down + residual(xmid) -> out (fp32)
    hmma_gemm<<<ggrid, 256, GSMEM>>>(hh, hl, wth + 5*(size_t)D*D, wtl + 5*(size_t)D*D,
                                     b2, xmid, out, nullptr, nullptr, 0);
}

// round 8
// speedup vs baseline: 3.5023x; 1.1763x over previous
#include <cuda_runtime.h>
#include <cuda_bf16.h>
#include <cuda_fp16.h>
#include <stdint.h>
#include <math.h>

#define D 768
#define BATCH 2
#define SEQ 2048
#define NROWS (BATCH*SEQ)   // 4096
#define NHEADS 12
#define HDIM 64
#define EPS 1e-5f

#define MT 128              // GEMM CTA M tile
#define NT 64               // GEMM CTA N tile
#define BK 32
#define KSTAGES (D/BK)      // 24

// ---------------- scratch ----------------
__device__ float g_xmid[NROWS*D];
__device__ __nv_bfloat16 g_xnh[NROWS*D], g_xnl[NROWS*D];
__device__ __half g_q16[NROWS*D], g_k16[NROWS*D], g_v16[NROWS*D];
__device__ __nv_bfloat16 g_ah[NROWS*D],  g_al[NROWS*D];
__device__ __nv_bfloat16 g_hh[NROWS*D],  g_hl[NROWS*D];
__device__ __nv_bfloat16 g_wth[6*D*D], g_wtl[6*D*D];
__device__ unsigned char g_mask8[(size_t)BATCH*SEQ*SEQ];

// ---------------- PTX helpers ----------------
__device__ __forceinline__ uint32_t smem_u32(const void* p) {
    uint32_t a;
    asm("{ .reg .u64 t; cvta.to.shared.u64 t, %1; cvt.u32.u64 %0, t; }" : "=r"(a) : "l"(p));
    return a;
}
__device__ __forceinline__ void cp_async16(uint32_t dst, const void* src) {
    asm volatile("cp.async.ca.shared.global [%0], [%1], 16;\n" :: "r"(dst), "l"(src));
}
__device__ __forceinline__ void cp_commit() { asm volatile("cp.async.commit_group;\n"); }
__device__ __forceinline__ void cp_wait0()  { asm volatile("cp.async.wait_group 0;\n" ::: "memory"); }
__device__ __forceinline__ void cp_wait1()  { asm volatile("cp.async.wait_group 1;\n" ::: "memory"); }

__device__ __forceinline__ void ldsm_x4(uint32_t addr, uint32_t* r) {
    asm volatile("ldmatrix.sync.aligned.m8n8.x4.shared.b16 {%0,%1,%2,%3}, [%4];"
                 : "=r"(r[0]), "=r"(r[1]), "=r"(r[2]), "=r"(r[3]) : "r"(addr));
}
__device__ __forceinline__ void ldsm_x4t(uint32_t addr, uint32_t* r) {
    asm volatile("ldmatrix.sync.aligned.m8n8.x4.trans.shared.b16 {%0,%1,%2,%3}, [%4];"
                 : "=r"(r[0]), "=r"(r[1]), "=r"(r[2]), "=r"(r[3]) : "r"(addr));
}
__device__ __forceinline__ void mma_bf16(float* c, const uint32_t* a, uint32_t b0, uint32_t b1) {
    asm volatile("mma.sync.aligned.m16n8k16.row.col.f32.bf16.bf16.f32 "
                 "{%0,%1,%2,%3},{%4,%5,%6,%7},{%8,%9},{%0,%1,%2,%3};"
                 : "+f"(c[0]), "+f"(c[1]), "+f"(c[2]), "+f"(c[3])
                 : "r"(a[0]), "r"(a[1]), "r"(a[2]), "r"(a[3]), "r"(b0), "r"(b1));
}
__device__ __forceinline__ void mma_f16(float* c, const uint32_t* a, uint32_t b0, uint32_t b1) {
    asm volatile("mma.sync.aligned.m16n8k16.row.col.f32.f16.f16.f32 "
                 "{%0,%1,%2,%3},{%4,%5,%6,%7},{%8,%9},{%0,%1,%2,%3};"
                 : "+f"(c[0]), "+f"(c[1]), "+f"(c[2]), "+f"(c[3])
                 : "r"(a[0]), "r"(a[1]), "r"(a[2]), "r"(a[3]), "r"(b0), "r"(b1));
}

// ---------------- split/pack helpers ----------------
__device__ __forceinline__ void split_bf16(float v, __nv_bfloat16& h, __nv_bfloat16& l) {
    h = __float2bfloat16(v);
    l = __float2bfloat16(v - __bfloat162float(h));
}
__device__ __forceinline__ uint32_t pack_bf16x2(__nv_bfloat16 a, __nv_bfloat16 b) {
    __nv_bfloat162 p; p.x = a; p.y = b;
    return *(uint32_t*)&p;
}
__device__ __forceinline__ uint32_t pack_half2(float a, float b) {
    __half2 h = __floats2half2_rn(a, b);
    return *(uint32_t*)&h;
}

// ---------------- weight transpose + split (all 6 in one launch) ----------------
__global__ void transpose_split6(const float* __restrict__ w0, const float* __restrict__ w1,
                                 const float* __restrict__ w2, const float* __restrict__ w3,
                                 const float* __restrict__ w4, const float* __restrict__ w5,
                                 __nv_bfloat16* __restrict__ Th, __nv_bfloat16* __restrict__ Tl) {
    __shared__ float tile[32][33];
    int z = blockIdx.z;
    const float* W = (z == 0) ? w0 : (z == 1) ? w1 : (z == 2) ? w2
                   : (z == 3) ? w3 : (z == 4) ? w4 : w5;
    __nv_bfloat16* th = Th + (size_t)z * D * D;
    __nv_bfloat16* tl = Tl + (size_t)z * D * D;
    int bx = blockIdx.x * 32, by = blockIdx.y * 32;
    int tx = threadIdx.x, ty = threadIdx.y;
    #pragma unroll
    for (int i = 0; i < 4; i++)
        tile[ty + 8*i][tx] = W[(size_t)(by + ty + 8*i) * D + bx + tx];
    __syncthreads();
    #pragma unroll
    for (int i = 0; i < 4; i++) {
        float v = tile[tx][ty + 8*i];
        __nv_bfloat16 h, l; split_bf16(v, h, l);
        size_t idx = (size_t)(bx + ty + 8*i) * D + by + tx;
        th[idx] = h; tl[idx] = l;
    }
}

// ---------------- mask int32 -> int8 ----------------
__global__ void mask_pack(const int* __restrict__ m, unsigned char* __restrict__ m8, int n4) {
    int i = blockIdx.x * blockDim.x + threadIdx.x;
    if (i < n4) {
        int4 v = *(const int4*)(m + (size_t)i * 4);
        uchar4 o;
        o.x = (unsigned char)v.x; o.y = (unsigned char)v.y;
        o.z = (unsigned char)v.z; o.w = (unsigned char)v.w;
        *(uchar4*)(m8 + (size_t)i * 4) = o;
    }
}

// ---------------- LayerNorm -> bf16 hi/lo ----------------
__global__ void ln_split(const float* __restrict__ x, const float* __restrict__ w,
                         const float* __restrict__ b,
                         __nv_bfloat16* __restrict__ yh, __nv_bfloat16* __restrict__ yl) {
    __shared__ float sh_s[8], sh_ss[8];
    __shared__ float mu_sh, rstd_sh;
    int row = blockIdx.x;
    const float* xr = x + (size_t)row * D;
    int t = threadIdx.x;
    float v0 = xr[t], v1 = xr[t + 256], v2 = xr[t + 512];
    float s  = v0 + v1 + v2;
    float ss = v0*v0 + v1*v1 + v2*v2;
    #pragma unroll
    for (int o = 16; o > 0; o >>= 1) {
        s  += __shfl_xor_sync(0xffffffffu, s,  o);
        ss += __shfl_xor_sync(0xffffffffu, ss, o);
    }
    int wid = t >> 5, lane = t & 31;
    if (lane == 0) { sh_s[wid] = s; sh_ss[wid] = ss; }
    __syncthreads();
    if (t == 0) {
        float S = 0.f, SS = 0.f;
        #pragma unroll
        for (int i = 0; i < 8; i++) { S += sh_s[i]; SS += sh_ss[i]; }
        float mu = S / (float)D;
        float var = SS / (float)D - mu * mu;
        mu_sh = mu; rstd_sh = rsqrtf(var + EPS);
    }
    __syncthreads();
    float mu = mu_sh, rs = rstd_sh;
    size_t base = (size_t)row * D;
    #pragma unroll
    for (int i = 0; i < 3; i++) {
        int c = t + 256 * i;
        float v = (i == 0) ? v0 : (i == 1) ? v1 : v2;
        float o = (v - mu) * rs * w[c] + b[c];
        __nv_bfloat16 h, l; split_bf16(o, h, l);
        yh[base + c] = h; yl[base + c] = l;
    }
}

// ---------------- HMMA split-precision GEMM core ----------------
#define STG 24576
#define OFF_AH 0
#define OFF_AL 8192
#define OFF_BH 16384
#define OFF_BL 20480
#define GSMEM  (2*STG)

__device__ __forceinline__ void gemm_core(
    const __nv_bfloat16* __restrict__ Ah, const __nv_bfloat16* __restrict__ Al,
    const __nv_bfloat16* __restrict__ Bh, const __nv_bfloat16* __restrict__ Bl,
    const float* __restrict__ bias, const float* __restrict__ res,
    float* __restrict__ Cf, __nv_bfloat16* __restrict__ Ch,
    __nv_bfloat16* __restrict__ Cl, __half* __restrict__ C16,
    int relu, int brow, int bcol, uint32_t sb)
{
    int t = threadIdx.x;
    int wid = t >> 5, lane = t & 31;
    int wm = wid & 3, wn = wid >> 2;

    float acc[2][4][4];
    #pragma unroll
    for (int i = 0; i < 2; i++)
        #pragma unroll
        for (int j = 0; j < 4; j++)
            #pragma unroll
            for (int c = 0; c < 4; c++) acc[i][j][c] = 0.f;

    auto load_stage = [&](int s) {
        uint32_t base = sb + (uint32_t)((s & 1) * STG);
        int k0 = s * BK;
        #pragma unroll
        for (int i = 0; i < 2; i++) {
            int id = t + i * 256;
            int r = id >> 2, c = id & 3;
            uint32_t so = (uint32_t)(r * 64 + ((c ^ ((r >> 1) & 3)) * 16));
            size_t g = (size_t)(brow + r) * D + k0 + c * 8;
            cp_async16(base + OFF_AH + so, Ah + g);
            cp_async16(base + OFF_AL + so, Al + g);
        }
        {
            int r = t >> 2, c = t & 3;
            uint32_t so = (uint32_t)(r * 64 + ((c ^ ((r >> 1) & 3)) * 16));
            size_t g = (size_t)(bcol + r) * D + k0 + c * 8;
            cp_async16(base + OFF_BH + so, Bh + g);
            cp_async16(base + OFF_BL + so, Bl + g);
        }
        cp_commit();
    };

    load_stage(0);

    for (int s = 0; s < KSTAGES; s++) {
        if (s < KSTAGES - 1) load_stage(s + 1);
        if (s < KSTAGES - 1) cp_wait1(); else cp_wait0();
        __syncthreads();

        uint32_t base = sb + (uint32_t)((s & 1) * STG);
        #pragma unroll
        for (int kstep = 0; kstep < 2; kstep++) {
            uint32_t ah[2][4], al_[2][4];
            #pragma unroll
            for (int mt = 0; mt < 2; mt++) {
                int row = wm * 32 + mt * 16 + (lane & 15);
                int chunk = kstep * 2 + (lane >> 4);
                uint32_t so = (uint32_t)(row * 64 + ((chunk ^ ((row >> 1) & 3)) * 16));
                ldsm_x4(base + OFF_AH + so, ah[mt]);
                ldsm_x4(base + OFF_AL + so, al_[mt]);
            }
            uint32_t bh[2][4], bl[2][4];
            #pragma unroll
            for (int nt2 = 0; nt2 < 2; nt2++) {
                int row = wn * 32 + nt2 * 16 + (lane & 7) + ((lane & 16) ? 8 : 0);
                int chunk = kstep * 2 + ((lane >> 3) & 1);
                uint32_t so = (uint32_t)(row * 64 + ((chunk ^ ((row >> 1) & 3)) * 16));
                ldsm_x4(base + OFF_BH + so, bh[nt2]);
                ldsm_x4(base + OFF_BL + so, bl[nt2]);
            }
            #pragma unroll
            for (int mt = 0; mt < 2; mt++)
                #pragma unroll
                for (int nt = 0; nt < 4; nt++) {
                    float* c = acc[mt][nt];
                    uint32_t b0h = bh[nt >> 1][(nt & 1) * 2], b1h = bh[nt >> 1][(nt & 1) * 2 + 1];
                    uint32_t b0l = bl[nt >> 1][(nt & 1) * 2], b1l = bl[nt >> 1][(nt & 1) * 2 + 1];
                    mma_bf16(c, ah[mt],  b0h, b1h);
                    mma_bf16(c, ah[mt],  b0l, b1l);
                    mma_bf16(c, al_[mt], b0h, b1h);
                }
        }
        __syncthreads();
    }

    #pragma unroll
    for (int mt = 0; mt < 2; mt++) {
        #pragma unroll
        for (int nt = 0; nt < 4; nt++) {
            float* c = acc[mt][nt];
            int col = bcol + wn * 32 + nt * 8 + (lane & 3) * 2;
            #pragma unroll
            for (int half = 0; half < 2; half++) {
                int row = brow + wm * 32 + mt * 16 + (lane >> 2) + half * 8;
                float2 o;
                o.x = c[half * 2 + 0];
                o.y = c[half * 2 + 1];
                const float2 bb = *(const float2*)(bias + col);
                o.x += bb.x; o.y += bb.y;
                size_t gidx = (size_t)row * D + col;
                if (res) {
                    float2 rv = *(const float2*)(res + gidx);
                    o.x += rv.x; o.y += rv.y;
                }
                if (relu) { o.x = fmaxf(o.x, 0.f); o.y = fmaxf(o.y, 0.f); }
                if (Cf) *(float2*)(Cf + gidx) = o;
                if (C16) *(uint32_t*)(C16 + gidx) = pack_half2(o.x, o.y);
                if (Ch) {
                    __nv_bfloat16 h0, l0, h1, l1;
                    split_bf16(o.x, h0, l0);
                    split_bf16(o.y, h1, l1);
                    *(uint32_t*)(Ch + gidx) = pack_bf16x2(h0, h1);
                    *(uint32_t*)(Cl + gidx) = pack_bf16x2(l0, l1);
                }
            }
        }
    }
}

__global__ void __launch_bounds__(256, 2)
hmma_gemm(const __nv_bfloat16* __restrict__ Ah, const __nv_bfloat16* __restrict__ Al,
          const __nv_bfloat16* __restrict__ Bh, const __nv_bfloat16* __restrict__ Bl,
          const float* __restrict__ bias, const float* __restrict__ res,
          float* __restrict__ Cf, __nv_bfloat16* __restrict__ Ch,
          __nv_bfloat16* __restrict__ Cl, int relu)
{
    extern __shared__ char smem[];
    gemm_core(Ah, Al, Bh, Bl, bias, res, Cf, Ch, Cl, nullptr, relu,
              blockIdx.y * MT, blockIdx.x * NT, smem_u32(smem));
}

// Merged QKV: grid.x = 36 (sel = x/12, col tile = x%12); fp16 outputs
__global__ void __launch_bounds__(256, 2)
qkv_gemm(const __nv_bfloat16* __restrict__ Ah, const __nv_bfloat16* __restrict__ Al,
         const __nv_bfloat16* __restrict__ Wth, const __nv_bfloat16* __restrict__ Wtl,
         const float* __restrict__ bq, const float* __restrict__ bk, const float* __restrict__ bv,
         __half* __restrict__ q16, __half* __restrict__ k16, __half* __restrict__ v16)
{
    extern __shared__ char smem[];
    int sel = blockIdx.x / 12;
    int bcol = (blockIdx.x % 12) * NT;
    const __nv_bfloat16* Bh = Wth + (size_t)sel * D * D;
    const __nv_bfloat16* Bl = Wtl + (size_t)sel * D * D;
    const float* bias = (sel == 0) ? bq : (sel == 1) ? bk : bv;
    __half* C16 = (sel == 0) ? q16 : (sel == 1) ? k16 : v16;
    gemm_core(Ah, Al, Bh, Bl, bias, nullptr, nullptr, nullptr, nullptr, C16, 0,
              blockIdx.y * MT, bcol, smem_u32(smem));
}

// ---------------- fp16 tensor-core flash attention ----------------
// 128q x 64k tiles, 8 warps (each m16). Single-product fp16 QK^T and PV.
#define AOFF_Q  0
#define AOFF_KV 16384        // + buf*16384 : K(8K) V(8K)
#define ASMEM   (16384 + 2*16384)   // 49152

__global__ void __launch_bounds__(256, 2)
attn_mma(const __half* __restrict__ q16, const __half* __restrict__ k16,
         const __half* __restrict__ v16,
         const float* __restrict__ bias, const unsigned char* __restrict__ mask8,
         __nv_bfloat16* __restrict__ outh, __nv_bfloat16* __restrict__ outl)
{
    extern __shared__ char smem[];
    uint32_t sb = smem_u32(smem);
    int t = threadIdx.x;
    int w = t >> 5, lane = t & 31;

    int qt = blockIdx.x;          // 0..15
    int hb = blockIdx.y;          // 0..23
    int hd = hb >> 1;
    int b  = hb & 1;

    size_t qrow0 = (size_t)b * SEQ + qt * 128;
    const __half* qg = q16 + qrow0 * D + hd * HDIM;
    const __half* kg = k16 + (size_t)b * SEQ * D + hd * HDIM;
    const __half* vg = v16 + (size_t)b * SEQ * D + hd * HDIM;
    const float* biasbase = bias + ((size_t)(hd * BATCH + b) * SEQ + qt * 128) * SEQ;
    const unsigned char* maskbase = mask8 + ((size_t)b * SEQ + qt * 128) * SEQ;

    // load Q tile (128x64 fp16 = 1024 16B chunks), swizzled
    #pragma unroll
    for (int i = 0; i < 4; i++) {
        int id = t + i * 256;
        int row = id >> 3, c = id & 7;
        uint32_t so = (uint32_t)(row * 128 + ((c ^ (row & 7)) * 16));
        cp_async16(sb + AOFF_Q + so, qg + (size_t)row * D + c * 8);
    }
    cp_commit();

    auto load_kv = [&](int kt) {
        uint32_t base = sb + AOFF_KV + (uint32_t)((kt & 1) * 16384);
        #pragma unroll
        for (int i = 0; i < 2; i++) {
            int id = t + i * 256;
            int row = id >> 3, c = id & 7;
            uint32_t so = (uint32_t)(row * 128 + ((c ^ (row & 7)) * 16));
            size_t g = (size_t)(kt * 64 + row) * D + c * 8;
            cp_async16(base + so,        kg + g);
            cp_async16(base + 8192 + so, vg + g);
        }
        cp_commit();
    };

    load_kv(0);

    float accO[8][4];
    #pragma unroll
    for (int j = 0; j < 8; j++)
        #pragma unroll
        for (int c = 0; c < 4; c++) accO[j][c] = 0.f;
    float m[2] = {-1e30f, -1e30f}, lsum[2] = {0.f, 0.f};

    const int NKT = SEQ / 64;   // 32
    for (int kt = 0; kt < NKT; kt++) {
        if (kt < NKT - 1) load_kv(kt + 1);
        if (kt < NKT - 1) cp_wait1(); else cp_wait0();
        __syncthreads();

        uint32_t base = sb + AOFF_KV + (uint32_t)((kt & 1) * 16384);

        // ---- S = Q @ K^T (single fp16 product) ----
        float s[8][4];
        #pragma unroll
        for (int j = 0; j < 8; j++)
            #pragma unroll
            for (int c = 0; c < 4; c++) s[j][c] = 0.f;

        #pragma unroll
        for (int kk = 0; kk < 4; kk++) {
            uint32_t qa[4];
            {
                int row = w * 16 + (lane & 15);
                int ch = kk * 2 + (lane >> 4);
                uint32_t so = (uint32_t)(row * 128 + ((ch ^ (row & 7)) * 16));
                ldsm_x4(sb + AOFF_Q + so, qa);
            }
            uint32_t kb[4][4];
            #pragma unroll
            for (int np = 0; np < 4; np++) {
                int row = np * 16 + (lane & 7) + ((lane & 16) ? 8 : 0);
                int ch = kk * 2 + ((lane >> 3) & 1);
                uint32_t so = (uint32_t)(row * 128 + ((ch ^ (row & 7)) * 16));
                ldsm_x4(base + so, kb[np]);
            }
            #pragma unroll
            for (int j = 0; j < 8; j++)
                mma_f16(s[j], qa, kb[j >> 1][(j & 1) * 2], kb[j >> 1][(j & 1) * 2 + 1]);
        }

        // ---- softmax in place (bias/mask inline; quad-lane reductions) ----
        #pragma unroll
        for (int hh = 0; hh < 2; hh++) {
            int row = w * 16 + (lane >> 2) + hh * 8;
            const float* bp = biasbase + (size_t)row * SEQ + kt * 64 + (lane & 3) * 2;
            const unsigned char* mp = maskbase + (size_t)row * SEQ + kt * 64 + (lane & 3) * 2;
            float mx = -1e30f;
            #pragma unroll
            for (int j = 0; j < 8; j++) {
                float2 bb = *(const float2*)(bp + j * 8);
                uchar2 mm = *(const uchar2*)(mp + j * 8);
                float v0 = mm.x ? (s[j][hh*2+0] + bb.x) * 0.125f : -1e30f;
                float v1 = mm.y ? (s[j][hh*2+1] + bb.y) * 0.125f : -1e30f;
                s[j][hh*2+0] = v0; s[j][hh*2+1] = v1;
                mx = fmaxf(mx, fmaxf(v0, v1));
            }
            mx = fmaxf(mx, __shfl_xor_sync(0xffffffffu, mx, 1));
            mx = fmaxf(mx, __shfl_xor_sync(0xffffffffu, mx, 2));
            float mn = fmaxf(m[hh], mx);
            float alpha = __expf(m[hh] - mn);
            m[hh] = mn;
            float rs = 0.f;
            #pragma unroll
            for (int j = 0; j < 8; j++) {
                float e0 = __expf(s[j][hh*2+0] - mn);
                float e1 = __expf(s[j][hh*2+1] - mn);
                s[j][hh*2+0] = e0; s[j][hh*2+1] = e1;
                rs += e0 + e1;
            }
            rs += __shfl_xor_sync(0xffffffffu, rs, 1);
            rs += __shfl_xor_sync(0xffffffffu, rs, 2);
            lsum[hh] = lsum[hh] * alpha + rs;
            #pragma unroll
            for (int j = 0; j < 8; j++) {
                accO[j][hh*2+0] *= alpha;
                accO[j][hh*2+1] *= alpha;
            }
        }

        // ---- O += P @ V (single fp16 product) ----
        #pragma unroll
        for (int kk = 0; kk < 4; kk++) {
            int j0 = kk * 2, j1 = kk * 2 + 1;
            uint32_t pa[4];
            pa[0] = pack_half2(s[j0][0], s[j0][1]);
            pa[1] = pack_half2(s[j0][2], s[j0][3]);
            pa[2] = pack_half2(s[j1][0], s[j1][1]);
            pa[3] = pack_half2(s[j1][2], s[j1][3]);
            uint32_t vb[4][4];
            #pragma unroll
            for (int np = 0; np < 4; np++) {
                int i = lane >> 3, jj = lane & 7;
                int tok = kk * 16 + (i & 1) * 8 + jj;
                int ch = np * 2 + (i >> 1);
                uint32_t so = (uint32_t)(tok * 128 + ((ch ^ (tok & 7)) * 16));
                ldsm_x4t(base + 8192 + so, vb[np]);
            }
            #pragma unroll
            for (int j = 0; j < 8; j++)
                mma_f16(accO[j], pa, vb[j >> 1][(j & 1) * 2], vb[j >> 1][(j & 1) * 2 + 1]);
        }
        __syncthreads();
    }

    // ---- epilogue: normalize + split-write (bf16 hi/lo for out-proj) ----
    #pragma unroll
    for (int hh = 0; hh < 2; hh++) {
        float inv = 1.0f / lsum[hh];
        size_t row = qrow0 + w * 16 + (lane >> 2) + hh * 8;
        #pragma unroll
        for (int j = 0; j < 8; j++) {
            int col = hd * HDIM + j * 8 + (lane & 3) * 2;
            float v0 = accO[j][hh*2+0] * inv;
            float v1 = accO[j][hh*2+1] * inv;
            __nv_bfloat16 h0, l0, h1, l1;
            split_bf16(v0, h0, l0);
            split_bf16(v1, h1, l1);
            *(uint32_t*)(outh + row * D + col) = pack_bf16x2(h0, h1);
            *(uint32_t*)(outl + row * D + col) = pack_bf16x2(l0, l1);
        }
    }
}

// ---------------- host launcher --------------------------------------------------
extern "C" void kernel_launch(void* const* d_in, const int* in_sizes, int n_in,
                              void* d_out, int out_size) {
    const float* x     = (const float*)d_in[0];
    const float* bias  = (const float*)d_in[1];
    const int*   mask  = (const int*)d_in[2];
    const float* ln1_w = (const float*)d_in[3];
    const float* ln1_b = (const float*)d_in[4];
    const float* wq    = (const float*)d_in[5];
    const float* bq    = (const float*)d_in[6];
    const float* wk    = (const float*)d_in[7];
    const float* bk    = (const float*)d_in[8];
    const float* wv    = (const float*)d_in[9];
    const float* bv    = (const float*)d_in[10];
    const float* wo    = (const float*)d_in[11];
    const float* bo    = (const float*)d_in[12];
    const float* ln2_w = (const float*)d_in[13];
    const float* ln2_b = (const float*)d_in[14];
    const float* w1    = (const float*)d_in[15];
    const float* b1    = (const float*)d_in[16];
    const float* w2    = (const float*)d_in[17];
    const float* b2    = (const float*)d_in[18];
    float* out = (float*)d_out;

    float *xmid;
    __nv_bfloat16 *xnh, *xnl, *ah, *al, *hh, *hl, *wth, *wtl;
    __half *q16, *k16, *v16;
    unsigned char* mask8;
    cudaGetSymbolAddress((void**)&xmid, g_xmid);
    cudaGetSymbolAddress((void**)&xnh,  g_xnh);
    cudaGetSymbolAddress((void**)&xnl,  g_xnl);
    cudaGetSymbolAddress((void**)&q16,  g_q16);
    cudaGetSymbolAddress((void**)&k16,  g_k16);
    cudaGetSymbolAddress((void**)&v16,  g_v16);
    cudaGetSymbolAddress((void**)&ah,   g_ah);
    cudaGetSymbolAddress((void**)&al,   g_al);
    cudaGetSymbolAddress((void**)&hh,   g_hh);
    cudaGetSymbolAddress((void**)&hl,   g_hl);
    cudaGetSymbolAddress((void**)&wth,  g_wth);
    cudaGetSymbolAddress((void**)&wtl,  g_wtl);
    cudaGetSymbolAddress((void**)&mask8, g_mask8);

    cudaFuncSetAttribute(hmma_gemm, cudaFuncAttributeMaxDynamicSharedMemorySize, GSMEM);
    cudaFuncSetAttribute(qkv_gemm,  cudaFuncAttributeMaxDynamicSharedMemorySize, GSMEM);
    cudaFuncSetAttribute(attn_mma,  cudaFuncAttributeMaxDynamicSharedMemorySize, ASMEM);

    dim3 tgrid(24, 24, 6), tblk(32, 8);
    transpose_split6<<<tgrid, tblk>>>(wq, wk, wv, wo, w1, w2, wth, wtl);
    mask_pack<<<(BATCH*SEQ*SEQ/4 + 255)/256, 256>>>(mask, mask8, BATCH*SEQ*SEQ/4);

    dim3 ggrid(D / NT, NROWS / MT);     // (12, 32)
    dim3 qgrid(3 * D / NT, NROWS / MT); // (36, 32)

    // LN1 -> split
    ln_split<<<NROWS, 256>>>(x, ln1_w, ln1_b, xnh, xnl);
    // merged QKV projections (fp16 out)
    qkv_gemm<<<qgrid, 256, GSMEM>>>(xnh, xnl, wth, wtl, bq, bk, bv, q16, k16, v16);
    // attention (fp16 tensor-core flash) -> split bf16 out
    dim3 attn_grid(SEQ / 128, NHEADS * BATCH);  // (16, 24)
    attn_mma<<<attn_grid, 256, ASMEM>>>(q16, k16, v16, bias, mask8, ah, al);
    // out-proj + residual(x) -> xmid (fp32)
    hmma_gemm<<<ggrid, 256, GSMEM>>>(ah, al, wth + 3*(size_t)D*D, wtl + 3*(size_t)D*D,
                                     bo, x, xmid, nullptr, nullptr, 0);
    // LN2 -> split
    ln_split<<<NROWS, 256>>>(xmid, ln2_w, ln2_b, xnh, xnl);
    // MLP up + ReLU -> split hidden
    hmma_gemm<<<ggrid, 256, GSMEM>>>(xnh, xnl, wth + 4*(size_t)D*D, wtl + 4*(size_t)D*D,
                                     b1, nullptr, nullptr, hh, hl, 1);
    // MLP down + residual(xmid) -> out (fp32)
    hmma_gemm<<<ggrid, 256, GSMEM>>>(hh, hl, wth + 5*(size_t)D*D, wtl + 5*(size_t)D*D,
                                     b2, xmid, out, nullptr, nullptr, 0);
}

// round 9
// speedup vs baseline: 3.9645x; 1.1320x over previous
#include <cuda_runtime.h>
#include <cuda_bf16.h>
#include <cuda_fp16.h>
#include <stdint.h>
#include <math.h>

#define D 768
#define BATCH 2
#define SEQ 2048
#define NROWS (BATCH*SEQ)   // 4096
#define NHEADS 12
#define HDIM 64
#define EPS 1e-5f

#define MT 128              // GEMM CTA M tile
#define NT 64               // GEMM CTA N tile
#define BK 32
#define KSTAGES (D/BK)      // 24

// ---------------- scratch ----------------
__device__ float g_xmid[NROWS*D];
__device__ __nv_bfloat16 g_xnh[NROWS*D], g_xnl[NROWS*D];
__device__ __half g_q16[NROWS*D], g_k16[NROWS*D], g_v16[NROWS*D];
__device__ __nv_bfloat16 g_ah[NROWS*D],  g_al[NROWS*D];
__device__ __nv_bfloat16 g_hh[NROWS*D],  g_hl[NROWS*D];
__device__ __nv_bfloat16 g_wth[6*D*D], g_wtl[6*D*D];
__device__ unsigned char g_mask8[(size_t)BATCH*SEQ*SEQ];

// ---------------- PTX helpers ----------------
__device__ __forceinline__ uint32_t smem_u32(const void* p) {
    uint32_t a;
    asm("{ .reg .u64 t; cvta.to.shared.u64 t, %1; cvt.u32.u64 %0, t; }" : "=r"(a) : "l"(p));
    return a;
}
__device__ __forceinline__ void cp_async16(uint32_t dst, const void* src) {
    asm volatile("cp.async.ca.shared.global [%0], [%1], 16;\n" :: "r"(dst), "l"(src));
}
__device__ __forceinline__ void cp_commit() { asm volatile("cp.async.commit_group;\n"); }
__device__ __forceinline__ void cp_wait0()  { asm volatile("cp.async.wait_group 0;\n" ::: "memory"); }
__device__ __forceinline__ void cp_wait1()  { asm volatile("cp.async.wait_group 1;\n" ::: "memory"); }

__device__ __forceinline__ void ldsm_x4(uint32_t addr, uint32_t* r) {
    asm volatile("ldmatrix.sync.aligned.m8n8.x4.shared.b16 {%0,%1,%2,%3}, [%4];"
                 : "=r"(r[0]), "=r"(r[1]), "=r"(r[2]), "=r"(r[3]) : "r"(addr));
}
__device__ __forceinline__ void ldsm_x4t(uint32_t addr, uint32_t* r) {
    asm volatile("ldmatrix.sync.aligned.m8n8.x4.trans.shared.b16 {%0,%1,%2,%3}, [%4];"
                 : "=r"(r[0]), "=r"(r[1]), "=r"(r[2]), "=r"(r[3]) : "r"(addr));
}
__device__ __forceinline__ void mma_bf16(float* c, const uint32_t* a, uint32_t b0, uint32_t b1) {
    asm volatile("mma.sync.aligned.m16n8k16.row.col.f32.bf16.bf16.f32 "
                 "{%0,%1,%2,%3},{%4,%5,%6,%7},{%8,%9},{%0,%1,%2,%3};"
                 : "+f"(c[0]), "+f"(c[1]), "+f"(c[2]), "+f"(c[3])
                 : "r"(a[0]), "r"(a[1]), "r"(a[2]), "r"(a[3]), "r"(b0), "r"(b1));
}
__device__ __forceinline__ void mma_f16(float* c, const uint32_t* a, uint32_t b0, uint32_t b1) {
    asm volatile("mma.sync.aligned.m16n8k16.row.col.f32.f16.f16.f32 "
                 "{%0,%1,%2,%3},{%4,%5,%6,%7},{%8,%9},{%0,%1,%2,%3};"
                 : "+f"(c[0]), "+f"(c[1]), "+f"(c[2]), "+f"(c[3])
                 : "r"(a[0]), "r"(a[1]), "r"(a[2]), "r"(a[3]), "r"(b0), "r"(b1));
}

// ---------------- split/pack helpers ----------------
__device__ __forceinline__ void split_bf16(float v, __nv_bfloat16& h, __nv_bfloat16& l) {
    h = __float2bfloat16(v);
    l = __float2bfloat16(v - __bfloat162float(h));
}
__device__ __forceinline__ uint32_t pack_bf16x2(__nv_bfloat16 a, __nv_bfloat16 b) {
    __nv_bfloat162 p; p.x = a; p.y = b;
    return *(uint32_t*)&p;
}
__device__ __forceinline__ uint32_t pack_half2(float a, float b) {
    __half2 h = __floats2half2_rn(a, b);
    return *(uint32_t*)&h;
}

// ---------------- weight transpose + split (all 6 in one launch) ----------------
__global__ void transpose_split6(const float* __restrict__ w0, const float* __restrict__ w1,
                                 const float* __restrict__ w2, const float* __restrict__ w3,
                                 const float* __restrict__ w4, const float* __restrict__ w5,
                                 __nv_bfloat16* __restrict__ Th, __nv_bfloat16* __restrict__ Tl) {
    __shared__ float tile[32][33];
    int z = blockIdx.z;
    const float* W = (z == 0) ? w0 : (z == 1) ? w1 : (z == 2) ? w2
                   : (z == 3) ? w3 : (z == 4) ? w4 : w5;
    __nv_bfloat16* th = Th + (size_t)z * D * D;
    __nv_bfloat16* tl = Tl + (size_t)z * D * D;
    int bx = blockIdx.x * 32, by = blockIdx.y * 32;
    int tx = threadIdx.x, ty = threadIdx.y;
    #pragma unroll
    for (int i = 0; i < 4; i++)
        tile[ty + 8*i][tx] = W[(size_t)(by + ty + 8*i) * D + bx + tx];
    __syncthreads();
    #pragma unroll
    for (int i = 0; i < 4; i++) {
        float v = tile[tx][ty + 8*i];
        __nv_bfloat16 h, l; split_bf16(v, h, l);
        size_t idx = (size_t)(bx + ty + 8*i) * D + by + tx;
        th[idx] = h; tl[idx] = l;
    }
}

// ---------------- mask int32 -> int8 ----------------
__global__ void mask_pack(const int* __restrict__ m, unsigned char* __restrict__ m8, int n4) {
    int i = blockIdx.x * blockDim.x + threadIdx.x;
    if (i < n4) {
        int4 v = *(const int4*)(m + (size_t)i * 4);
        uchar4 o;
        o.x = (unsigned char)v.x; o.y = (unsigned char)v.y;
        o.z = (unsigned char)v.z; o.w = (unsigned char)v.w;
        *(uchar4*)(m8 + (size_t)i * 4) = o;
    }
}

// ---------------- LayerNorm -> bf16 hi/lo ----------------
__global__ void ln_split(const float* __restrict__ x, const float* __restrict__ w,
                         const float* __restrict__ b,
                         __nv_bfloat16* __restrict__ yh, __nv_bfloat16* __restrict__ yl) {
    __shared__ float sh_s[8], sh_ss[8];
    __shared__ float mu_sh, rstd_sh;
    int row = blockIdx.x;
    const float* xr = x + (size_t)row * D;
    int t = threadIdx.x;
    float v0 = xr[t], v1 = xr[t + 256], v2 = xr[t + 512];
    float s  = v0 + v1 + v2;
    float ss = v0*v0 + v1*v1 + v2*v2;
    #pragma unroll
    for (int o = 16; o > 0; o >>= 1) {
        s  += __shfl_xor_sync(0xffffffffu, s,  o);
        ss += __shfl_xor_sync(0xffffffffu, ss, o);
    }
    int wid = t >> 5, lane = t & 31;
    if (lane == 0) { sh_s[wid] = s; sh_ss[wid] = ss; }
    __syncthreads();
    if (t == 0) {
        float S = 0.f, SS = 0.f;
        #pragma unroll
        for (int i = 0; i < 8; i++) { S += sh_s[i]; SS += sh_ss[i]; }
        float mu = S / (float)D;
        float var = SS / (float)D - mu * mu;
        mu_sh = mu; rstd_sh = rsqrtf(var + EPS);
    }
    __syncthreads();
    float mu = mu_sh, rs = rstd_sh;
    size_t base = (size_t)row * D;
    #pragma unroll
    for (int i = 0; i < 3; i++) {
        int c = t + 256 * i;
        float v = (i == 0) ? v0 : (i == 1) ? v1 : v2;
        float o = (v - mu) * rs * w[c] + b[c];
        __nv_bfloat16 h, l; split_bf16(o, h, l);
        yh[base + c] = h; yl[base + c] = l;
    }
}

// ---------------- HMMA split-precision GEMM core ----------------
#define STG 24576
#define OFF_AH 0
#define OFF_AL 8192
#define OFF_BH 16384
#define OFF_BL 20480
#define GSMEM  (2*STG)

__device__ __forceinline__ void gemm_core(
    const __nv_bfloat16* __restrict__ Ah, const __nv_bfloat16* __restrict__ Al,
    const __nv_bfloat16* __restrict__ Bh, const __nv_bfloat16* __restrict__ Bl,
    const float* __restrict__ bias, const float* __restrict__ res,
    float* __restrict__ Cf, __nv_bfloat16* __restrict__ Ch,
    __nv_bfloat16* __restrict__ Cl, __half* __restrict__ C16,
    int relu, int brow, int bcol, uint32_t sb)
{
    int t = threadIdx.x;
    int wid = t >> 5, lane = t & 31;
    int wm = wid & 3, wn = wid >> 2;

    float acc[2][4][4];
    #pragma unroll
    for (int i = 0; i < 2; i++)
        #pragma unroll
        for (int j = 0; j < 4; j++)
            #pragma unroll
            for (int c = 0; c < 4; c++) acc[i][j][c] = 0.f;

    auto load_stage = [&](int s) {
        uint32_t base = sb + (uint32_t)((s & 1) * STG);
        int k0 = s * BK;
        #pragma unroll
        for (int i = 0; i < 2; i++) {
            int id = t + i * 256;
            int r = id >> 2, c = id & 3;
            uint32_t so = (uint32_t)(r * 64 + ((c ^ ((r >> 1) & 3)) * 16));
            size_t g = (size_t)(brow + r) * D + k0 + c * 8;
            cp_async16(base + OFF_AH + so, Ah + g);
            cp_async16(base + OFF_AL + so, Al + g);
        }
        {
            int r = t >> 2, c = t & 3;
            uint32_t so = (uint32_t)(r * 64 + ((c ^ ((r >> 1) & 3)) * 16));
            size_t g = (size_t)(bcol + r) * D + k0 + c * 8;
            cp_async16(base + OFF_BH + so, Bh + g);
            cp_async16(base + OFF_BL + so, Bl + g);
        }
        cp_commit();
    };

    load_stage(0);

    for (int s = 0; s < KSTAGES; s++) {
        if (s < KSTAGES - 1) load_stage(s + 1);
        if (s < KSTAGES - 1) cp_wait1(); else cp_wait0();
        __syncthreads();

        uint32_t base = sb + (uint32_t)((s & 1) * STG);
        #pragma unroll
        for (int kstep = 0; kstep < 2; kstep++) {
            uint32_t ah[2][4], al_[2][4];
            #pragma unroll
            for (int mt = 0; mt < 2; mt++) {
                int row = wm * 32 + mt * 16 + (lane & 15);
                int chunk = kstep * 2 + (lane >> 4);
                uint32_t so = (uint32_t)(row * 64 + ((chunk ^ ((row >> 1) & 3)) * 16));
                ldsm_x4(base + OFF_AH + so, ah[mt]);
                ldsm_x4(base + OFF_AL + so, al_[mt]);
            }
            uint32_t bh[2][4], bl[2][4];
            #pragma unroll
            for (int nt2 = 0; nt2 < 2; nt2++) {
                int row = wn * 32 + nt2 * 16 + (lane & 7) + ((lane & 16) ? 8 : 0);
                int chunk = kstep * 2 + ((lane >> 3) & 1);
                uint32_t so = (uint32_t)(row * 64 + ((chunk ^ ((row >> 1) & 3)) * 16));
                ldsm_x4(base + OFF_BH + so, bh[nt2]);
                ldsm_x4(base + OFF_BL + so, bl[nt2]);
            }
            #pragma unroll
            for (int mt = 0; mt < 2; mt++)
                #pragma unroll
                for (int nt = 0; nt < 4; nt++) {
                    float* c = acc[mt][nt];
                    uint32_t b0h = bh[nt >> 1][(nt & 1) * 2], b1h = bh[nt >> 1][(nt & 1) * 2 + 1];
                    uint32_t b0l = bl[nt >> 1][(nt & 1) * 2], b1l = bl[nt >> 1][(nt & 1) * 2 + 1];
                    mma_bf16(c, ah[mt],  b0h, b1h);
                    mma_bf16(c, ah[mt],  b0l, b1l);
                    mma_bf16(c, al_[mt], b0h, b1h);
                }
        }
        __syncthreads();
    }

    #pragma unroll
    for (int mt = 0; mt < 2; mt++) {
        #pragma unroll
        for (int nt = 0; nt < 4; nt++) {
            float* c = acc[mt][nt];
            int col = bcol + wn * 32 + nt * 8 + (lane & 3) * 2;
            #pragma unroll
            for (int half = 0; half < 2; half++) {
                int row = brow + wm * 32 + mt * 16 + (lane >> 2) + half * 8;
                float2 o;
                o.x = c[half * 2 + 0];
                o.y = c[half * 2 + 1];
                const float2 bb = *(const float2*)(bias + col);
                o.x += bb.x; o.y += bb.y;
                size_t gidx = (size_t)row * D + col;
                if (res) {
                    float2 rv = *(const float2*)(res + gidx);
                    o.x += rv.x; o.y += rv.y;
                }
                if (relu) { o.x = fmaxf(o.x, 0.f); o.y = fmaxf(o.y, 0.f); }
                if (Cf) *(float2*)(Cf + gidx) = o;
                if (C16) *(uint32_t*)(C16 + gidx) = pack_half2(o.x, o.y);
                if (Ch) {
                    __nv_bfloat16 h0, l0, h1, l1;
                    split_bf16(o.x, h0, l0);
                    split_bf16(o.y, h1, l1);
                    *(uint32_t*)(Ch + gidx) = pack_bf16x2(h0, h1);
                    *(uint32_t*)(Cl + gidx) = pack_bf16x2(l0, l1);
                }
            }
        }
    }
}

__global__ void __launch_bounds__(256, 2)
hmma_gemm(const __nv_bfloat16* __restrict__ Ah, const __nv_bfloat16* __restrict__ Al,
          const __nv_bfloat16* __restrict__ Bh, const __nv_bfloat16* __restrict__ Bl,
          const float* __restrict__ bias, const float* __restrict__ res,
          float* __restrict__ Cf, __nv_bfloat16* __restrict__ Ch,
          __nv_bfloat16* __restrict__ Cl, int relu)
{
    extern __shared__ char smem[];
    gemm_core(Ah, Al, Bh, Bl, bias, res, Cf, Ch, Cl, nullptr, relu,
              blockIdx.y * MT, blockIdx.x * NT, smem_u32(smem));
}

// Merged QKV: grid.x = 36 (sel = x/12, col tile = x%12); fp16 outputs
__global__ void __launch_bounds__(256, 2)
qkv_gemm(const __nv_bfloat16* __restrict__ Ah, const __nv_bfloat16* __restrict__ Al,
         const __nv_bfloat16* __restrict__ Wth, const __nv_bfloat16* __restrict__ Wtl,
         const float* __restrict__ bq, const float* __restrict__ bk, const float* __restrict__ bv,
         __half* __restrict__ q16, __half* __restrict__ k16, __half* __restrict__ v16)
{
    extern __shared__ char smem[];
    int sel = blockIdx.x / 12;
    int bcol = (blockIdx.x % 12) * NT;
    const __nv_bfloat16* Bh = Wth + (size_t)sel * D * D;
    const __nv_bfloat16* Bl = Wtl + (size_t)sel * D * D;
    const float* bias = (sel == 0) ? bq : (sel == 1) ? bk : bv;
    __half* C16 = (sel == 0) ? q16 : (sel == 1) ? k16 : v16;
    gemm_core(Ah, Al, Bh, Bl, bias, nullptr, nullptr, nullptr, nullptr, C16, 0,
              blockIdx.y * MT, bcol, smem_u32(smem));
}

// ---------------- fp16 tensor-core flash attention ----------------
// 128q x 64k tiles, 8 warps. cp.async-pipelined K/V AND bias/mask.
#define AOFF_Q    0
#define AOFF_KV   16384              // + buf*16384 : K(8K) V(8K)
#define AOFF_BIAS 49152              // 128 rows x 272B (64 fp32 + 16B pad)
#define AOFF_MASK 83968              // 128 rows x 80B  (64 u8 + 16B pad)
#define ASMEM     94208

__global__ void __launch_bounds__(256, 2)
attn_mma(const __half* __restrict__ q16, const __half* __restrict__ k16,
         const __half* __restrict__ v16,
         const float* __restrict__ bias, const unsigned char* __restrict__ mask8,
         __nv_bfloat16* __restrict__ outh, __nv_bfloat16* __restrict__ outl)
{
    extern __shared__ char smem[];
    uint32_t sb = smem_u32(smem);
    int t = threadIdx.x;
    int w = t >> 5, lane = t & 31;

    int qt = blockIdx.x;          // 0..15
    int hb = blockIdx.y;          // 0..23
    int hd = hb >> 1;
    int b  = hb & 1;

    size_t qrow0 = (size_t)b * SEQ + qt * 128;
    const __half* qg = q16 + qrow0 * D + hd * HDIM;
    const __half* kg = k16 + (size_t)b * SEQ * D + hd * HDIM;
    const __half* vg = v16 + (size_t)b * SEQ * D + hd * HDIM;
    const float* biasbase = bias + ((size_t)(hd * BATCH + b) * SEQ + qt * 128) * SEQ;
    const unsigned char* maskbase = mask8 + ((size_t)b * SEQ + qt * 128) * SEQ;

    // Q tile (128x64 fp16), swizzled — its own group
    #pragma unroll
    for (int i = 0; i < 4; i++) {
        int id = t + i * 256;
        int row = id >> 3, c = id & 7;
        uint32_t so = (uint32_t)(row * 128 + ((c ^ (row & 7)) * 16));
        cp_async16(sb + AOFF_Q + so, qg + (size_t)row * D + c * 8);
    }
    cp_commit();

    auto load_kv = [&](int kt) {
        uint32_t base = sb + AOFF_KV + (uint32_t)((kt & 1) * 16384);
        #pragma unroll
        for (int i = 0; i < 2; i++) {
            int id = t + i * 256;
            int row = id >> 3, c = id & 7;
            uint32_t so = (uint32_t)(row * 128 + ((c ^ (row & 7)) * 16));
            size_t g = (size_t)(kt * 64 + row) * D + c * 8;
            cp_async16(base + so,        kg + g);
            cp_async16(base + 8192 + so, vg + g);
        }
        cp_commit();
    };

    // bias (128x64 fp32 -> 2048 16B chunks) + mask (128x64 u8 -> 512 chunks)
    auto load_bm = [&](int kt) {
        #pragma unroll
        for (int i = 0; i < 8; i++) {
            int id = t + i * 256;
            int row = id >> 4, c = id & 15;
            cp_async16(sb + AOFF_BIAS + (uint32_t)(row * 272 + c * 16),
                       biasbase + (size_t)row * SEQ + kt * 64 + c * 4);
        }
        #pragma unroll
        for (int i = 0; i < 2; i++) {
            int id = t + i * 256;
            int row = id >> 2, c = id & 3;
            cp_async16(sb + AOFF_MASK + (uint32_t)(row * 80 + c * 16),
                       maskbase + (size_t)row * SEQ + kt * 64 + c * 16);
        }
        cp_commit();
    };

    load_kv(0);
    load_bm(0);
    load_kv(1);

    float accO[8][4];
    #pragma unroll
    for (int j = 0; j < 8; j++)
        #pragma unroll
        for (int c = 0; c < 4; c++) accO[j][c] = 0.f;
    float m[2] = {-1e30f, -1e30f}, lsum[2] = {0.f, 0.f};

    const int NKT = SEQ / 64;   // 32
    for (int kt = 0; kt < NKT; kt++) {
        // need KV(kt) + bias(kt); KV(kt+1) may stay in flight
        if (kt < NKT - 1) cp_wait1(); else cp_wait0();
        __syncthreads();

        uint32_t base = sb + AOFF_KV + (uint32_t)((kt & 1) * 16384);

        // ---- S = Q @ K^T ----
        float s[8][4];
        #pragma unroll
        for (int j = 0; j < 8; j++)
            #pragma unroll
            for (int c = 0; c < 4; c++) s[j][c] = 0.f;

        #pragma unroll
        for (int kk = 0; kk < 4; kk++) {
            uint32_t qa[4];
            {
                int row = w * 16 + (lane & 15);
                int ch = kk * 2 + (lane >> 4);
                uint32_t so = (uint32_t)(row * 128 + ((ch ^ (row & 7)) * 16));
                ldsm_x4(sb + AOFF_Q + so, qa);
            }
            uint32_t kb[4][4];
            #pragma unroll
            for (int np = 0; np < 4; np++) {
                int row = np * 16 + (lane & 7) + ((lane & 16) ? 8 : 0);
                int ch = kk * 2 + ((lane >> 3) & 1);
                uint32_t so = (uint32_t)(row * 128 + ((ch ^ (row & 7)) * 16));
                ldsm_x4(base + so, kb[np]);
            }
            #pragma unroll
            for (int j = 0; j < 8; j++)
                mma_f16(s[j], qa, kb[j >> 1][(j & 1) * 2], kb[j >> 1][(j & 1) * 2 + 1]);
        }

        // ---- softmax in place (bias/mask from SMEM) ----
        #pragma unroll
        for (int hh = 0; hh < 2; hh++) {
            int row = w * 16 + (lane >> 2) + hh * 8;
            const float* bsm = (const float*)(smem + AOFF_BIAS + (size_t)row * 272)
                               + (lane & 3) * 2;
            const unsigned char* msm = (const unsigned char*)(smem + AOFF_MASK
                               + (size_t)row * 80) + (lane & 3) * 2;
            float mx = -1e30f;
            #pragma unroll
            for (int j = 0; j < 8; j++) {
                float2 bb = *(const float2*)(bsm + j * 8);
                uchar2 mm = *(const uchar2*)(msm + j * 8);
                float v0 = mm.x ? (s[j][hh*2+0] + bb.x) * 0.125f : -1e30f;
                float v1 = mm.y ? (s[j][hh*2+1] + bb.y) * 0.125f : -1e30f;
                s[j][hh*2+0] = v0; s[j][hh*2+1] = v1;
                mx = fmaxf(mx, fmaxf(v0, v1));
            }
            mx = fmaxf(mx, __shfl_xor_sync(0xffffffffu, mx, 1));
            mx = fmaxf(mx, __shfl_xor_sync(0xffffffffu, mx, 2));
            float mn = fmaxf(m[hh], mx);
            float alpha = __expf(m[hh] - mn);
            m[hh] = mn;
            float rs = 0.f;
            #pragma unroll
            for (int j = 0; j < 8; j++) {
                float e0 = __expf(s[j][hh*2+0] - mn);
                float e1 = __expf(s[j][hh*2+1] - mn);
                s[j][hh*2+0] = e0; s[j][hh*2+1] = e1;
                rs += e0 + e1;
            }
            rs += __shfl_xor_sync(0xffffffffu, rs, 1);
            rs += __shfl_xor_sync(0xffffffffu, rs, 2);
            lsum[hh] = lsum[hh] * alpha + rs;
            #pragma unroll
            for (int j = 0; j < 8; j++) {
                accO[j][hh*2+0] *= alpha;
                accO[j][hh*2+1] *= alpha;
            }
        }

        // ---- O += P @ V ----
        #pragma unroll
        for (int kk = 0; kk < 4; kk++) {
            int j0 = kk * 2, j1 = kk * 2 + 1;
            uint32_t pa[4];
            pa[0] = pack_half2(s[j0][0], s[j0][1]);
            pa[1] = pack_half2(s[j0][2], s[j0][3]);
            pa[2] = pack_half2(s[j1][0], s[j1][1]);
            pa[3] = pack_half2(s[j1][2], s[j1][3]);
            uint32_t vb[4][4];
            #pragma unroll
            for (int np = 0; np < 4; np++) {
                int i = lane >> 3, jj = lane & 7;
                int tok = kk * 16 + (i & 1) * 8 + jj;
                int ch = np * 2 + (i >> 1);
                uint32_t so = (uint32_t)(tok * 128 + ((ch ^ (tok & 7)) * 16));
                ldsm_x4t(base + 8192 + so, vb[np]);
            }
            #pragma unroll
            for (int j = 0; j < 8; j++)
                mma_f16(accO[j], pa, vb[j >> 1][(j & 1) * 2], vb[j >> 1][(j & 1) * 2 + 1]);
        }
        __syncthreads();   // all consumers done: bias & KV(kt) buffers reusable

        if (kt + 1 < NKT) load_bm(kt + 1);
        if (kt + 2 < NKT) load_kv(kt + 2);
    }

    // ---- epilogue: normalize + split-write ----
    #pragma unroll
    for (int hh = 0; hh < 2; hh++) {
        float inv = 1.0f / lsum[hh];
        size_t row = qrow0 + w * 16 + (lane >> 2) + hh * 8;
        #pragma unroll
        for (int j = 0; j < 8; j++) {
            int col = hd * HDIM + j * 8 + (lane & 3) * 2;
            float v0 = accO[j][hh*2+0] * inv;
            float v1 = accO[j][hh*2+1] * inv;
            __nv_bfloat16 h0, l0, h1, l1;
            split_bf16(v0, h0, l0);
            split_bf16(v1, h1, l1);
            *(uint32_t*)(outh + row * D + col) = pack_bf16x2(h0, h1);
            *(uint32_t*)(outl + row * D + col) = pack_bf16x2(l0, l1);
        }
    }
}

// ---------------- host launcher --------------------------------------------------
extern "C" void kernel_launch(void* const* d_in, const int* in_sizes, int n_in,
                              void* d_out, int out_size) {
    const float* x     = (const float*)d_in[0];
    const float* bias  = (const float*)d_in[1];
    const int*   mask  = (const int*)d_in[2];
    const float* ln1_w = (const float*)d_in[3];
    const float* ln1_b = (const float*)d_in[4];
    const float* wq    = (const float*)d_in[5];
    const float* bq    = (const float*)d_in[6];
    const float* wk    = (const float*)d_in[7];
    const float* bk    = (const float*)d_in[8];
    const float* wv    = (const float*)d_in[9];
    const float* bv    = (const float*)d_in[10];
    const float* wo    = (const float*)d_in[11];
    const float* bo    = (const float*)d_in[12];
    const float* ln2_w = (const float*)d_in[13];
    const float* ln2_b = (const float*)d_in[14];
    const float* w1    = (const float*)d_in[15];
    const float* b1    = (const float*)d_in[16];
    const float* w2    = (const float*)d_in[17];
    const float* b2    = (const float*)d_in[18];
    float* out = (float*)d_out;

    float *xmid;
    __nv_bfloat16 *xnh, *xnl, *ah, *al, *hh, *hl, *wth, *wtl;
    __half *q16, *k16, *v16;
    unsigned char* mask8;
    cudaGetSymbolAddress((void**)&xmid, g_xmid);
    cudaGetSymbolAddress((void**)&xnh,  g_xnh);
    cudaGetSymbolAddress((void**)&xnl,  g_xnl);
    cudaGetSymbolAddress((void**)&q16,  g_q16);
    cudaGetSymbolAddress((void**)&k16,  g_k16);
    cudaGetSymbolAddress((void**)&v16,  g_v16);
    cudaGetSymbolAddress((void**)&ah,   g_ah);
    cudaGetSymbolAddress((void**)&al,   g_al);
    cudaGetSymbolAddress((void**)&hh,   g_hh);
    cudaGetSymbolAddress((void**)&hl,   g_hl);
    cudaGetSymbolAddress((void**)&wth,  g_wth);
    cudaGetSymbolAddress((void**)&wtl,  g_wtl);
    cudaGetSymbolAddress((void**)&mask8, g_mask8);

    cudaFuncSetAttribute(hmma_gemm, cudaFuncAttributeMaxDynamicSharedMemorySize, GSMEM);
    cudaFuncSetAttribute(qkv_gemm,  cudaFuncAttributeMaxDynamicSharedMemorySize, GSMEM);
    cudaFuncSetAttribute(attn_mma,  cudaFuncAttributeMaxDynamicSharedMemorySize, ASMEM);

    dim3 tgrid(24, 24, 6), tblk(32, 8);
    transpose_split6<<<tgrid, tblk>>>(wq, wk, wv, wo, w1, w2, wth, wtl);
    mask_pack<<<(BATCH*SEQ*SEQ/4 + 255)/256, 256>>>(mask, mask8, BATCH*SEQ*SEQ/4);

    dim3 ggrid(D / NT, NROWS / MT);     // (12, 32)
    dim3 qgrid(3 * D / NT, NROWS / MT); // (36, 32)

    // LN1 -> split
    ln_split<<<NROWS, 256>>>(x, ln1_w, ln1_b, xnh, xnl);
    // merged QKV projections (fp16 out)
    qkv_gemm<<<qgrid, 256, GSMEM>>>(xnh, xnl, wth, wtl, bq, bk, bv, q16, k16, v16);
    // attention (fp16 tensor-core flash, fully cp.async-pipelined)
    dim3 attn_grid(SEQ / 128, NHEADS * BATCH);  // (16, 24)
    attn_mma<<<attn_grid, 256, ASMEM>>>(q16, k16, v16, bias, mask8, ah, al);
    // out-proj + residual(x) -> xmid (fp32)
    hmma_gemm<<<ggrid, 256, GSMEM>>>(ah, al, wth + 3*(size_t)D*D, wtl + 3*(size_t)D*D,
                                     bo, x, xmid, nullptr, nullptr, 0);
    // LN2 -> split
    ln_split<<<NROWS, 256>>>(xmid, ln2_w, ln2_b, xnh, xnl);
    // MLP up + ReLU -> split hidden
    hmma_gemm<<<ggrid, 256, GSMEM>>>(xnh, xnl, wth + 4*(size_t)D*D, wtl + 4*(size_t)D*D,
                                     b1, nullptr, nullptr, hh, hl, 1);
    // MLP down + residual(xmid) -> out (fp32)
    hmma_gemm<<<ggrid, 256, GSMEM>>>(hh, hl, wth + 5*(size_t)D*D, wtl + 5*(size_t)D*D,
                                     b2, xmid, out, nullptr, nullptr, 0);
}

// round 10
// speedup vs baseline: 5.6291x; 1.4199x over previous
#include <cuda_runtime.h>
#include <cuda_fp16.h>
#include <stdint.h>
#include <math.h>

#define D 768
#define BATCH 2
#define SEQ 2048
#define NROWS (BATCH*SEQ)   // 4096
#define NHEADS 12
#define HDIM 64
#define EPS 1e-5f

#define MT 128              // GEMM CTA M tile
#define NT 64               // GEMM CTA N tile
#define BK 32
#define KSTAGES (D/BK)      // 24

// ---------------- scratch ----------------
__device__ float g_xmid[NROWS*D];
__device__ __half g_xn16[NROWS*D];
__device__ __half g_q16[NROWS*D], g_k16[NROWS*D], g_v16[NROWS*D];
__device__ __half g_a16[NROWS*D];
__device__ __half g_h16[NROWS*D];
__device__ __half g_wt16[6*D*D];
__device__ unsigned char g_mask8[(size_t)BATCH*SEQ*SEQ];

// ---------------- PTX helpers ----------------
__device__ __forceinline__ uint32_t smem_u32(const void* p) {
    uint32_t a;
    asm("{ .reg .u64 t; cvta.to.shared.u64 t, %1; cvt.u32.u64 %0, t; }" : "=r"(a) : "l"(p));
    return a;
}
__device__ __forceinline__ void cp_async16(uint32_t dst, const void* src) {
    asm volatile("cp.async.ca.shared.global [%0], [%1], 16;\n" :: "r"(dst), "l"(src));
}
__device__ __forceinline__ void cp_commit() { asm volatile("cp.async.commit_group;\n"); }
__device__ __forceinline__ void cp_wait0()  { asm volatile("cp.async.wait_group 0;\n" ::: "memory"); }
__device__ __forceinline__ void cp_wait1()  { asm volatile("cp.async.wait_group 1;\n" ::: "memory"); }

__device__ __forceinline__ void ldsm_x4(uint32_t addr, uint32_t* r) {
    asm volatile("ldmatrix.sync.aligned.m8n8.x4.shared.b16 {%0,%1,%2,%3}, [%4];"
                 : "=r"(r[0]), "=r"(r[1]), "=r"(r[2]), "=r"(r[3]) : "r"(addr));
}
__device__ __forceinline__ void ldsm_x4t(uint32_t addr, uint32_t* r) {
    asm volatile("ldmatrix.sync.aligned.m8n8.x4.trans.shared.b16 {%0,%1,%2,%3}, [%4];"
                 : "=r"(r[0]), "=r"(r[1]), "=r"(r[2]), "=r"(r[3]) : "r"(addr));
}
__device__ __forceinline__ void mma_f16(float* c, const uint32_t* a, uint32_t b0, uint32_t b1) {
    asm volatile("mma.sync.aligned.m16n8k16.row.col.f32.f16.f16.f32 "
                 "{%0,%1,%2,%3},{%4,%5,%6,%7},{%8,%9},{%0,%1,%2,%3};"
                 : "+f"(c[0]), "+f"(c[1]), "+f"(c[2]), "+f"(c[3])
                 : "r"(a[0]), "r"(a[1]), "r"(a[2]), "r"(a[3]), "r"(b0), "r"(b1));
}

__device__ __forceinline__ uint32_t pack_half2(float a, float b) {
    __half2 h = __floats2half2_rn(a, b);
    return *(uint32_t*)&h;
}

// ---------------- weight transpose -> fp16 (all 6 in one launch) ----------------
__global__ void transpose6(const float* __restrict__ w0, const float* __restrict__ w1,
                           const float* __restrict__ w2, const float* __restrict__ w3,
                           const float* __restrict__ w4, const float* __restrict__ w5,
                           __half* __restrict__ T16) {
    __shared__ float tile[32][33];
    int z = blockIdx.z;
    const float* W = (z == 0) ? w0 : (z == 1) ? w1 : (z == 2) ? w2
                   : (z == 3) ? w3 : (z == 4) ? w4 : w5;
    __half* t16 = T16 + (size_t)z * D * D;
    int bx = blockIdx.x * 32, by = blockIdx.y * 32;
    int tx = threadIdx.x, ty = threadIdx.y;
    #pragma unroll
    for (int i = 0; i < 4; i++)
        tile[ty + 8*i][tx] = W[(size_t)(by + ty + 8*i) * D + bx + tx];
    __syncthreads();
    #pragma unroll
    for (int i = 0; i < 4; i++) {
        float v = tile[tx][ty + 8*i];
        t16[(size_t)(bx + ty + 8*i) * D + by + tx] = __float2half(v);
    }
}

// ---------------- mask int32 -> int8 ----------------
__global__ void mask_pack(const int* __restrict__ m, unsigned char* __restrict__ m8, int n4) {
    int i = blockIdx.x * blockDim.x + threadIdx.x;
    if (i < n4) {
        int4 v = *(const int4*)(m + (size_t)i * 4);
        uchar4 o;
        o.x = (unsigned char)v.x; o.y = (unsigned char)v.y;
        o.z = (unsigned char)v.z; o.w = (unsigned char)v.w;
        *(uchar4*)(m8 + (size_t)i * 4) = o;
    }
}

// ---------------- LayerNorm -> fp16 ----------------
__global__ void ln_f16(const float* __restrict__ x, const float* __restrict__ w,
                       const float* __restrict__ b, __half* __restrict__ y16) {
    __shared__ float sh_s[8], sh_ss[8];
    __shared__ float mu_sh, rstd_sh;
    int row = blockIdx.x;
    const float* xr = x + (size_t)row * D;
    int t = threadIdx.x;
    float v0 = xr[t], v1 = xr[t + 256], v2 = xr[t + 512];
    float s  = v0 + v1 + v2;
    float ss = v0*v0 + v1*v1 + v2*v2;
    #pragma unroll
    for (int o = 16; o > 0; o >>= 1) {
        s  += __shfl_xor_sync(0xffffffffu, s,  o);
        ss += __shfl_xor_sync(0xffffffffu, ss, o);
    }
    int wid = t >> 5, lane = t & 31;
    if (lane == 0) { sh_s[wid] = s; sh_ss[wid] = ss; }
    __syncthreads();
    if (t == 0) {
        float S = 0.f, SS = 0.f;
        #pragma unroll
        for (int i = 0; i < 8; i++) { S += sh_s[i]; SS += sh_ss[i]; }
        float mu = S / (float)D;
        float var = SS / (float)D - mu * mu;
        mu_sh = mu; rstd_sh = rsqrtf(var + EPS);
    }
    __syncthreads();
    float mu = mu_sh, rs = rstd_sh;
    size_t base = (size_t)row * D;
    #pragma unroll
    for (int i = 0; i < 3; i++) {
        int c = t + 256 * i;
        float v = (i == 0) ? v0 : (i == 1) ? v1 : v2;
        float o = (v - mu) * rs * w[c] + b[c];
        y16[base + c] = __float2half(o);
    }
}

// ---------------- fp16 HMMA GEMM core ----------------
// C[4096,768] = A16 @ W16^T + bias (+res)(relu); Wt[n][k].
// CTA 128x64, 8 warps (4Mx2N), BK=32, double-buffered cp.async.
#define STG 12288
#define OFF_A 0
#define OFF_B 8192
#define GSMEM (2*STG)

__device__ __forceinline__ void gemm_core_f16(
    const __half* __restrict__ A16, const __half* __restrict__ W16,
    const float* __restrict__ bias, const float* __restrict__ res,
    float* __restrict__ Cf, __half* __restrict__ C16,
    int relu, int brow, int bcol, uint32_t sb)
{
    int t = threadIdx.x;
    int wid = t >> 5, lane = t & 31;
    int wm = wid & 3, wn = wid >> 2;

    float acc[2][4][4];
    #pragma unroll
    for (int i = 0; i < 2; i++)
        #pragma unroll
        for (int j = 0; j < 4; j++)
            #pragma unroll
            for (int c = 0; c < 4; c++) acc[i][j][c] = 0.f;

    auto load_stage = [&](int s) {
        uint32_t base = sb + (uint32_t)((s & 1) * STG);
        int k0 = s * BK;
        #pragma unroll
        for (int i = 0; i < 2; i++) {
            int id = t + i * 256;
            int r = id >> 2, c = id & 3;
            uint32_t so = (uint32_t)(r * 64 + ((c ^ ((r >> 1) & 3)) * 16));
            cp_async16(base + OFF_A + so, A16 + (size_t)(brow + r) * D + k0 + c * 8);
        }
        {
            int r = t >> 2, c = t & 3;
            uint32_t so = (uint32_t)(r * 64 + ((c ^ ((r >> 1) & 3)) * 16));
            cp_async16(base + OFF_B + so, W16 + (size_t)(bcol + r) * D + k0 + c * 8);
        }
        cp_commit();
    };

    load_stage(0);

    for (int s = 0; s < KSTAGES; s++) {
        if (s < KSTAGES - 1) load_stage(s + 1);
        if (s < KSTAGES - 1) cp_wait1(); else cp_wait0();
        __syncthreads();

        uint32_t base = sb + (uint32_t)((s & 1) * STG);
        #pragma unroll
        for (int kstep = 0; kstep < 2; kstep++) {
            uint32_t af[2][4];
            #pragma unroll
            for (int mt = 0; mt < 2; mt++) {
                int row = wm * 32 + mt * 16 + (lane & 15);
                int chunk = kstep * 2 + (lane >> 4);
                uint32_t so = (uint32_t)(row * 64 + ((chunk ^ ((row >> 1) & 3)) * 16));
                ldsm_x4(base + OFF_A + so, af[mt]);
            }
            uint32_t bf[2][4];
            #pragma unroll
            for (int nt2 = 0; nt2 < 2; nt2++) {
                int row = wn * 32 + nt2 * 16 + (lane & 7) + ((lane & 16) ? 8 : 0);
                int chunk = kstep * 2 + ((lane >> 3) & 1);
                uint32_t so = (uint32_t)(row * 64 + ((chunk ^ ((row >> 1) & 3)) * 16));
                ldsm_x4(base + OFF_B + so, bf[nt2]);
            }
            #pragma unroll
            for (int mt = 0; mt < 2; mt++)
                #pragma unroll
                for (int nt = 0; nt < 4; nt++)
                    mma_f16(acc[mt][nt], af[mt],
                            bf[nt >> 1][(nt & 1) * 2], bf[nt >> 1][(nt & 1) * 2 + 1]);
        }
        __syncthreads();
    }

    #pragma unroll
    for (int mt = 0; mt < 2; mt++) {
        #pragma unroll
        for (int nt = 0; nt < 4; nt++) {
            float* c = acc[mt][nt];
            int col = bcol + wn * 32 + nt * 8 + (lane & 3) * 2;
            #pragma unroll
            for (int half = 0; half < 2; half++) {
                int row = brow + wm * 32 + mt * 16 + (lane >> 2) + half * 8;
                float2 o;
                o.x = c[half * 2 + 0];
                o.y = c[half * 2 + 1];
                const float2 bb = *(const float2*)(bias + col);
                o.x += bb.x; o.y += bb.y;
                size_t gidx = (size_t)row * D + col;
                if (res) {
                    float2 rv = *(const float2*)(res + gidx);
                    o.x += rv.x; o.y += rv.y;
                }
                if (relu) { o.x = fmaxf(o.x, 0.f); o.y = fmaxf(o.y, 0.f); }
                if (Cf)  *(float2*)(Cf + gidx) = o;
                if (C16) *(uint32_t*)(C16 + gidx) = pack_half2(o.x, o.y);
            }
        }
    }
}

__global__ void __launch_bounds__(256, 3)
hmma_gemm(const __half* __restrict__ A16, const __half* __restrict__ W16,
          const float* __restrict__ bias, const float* __restrict__ res,
          float* __restrict__ Cf, __half* __restrict__ C16, int relu)
{
    extern __shared__ char smem[];
    gemm_core_f16(A16, W16, bias, res, Cf, C16, relu,
                  blockIdx.y * MT, blockIdx.x * NT, smem_u32(smem));
}

// Merged QKV: grid.x = 36 (sel = x/12, col tile = x%12)
__global__ void __launch_bounds__(256, 3)
qkv_gemm(const __half* __restrict__ A16, const __half* __restrict__ Wt16,
         const float* __restrict__ bq, const float* __restrict__ bk, const float* __restrict__ bv,
         __half* __restrict__ q16, __half* __restrict__ k16, __half* __restrict__ v16)
{
    extern __shared__ char smem[];
    int sel = blockIdx.x / 12;
    int bcol = (blockIdx.x % 12) * NT;
    const __half* W = Wt16 + (size_t)sel * D * D;
    const float* bias = (sel == 0) ? bq : (sel == 1) ? bk : bv;
    __half* C16 = (sel == 0) ? q16 : (sel == 1) ? k16 : v16;
    gemm_core_f16(A16, W, bias, nullptr, nullptr, C16, 0,
                  blockIdx.y * MT, bcol, smem_u32(smem));
}

// ---------------- fp16 tensor-core flash attention ----------------
// 128q x 64k tiles, 8 warps. cp.async-pipelined K/V AND bias/mask.
#define AOFF_Q    0
#define AOFF_KV   16384              // + buf*16384 : K(8K) V(8K)
#define AOFF_BIAS 49152              // 128 rows x 272B (64 fp32 + 16B pad)
#define AOFF_MASK 83968              // 128 rows x 80B  (64 u8 + 16B pad)
#define ASMEM     94208

__global__ void __launch_bounds__(256, 2)
attn_mma(const __half* __restrict__ q16, const __half* __restrict__ k16,
         const __half* __restrict__ v16,
         const float* __restrict__ bias, const unsigned char* __restrict__ mask8,
         __half* __restrict__ out16)
{
    extern __shared__ char smem[];
    uint32_t sb = smem_u32(smem);
    int t = threadIdx.x;
    int w = t >> 5, lane = t & 31;

    int qt = blockIdx.x;          // 0..15
    int hb = blockIdx.y;          // 0..23
    int hd = hb >> 1;
    int b  = hb & 1;

    size_t qrow0 = (size_t)b * SEQ + qt * 128;
    const __half* qg = q16 + qrow0 * D + hd * HDIM;
    const __half* kg = k16 + (size_t)b * SEQ * D + hd * HDIM;
    const __half* vg = v16 + (size_t)b * SEQ * D + hd * HDIM;
    const float* biasbase = bias + ((size_t)(hd * BATCH + b) * SEQ + qt * 128) * SEQ;
    const unsigned char* maskbase = mask8 + ((size_t)b * SEQ + qt * 128) * SEQ;

    // Q tile (128x64 fp16), swizzled — its own group
    #pragma unroll
    for (int i = 0; i < 4; i++) {
        int id = t + i * 256;
        int row = id >> 3, c = id & 7;
        uint32_t so = (uint32_t)(row * 128 + ((c ^ (row & 7)) * 16));
        cp_async16(sb + AOFF_Q + so, qg + (size_t)row * D + c * 8);
    }
    cp_commit();

    auto load_kv = [&](int kt) {
        uint32_t base = sb + AOFF_KV + (uint32_t)((kt & 1) * 16384);
        #pragma unroll
        for (int i = 0; i < 2; i++) {
            int id = t + i * 256;
            int row = id >> 3, c = id & 7;
            uint32_t so = (uint32_t)(row * 128 + ((c ^ (row & 7)) * 16));
            size_t g = (size_t)(kt * 64 + row) * D + c * 8;
            cp_async16(base + so,        kg + g);
            cp_async16(base + 8192 + so, vg + g);
        }
        cp_commit();
    };

    auto load_bm = [&](int kt) {
        #pragma unroll
        for (int i = 0; i < 8; i++) {
            int id = t + i * 256;
            int row = id >> 4, c = id & 15;
            cp_async16(sb + AOFF_BIAS + (uint32_t)(row * 272 + c * 16),
                       biasbase + (size_t)row * SEQ + kt * 64 + c * 4);
        }
        #pragma unroll
        for (int i = 0; i < 2; i++) {
            int id = t + i * 256;
            int row = id >> 2, c = id & 3;
            cp_async16(sb + AOFF_MASK + (uint32_t)(row * 80 + c * 16),
                       maskbase + (size_t)row * SEQ + kt * 64 + c * 16);
        }
        cp_commit();
    };

    load_kv(0);
    load_bm(0);
    load_kv(1);

    float accO[8][4];
    #pragma unroll
    for (int j = 0; j < 8; j++)
        #pragma unroll
        for (int c = 0; c < 4; c++) accO[j][c] = 0.f;
    float m[2] = {-1e30f, -1e30f}, lsum[2] = {0.f, 0.f};

    const int NKT = SEQ / 64;   // 32
    for (int kt = 0; kt < NKT; kt++) {
        if (kt < NKT - 1) cp_wait1(); else cp_wait0();
        __syncthreads();

        uint32_t base = sb + AOFF_KV + (uint32_t)((kt & 1) * 16384);

        // ---- S = Q @ K^T ----
        float s[8][4];
        #pragma unroll
        for (int j = 0; j < 8; j++)
            #pragma unroll
            for (int c = 0; c < 4; c++) s[j][c] = 0.f;

        #pragma unroll
        for (int kk = 0; kk < 4; kk++) {
            uint32_t qa[4];
            {
                int row = w * 16 + (lane & 15);
                int ch = kk * 2 + (lane >> 4);
                uint32_t so = (uint32_t)(row * 128 + ((ch ^ (row & 7)) * 16));
                ldsm_x4(sb + AOFF_Q + so, qa);
            }
            uint32_t kb[4][4];
            #pragma unroll
            for (int np = 0; np < 4; np++) {
                int row = np * 16 + (lane & 7) + ((lane & 16) ? 8 : 0);
                int ch = kk * 2 + ((lane >> 3) & 1);
                uint32_t so = (uint32_t)(row * 128 + ((ch ^ (row & 7)) * 16));
                ldsm_x4(base + so, kb[np]);
            }
            #pragma unroll
            for (int j = 0; j < 8; j++)
                mma_f16(s[j], qa, kb[j >> 1][(j & 1) * 2], kb[j >> 1][(j & 1) * 2 + 1]);
        }

        // ---- softmax in place (bias/mask from SMEM) ----
        #pragma unroll
        for (int hh = 0; hh < 2; hh++) {
            int row = w * 16 + (lane >> 2) + hh * 8;
            const float* bsm = (const float*)(smem + AOFF_BIAS + (size_t)row * 272)
                               + (lane & 3) * 2;
            const unsigned char* msm = (const unsigned char*)(smem + AOFF_MASK
                               + (size_t)row * 80) + (lane & 3) * 2;
            float mx = -1e30f;
            #pragma unroll
            for (int j = 0; j < 8; j++) {
                float2 bb = *(const float2*)(bsm + j * 8);
                uchar2 mm = *(const uchar2*)(msm + j * 8);
                float v0 = mm.x ? (s[j][hh*2+0] + bb.x) * 0.125f : -1e30f;
                float v1 = mm.y ? (s[j][hh*2+1] + bb.y) * 0.125f : -1e30f;
                s[j][hh*2+0] = v0; s[j][hh*2+1] = v1;
                mx = fmaxf(mx, fmaxf(v0, v1));
            }
            mx = fmaxf(mx, __shfl_xor_sync(0xffffffffu, mx, 1));
            mx = fmaxf(mx, __shfl_xor_sync(0xffffffffu, mx, 2));
            float mn = fmaxf(m[hh], mx);
            float alpha = __expf(m[hh] - mn);
            m[hh] = mn;
            float rs = 0.f;
            #pragma unroll
            for (int j = 0; j < 8; j++) {
                float e0 = __expf(s[j][hh*2+0] - mn);
                float e1 = __expf(s[j][hh*2+1] - mn);
                s[j][hh*2+0] = e0; s[j][hh*2+1] = e1;
                rs += e0 + e1;
            }
            rs += __shfl_xor_sync(0xffffffffu, rs, 1);
            rs += __shfl_xor_sync(0xffffffffu, rs, 2);
            lsum[hh] = lsum[hh] * alpha + rs;
            #pragma unroll
            for (int j = 0; j < 8; j++) {
                accO[j][hh*2+0] *= alpha;
                accO[j][hh*2+1] *= alpha;
            }
        }

        // ---- O += P @ V ----
        #pragma unroll
        for (int kk = 0; kk < 4; kk++) {
            int j0 = kk * 2, j1 = kk * 2 + 1;
            uint32_t pa[4];
            pa[0] = pack_half2(s[j0][0], s[j0][1]);
            pa[1] = pack_half2(s[j0][2], s[j0][3]);
            pa[2] = pack_half2(s[j1][0], s[j1][1]);
            pa[3] = pack_half2(s[j1][2], s[j1][3]);
            uint32_t vb[4][4];
            #pragma unroll
            for (int np = 0; np < 4; np++) {
                int i = lane >> 3, jj = lane & 7;
                int tok = kk * 16 + (i & 1) * 8 + jj;
                int ch = np * 2 + (i >> 1);
                uint32_t so = (uint32_t)(tok * 128 + ((ch ^ (tok & 7)) * 16));
                ldsm_x4t(base + 8192 + so, vb[np]);
            }
            #pragma unroll
            for (int j = 0; j < 8; j++)
                mma_f16(accO[j], pa, vb[j >> 1][(j & 1) * 2], vb[j >> 1][(j & 1) * 2 + 1]);
        }
        __syncthreads();

        if (kt + 1 < NKT) load_bm(kt + 1);
        if (kt + 2 < NKT) load_kv(kt + 2);
    }

    // ---- epilogue: normalize + fp16 write ----
    #pragma unroll
    for (int hh = 0; hh < 2; hh++) {
        float inv = 1.0f / lsum[hh];
        size_t row = qrow0 + w * 16 + (lane >> 2) + hh * 8;
        #pragma unroll
        for (int j = 0; j < 8; j++) {
            int col = hd * HDIM + j * 8 + (lane & 3) * 2;
            *(uint32_t*)(out16 + row * D + col) =
                pack_half2(accO[j][hh*2+0] * inv, accO[j][hh*2+1] * inv);
        }
    }
}

// ---------------- host launcher --------------------------------------------------
extern "C" void kernel_launch(void* const* d_in, const int* in_sizes, int n_in,
                              void* d_out, int out_size) {
    const float* x     = (const float*)d_in[0];
    const float* bias  = (const float*)d_in[1];
    const int*   mask  = (const int*)d_in[2];
    const float* ln1_w = (const float*)d_in[3];
    const float* ln1_b = (const float*)d_in[4];
    const float* wq    = (const float*)d_in[5];
    const float* bq    = (const float*)d_in[6];
    const float* wk    = (const float*)d_in[7];
    const float* bk    = (const float*)d_in[8];
    const float* wv    = (const float*)d_in[9];
    const float* bv    = (const float*)d_in[10];
    const float* wo    = (const float*)d_in[11];
    const float* bo    = (const float*)d_in[12];
    const float* ln2_w = (const float*)d_in[13];
    const float* ln2_b = (const float*)d_in[14];
    const float* w1    = (const float*)d_in[15];
    const float* b1    = (const float*)d_in[16];
    const float* w2    = (const float*)d_in[17];
    const float* b2    = (const float*)d_in[18];
    float* out = (float*)d_out;

    float *xmid;
    __half *xn16, *q16, *k16, *v16, *a16, *h16, *wt16;
    unsigned char* mask8;
    cudaGetSymbolAddress((void**)&xmid, g_xmid);
    cudaGetSymbolAddress((void**)&xn16, g_xn16);
    cudaGetSymbolAddress((void**)&q16,  g_q16);
    cudaGetSymbolAddress((void**)&k16,  g_k16);
    cudaGetSymbolAddress((void**)&v16,  g_v16);
    cudaGetSymbolAddress((void**)&a16,  g_a16);
    cudaGetSymbolAddress((void**)&h16,  g_h16);
    cudaGetSymbolAddress((void**)&wt16, g_wt16);
    cudaGetSymbolAddress((void**)&mask8, g_mask8);

    cudaFuncSetAttribute(hmma_gemm, cudaFuncAttributeMaxDynamicSharedMemorySize, GSMEM);
    cudaFuncSetAttribute(qkv_gemm,  cudaFuncAttributeMaxDynamicSharedMemorySize, GSMEM);
    cudaFuncSetAttribute(attn_mma,  cudaFuncAttributeMaxDynamicSharedMemorySize, ASMEM);

    dim3 tgrid(24, 24, 6), tblk(32, 8);
    transpose6<<<tgrid, tblk>>>(wq, wk, wv, wo, w1, w2, wt16);
    mask_pack<<<(BATCH*SEQ*SEQ/4 + 255)/256, 256>>>(mask, mask8, BATCH*SEQ*SEQ/4);

    dim3 ggrid(D / NT, NROWS / MT);     // (12, 32)
    dim3 qgrid(3 * D / NT, NROWS / MT); // (36, 32)

    // LN1 -> fp16
    ln_f16<<<NROWS, 256>>>(x, ln1_w, ln1_b, xn16);
    // merged QKV projections
    qkv_gemm<<<qgrid, 256, GSMEM>>>(xn16, wt16, bq, bk, bv, q16, k16, v16);
    // attention (fp16 tensor-core flash, fully cp.async-pipelined)
    dim3 attn_grid(SEQ / 128, NHEADS * BATCH);  // (16, 24)
    attn_mma<<<attn_grid, 256, ASMEM>>>(q16, k16, v16, bias, mask8, a16);
    // out-proj + residual(x) -> xmid (fp32)
    hmma_gemm<<<ggrid, 256, GSMEM>>>(a16, wt16 + 3*(size_t)D*D, bo, x, xmid, nullptr, 0);
    // LN2 -> fp16
    ln_f16<<<NROWS, 256>>>(xmid, ln2_w, ln2_b, xn16);
    // MLP up + ReLU -> fp16 hidden
    hmma_gemm<<<ggrid, 256, GSMEM>>>(xn16, wt16 + 4*(size_t)D*D, b1, nullptr,
                                     nullptr, h16, 1);
    // MLP down + residual(xmid) -> out (fp32)
    hmma_gemm<<<ggrid, 256, GSMEM>>>(h16, wt16 + 5*(size_t)D*D, b2, xmid,
                                     out, nullptr, 0);
}

// round 11
// speedup vs baseline: 5.6575x; 1.0050x over previous
#include <cuda_runtime.h>
#include <cuda_fp16.h>
#include <stdint.h>
#include <math.h>

#define D 768
#define BATCH 2
#define SEQ 2048
#define NROWS (BATCH*SEQ)   // 4096
#define NHEADS 12
#define HDIM 64
#define EPS 1e-5f

#define MT 128              // GEMM CTA M tile
#define NT 128              // GEMM CTA N tile
#define BK 32
#define KSTAGES (D/BK)      // 24

// ---------------- scratch ----------------
__device__ float g_xmid[NROWS*D];
__device__ __half g_xn16[NROWS*D];
__device__ __half g_q16[NROWS*D], g_k16[NROWS*D], g_v16[NROWS*D];
__device__ __half g_a16[NROWS*D];
__device__ __half g_h16[NROWS*D];
__device__ __half g_wt16[6*D*D];
__device__ unsigned char g_mask8[(size_t)BATCH*SEQ*SEQ];

// ---------------- PTX helpers ----------------
__device__ __forceinline__ uint32_t smem_u32(const void* p) {
    uint32_t a;
    asm("{ .reg .u64 t; cvta.to.shared.u64 t, %1; cvt.u32.u64 %0, t; }" : "=r"(a) : "l"(p));
    return a;
}
__device__ __forceinline__ void cp_async16(uint32_t dst, const void* src) {
    asm volatile("cp.async.ca.shared.global [%0], [%1], 16;\n" :: "r"(dst), "l"(src));
}
__device__ __forceinline__ void cp_commit() { asm volatile("cp.async.commit_group;\n"); }
__device__ __forceinline__ void cp_wait0()  { asm volatile("cp.async.wait_group 0;\n" ::: "memory"); }
__device__ __forceinline__ void cp_wait1()  { asm volatile("cp.async.wait_group 1;\n" ::: "memory"); }

__device__ __forceinline__ void ldsm_x4(uint32_t addr, uint32_t* r) {
    asm volatile("ldmatrix.sync.aligned.m8n8.x4.shared.b16 {%0,%1,%2,%3}, [%4];"
                 : "=r"(r[0]), "=r"(r[1]), "=r"(r[2]), "=r"(r[3]) : "r"(addr));
}
__device__ __forceinline__ void ldsm_x4t(uint32_t addr, uint32_t* r) {
    asm volatile("ldmatrix.sync.aligned.m8n8.x4.trans.shared.b16 {%0,%1,%2,%3}, [%4];"
                 : "=r"(r[0]), "=r"(r[1]), "=r"(r[2]), "=r"(r[3]) : "r"(addr));
}
__device__ __forceinline__ void mma_f16(float* c, const uint32_t* a, uint32_t b0, uint32_t b1) {
    asm volatile("mma.sync.aligned.m16n8k16.row.col.f32.f16.f16.f32 "
                 "{%0,%1,%2,%3},{%4,%5,%6,%7},{%8,%9},{%0,%1,%2,%3};"
                 : "+f"(c[0]), "+f"(c[1]), "+f"(c[2]), "+f"(c[3])
                 : "r"(a[0]), "r"(a[1]), "r"(a[2]), "r"(a[3]), "r"(b0), "r"(b1));
}

__device__ __forceinline__ uint32_t pack_half2(float a, float b) {
    __half2 h = __floats2half2_rn(a, b);
    return *(uint32_t*)&h;
}

// ---------------- weight transpose -> fp16 (all 6 in one launch) ----------------
__global__ void transpose6(const float* __restrict__ w0, const float* __restrict__ w1,
                           const float* __restrict__ w2, const float* __restrict__ w3,
                           const float* __restrict__ w4, const float* __restrict__ w5,
                           __half* __restrict__ T16) {
    __shared__ float tile[32][33];
    int z = blockIdx.z;
    const float* W = (z == 0) ? w0 : (z == 1) ? w1 : (z == 2) ? w2
                   : (z == 3) ? w3 : (z == 4) ? w4 : w5;
    __half* t16 = T16 + (size_t)z * D * D;
    int bx = blockIdx.x * 32, by = blockIdx.y * 32;
    int tx = threadIdx.x, ty = threadIdx.y;
    #pragma unroll
    for (int i = 0; i < 4; i++)
        tile[ty + 8*i][tx] = W[(size_t)(by + ty + 8*i) * D + bx + tx];
    __syncthreads();
    #pragma unroll
    for (int i = 0; i < 4; i++) {
        float v = tile[tx][ty + 8*i];
        t16[(size_t)(bx + ty + 8*i) * D + by + tx] = __float2half(v);
    }
}

// ---------------- mask int32 -> int8 ----------------
__global__ void mask_pack(const int* __restrict__ m, unsigned char* __restrict__ m8, int n4) {
    int i = blockIdx.x * blockDim.x + threadIdx.x;
    if (i < n4) {
        int4 v = *(const int4*)(m + (size_t)i * 4);
        uchar4 o;
        o.x = (unsigned char)v.x; o.y = (unsigned char)v.y;
        o.z = (unsigned char)v.z; o.w = (unsigned char)v.w;
        *(uchar4*)(m8 + (size_t)i * 4) = o;
    }
}

// ---------------- LayerNorm -> fp16 ----------------
__global__ void ln_f16(const float* __restrict__ x, const float* __restrict__ w,
                       const float* __restrict__ b, __half* __restrict__ y16) {
    __shared__ float sh_s[8], sh_ss[8];
    __shared__ float mu_sh, rstd_sh;
    int row = blockIdx.x;
    const float* xr = x + (size_t)row * D;
    int t = threadIdx.x;
    float v0 = xr[t], v1 = xr[t + 256], v2 = xr[t + 512];
    float s  = v0 + v1 + v2;
    float ss = v0*v0 + v1*v1 + v2*v2;
    #pragma unroll
    for (int o = 16; o > 0; o >>= 1) {
        s  += __shfl_xor_sync(0xffffffffu, s,  o);
        ss += __shfl_xor_sync(0xffffffffu, ss, o);
    }
    int wid = t >> 5, lane = t & 31;
    if (lane == 0) { sh_s[wid] = s; sh_ss[wid] = ss; }
    __syncthreads();
    if (t == 0) {
        float S = 0.f, SS = 0.f;
        #pragma unroll
        for (int i = 0; i < 8; i++) { S += sh_s[i]; SS += sh_ss[i]; }
        float mu = S / (float)D;
        float var = SS / (float)D - mu * mu;
        mu_sh = mu; rstd_sh = rsqrtf(var + EPS);
    }
    __syncthreads();
    float mu = mu_sh, rs = rstd_sh;
    size_t base = (size_t)row * D;
    #pragma unroll
    for (int i = 0; i < 3; i++) {
        int c = t + 256 * i;
        float v = (i == 0) ? v0 : (i == 1) ? v1 : v2;
        float o = (v - mu) * rs * w[c] + b[c];
        y16[base + c] = __float2half(o);
    }
}

// ---------------- fp16 HMMA GEMM core: CTA 128x128, 8 warps of 64x32 -------------
#define STG 16384
#define OFF_A 0
#define OFF_B 8192
#define GSMEM (2*STG)

__device__ __forceinline__ void gemm_core_f16(
    const __half* __restrict__ A16, const __half* __restrict__ W16,
    const float* __restrict__ bias, const float* __restrict__ res,
    float* __restrict__ Cf, __half* __restrict__ C16,
    int relu, int brow, int bcol, uint32_t sb)
{
    int t = threadIdx.x;
    int wid = t >> 5, lane = t & 31;
    int wm = wid & 1, wn = wid >> 1;   // 2 M halves x 4 N quarters

    float acc[4][4][4];
    #pragma unroll
    for (int i = 0; i < 4; i++)
        #pragma unroll
        for (int j = 0; j < 4; j++)
            #pragma unroll
            for (int c = 0; c < 4; c++) acc[i][j][c] = 0.f;

    auto load_stage = [&](int s) {
        uint32_t base = sb + (uint32_t)((s & 1) * STG);
        int k0 = s * BK;
        #pragma unroll
        for (int i = 0; i < 2; i++) {
            int id = t + i * 256;
            int r = id >> 2, c = id & 3;
            uint32_t so = (uint32_t)(r * 64 + ((c ^ ((r >> 1) & 3)) * 16));
            cp_async16(base + OFF_A + so, A16 + (size_t)(brow + r) * D + k0 + c * 8);
            cp_async16(base + OFF_B + so, W16 + (size_t)(bcol + r) * D + k0 + c * 8);
        }
        cp_commit();
    };

    load_stage(0);

    for (int s = 0; s < KSTAGES; s++) {
        if (s < KSTAGES - 1) load_stage(s + 1);
        if (s < KSTAGES - 1) cp_wait1(); else cp_wait0();
        __syncthreads();

        uint32_t base = sb + (uint32_t)((s & 1) * STG);
        #pragma unroll
        for (int kstep = 0; kstep < 2; kstep++) {
            uint32_t af[4][4];
            #pragma unroll
            for (int mt = 0; mt < 4; mt++) {
                int row = wm * 64 + mt * 16 + (lane & 15);
                int chunk = kstep * 2 + (lane >> 4);
                uint32_t so = (uint32_t)(row * 64 + ((chunk ^ ((row >> 1) & 3)) * 16));
                ldsm_x4(base + OFF_A + so, af[mt]);
            }
            uint32_t bf[2][4];
            #pragma unroll
            for (int nt2 = 0; nt2 < 2; nt2++) {
                int row = wn * 32 + nt2 * 16 + (lane & 7) + ((lane & 16) ? 8 : 0);
                int chunk = kstep * 2 + ((lane >> 3) & 1);
                uint32_t so = (uint32_t)(row * 64 + ((chunk ^ ((row >> 1) & 3)) * 16));
                ldsm_x4(base + OFF_B + so, bf[nt2]);
            }
            #pragma unroll
            for (int mt = 0; mt < 4; mt++)
                #pragma unroll
                for (int nt = 0; nt < 4; nt++)
                    mma_f16(acc[mt][nt], af[mt],
                            bf[nt >> 1][(nt & 1) * 2], bf[nt >> 1][(nt & 1) * 2 + 1]);
        }
        __syncthreads();
    }

    #pragma unroll
    for (int mt = 0; mt < 4; mt++) {
        #pragma unroll
        for (int nt = 0; nt < 4; nt++) {
            float* c = acc[mt][nt];
            int col = bcol + wn * 32 + nt * 8 + (lane & 3) * 2;
            #pragma unroll
            for (int half = 0; half < 2; half++) {
                int row = brow + wm * 64 + mt * 16 + (lane >> 2) + half * 8;
                float2 o;
                o.x = c[half * 2 + 0];
                o.y = c[half * 2 + 1];
                const float2 bb = *(const float2*)(bias + col);
                o.x += bb.x; o.y += bb.y;
                size_t gidx = (size_t)row * D + col;
                if (res) {
                    float2 rv = *(const float2*)(res + gidx);
                    o.x += rv.x; o.y += rv.y;
                }
                if (relu) { o.x = fmaxf(o.x, 0.f); o.y = fmaxf(o.y, 0.f); }
                if (Cf)  *(float2*)(Cf + gidx) = o;
                if (C16) *(uint32_t*)(C16 + gidx) = pack_half2(o.x, o.y);
            }
        }
    }
}

__global__ void __launch_bounds__(256, 2)
hmma_gemm(const __half* __restrict__ A16, const __half* __restrict__ W16,
          const float* __restrict__ bias, const float* __restrict__ res,
          float* __restrict__ Cf, __half* __restrict__ C16, int relu)
{
    extern __shared__ char smem[];
    gemm_core_f16(A16, W16, bias, res, Cf, C16, relu,
                  blockIdx.y * MT, blockIdx.x * NT, smem_u32(smem));
}

// Merged QKV: grid.x = 18 (sel = x/6, col tile = x%6)
__global__ void __launch_bounds__(256, 2)
qkv_gemm(const __half* __restrict__ A16, const __half* __restrict__ Wt16,
         const float* __restrict__ bq, const float* __restrict__ bk, const float* __restrict__ bv,
         __half* __restrict__ q16, __half* __restrict__ k16, __half* __restrict__ v16)
{
    extern __shared__ char smem[];
    int sel = blockIdx.x / 6;
    int bcol = (blockIdx.x % 6) * NT;
    const __half* W = Wt16 + (size_t)sel * D * D;
    const float* bias = (sel == 0) ? bq : (sel == 1) ? bk : bv;
    __half* C16 = (sel == 0) ? q16 : (sel == 1) ? k16 : v16;
    gemm_core_f16(A16, W, bias, nullptr, nullptr, C16, 0,
                  blockIdx.y * MT, bcol, smem_u32(smem));
}

// ---------------- fp16 tensor-core flash attention ----------------
// 128q x 64k tiles, 8 warps. cp.async-pipelined K/V AND bias/mask.
#define AOFF_Q    0
#define AOFF_KV   16384              // + buf*16384 : K(8K) V(8K)
#define AOFF_BIAS 49152              // 128 rows x 272B (64 fp32 + 16B pad)
#define AOFF_MASK 83968              // 128 rows x 80B  (64 u8 + 16B pad)
#define ASMEM     94208

__global__ void __launch_bounds__(256, 2)
attn_mma(const __half* __restrict__ q16, const __half* __restrict__ k16,
         const __half* __restrict__ v16,
         const float* __restrict__ bias, const unsigned char* __restrict__ mask8,
         __half* __restrict__ out16)
{
    extern __shared__ char smem[];
    uint32_t sb = smem_u32(smem);
    int t = threadIdx.x;
    int w = t >> 5, lane = t & 31;

    int qt = blockIdx.x;          // 0..15
    int hb = blockIdx.y;          // 0..23
    int hd = hb >> 1;
    int b  = hb & 1;

    size_t qrow0 = (size_t)b * SEQ + qt * 128;
    const __half* qg = q16 + qrow0 * D + hd * HDIM;
    const __half* kg = k16 + (size_t)b * SEQ * D + hd * HDIM;
    const __half* vg = v16 + (size_t)b * SEQ * D + hd * HDIM;
    const float* biasbase = bias + ((size_t)(hd * BATCH + b) * SEQ + qt * 128) * SEQ;
    const unsigned char* maskbase = mask8 + ((size_t)b * SEQ + qt * 128) * SEQ;

    // Q tile (128x64 fp16), swizzled — its own group
    #pragma unroll
    for (int i = 0; i < 4; i++) {
        int id = t + i * 256;
        int row = id >> 3, c = id & 7;
        uint32_t so = (uint32_t)(row * 128 + ((c ^ (row & 7)) * 16));
        cp_async16(sb + AOFF_Q + so, qg + (size_t)row * D + c * 8);
    }
    cp_commit();

    auto load_kv = [&](int kt) {
        uint32_t base = sb + AOFF_KV + (uint32_t)((kt & 1) * 16384);
        #pragma unroll
        for (int i = 0; i < 2; i++) {
            int id = t + i * 256;
            int row = id >> 3, c = id & 7;
            uint32_t so = (uint32_t)(row * 128 + ((c ^ (row & 7)) * 16));
            size_t g = (size_t)(kt * 64 + row) * D + c * 8;
            cp_async16(base + so,        kg + g);
            cp_async16(base + 8192 + so, vg + g);
        }
        cp_commit();
    };

    auto load_bm = [&](int kt) {
        #pragma unroll
        for (int i = 0; i < 8; i++) {
            int id = t + i * 256;
            int row = id >> 4, c = id & 15;
            cp_async16(sb + AOFF_BIAS + (uint32_t)(row * 272 + c * 16),
                       biasbase + (size_t)row * SEQ + kt * 64 + c * 4);
        }
        #pragma unroll
        for (int i = 0; i < 2; i++) {
            int id = t + i * 256;
            int row = id >> 2, c = id & 3;
            cp_async16(sb + AOFF_MASK + (uint32_t)(row * 80 + c * 16),
                       maskbase + (size_t)row * SEQ + kt * 64 + c * 16);
        }
        cp_commit();
    };

    load_kv(0);
    load_bm(0);
    load_kv(1);

    float accO[8][4];
    #pragma unroll
    for (int j = 0; j < 8; j++)
        #pragma unroll
        for (int c = 0; c < 4; c++) accO[j][c] = 0.f;
    float m[2] = {-1e30f, -1e30f}, lsum[2] = {0.f, 0.f};

    const int NKT = SEQ / 64;   // 32
    for (int kt = 0; kt < NKT; kt++) {
        if (kt < NKT - 1) cp_wait1(); else cp_wait0();
        __syncthreads();

        uint32_t base = sb + AOFF_KV + (uint32_t)((kt & 1) * 16384);

        // ---- S = Q @ K^T ----
        float s[8][4];
        #pragma unroll
        for (int j = 0; j < 8; j++)
            #pragma unroll
            for (int c = 0; c < 4; c++) s[j][c] = 0.f;

        #pragma unroll
        for (int kk = 0; kk < 4; kk++) {
            uint32_t qa[4];
            {
                int row = w * 16 + (lane & 15);
                int ch = kk * 2 + (lane >> 4);
                uint32_t so = (uint32_t)(row * 128 + ((ch ^ (row & 7)) * 16));
                ldsm_x4(sb + AOFF_Q + so, qa);
            }
            uint32_t kb[4][4];
            #pragma unroll
            for (int np = 0; np < 4; np++) {
                int row = np * 16 + (lane & 7) + ((lane & 16) ? 8 : 0);
                int ch = kk * 2 + ((lane >> 3) & 1);
                uint32_t so = (uint32_t)(row * 128 + ((ch ^ (row & 7)) * 16));
                ldsm_x4(base + so, kb[np]);
            }
            #pragma unroll
            for (int j = 0; j < 8; j++)
                mma_f16(s[j], qa, kb[j >> 1][(j & 1) * 2], kb[j >> 1][(j & 1) * 2 + 1]);
        }

        // ---- softmax in place (bias/mask from SMEM) ----
        #pragma unroll
        for (int hh = 0; hh < 2; hh++) {
            int row = w * 16 + (lane >> 2) + hh * 8;
            const float* bsm = (const float*)(smem + AOFF_BIAS + (size_t)row * 272)
                               + (lane & 3) * 2;
            const unsigned char* msm = (const unsigned char*)(smem + AOFF_MASK
                               + (size_t)row * 80) + (lane & 3) * 2;
            float mx = -1e30f;
            #pragma unroll
            for (int j = 0; j < 8; j++) {
                float2 bb = *(const float2*)(bsm + j * 8);
                uchar2 mm = *(const uchar2*)(msm + j * 8);
                float v0 = mm.x ? (s[j][hh*2+0] + bb.x) * 0.125f : -1e30f;
                float v1 = mm.y ? (s[j][hh*2+1] + bb.y) * 0.125f : -1e30f;
                s[j][hh*2+0] = v0; s[j][hh*2+1] = v1;
                mx = fmaxf(mx, fmaxf(v0, v1));
            }
            mx = fmaxf(mx, __shfl_xor_sync(0xffffffffu, mx, 1));
            mx = fmaxf(mx, __shfl_xor_sync(0xffffffffu, mx, 2));
            float mn = fmaxf(m[hh], mx);
            float alpha = __expf(m[hh] - mn);
            m[hh] = mn;
            float rs = 0.f;
            #pragma unroll
            for (int j = 0; j < 8; j++) {
                float e0 = __expf(s[j][hh*2+0] - mn);
                float e1 = __expf(s[j][hh*2+1] - mn);
                s[j][hh*2+0] = e0; s[j][hh*2+1] = e1;
                rs += e0 + e1;
            }
            rs += __shfl_xor_sync(0xffffffffu, rs, 1);
            rs += __shfl_xor_sync(0xffffffffu, rs, 2);
            lsum[hh] = lsum[hh] * alpha + rs;
            #pragma unroll
            for (int j = 0; j < 8; j++) {
                accO[j][hh*2+0] *= alpha;
                accO[j][hh*2+1] *= alpha;
            }
        }

        // ---- O += P @ V ----
        #pragma unroll
        for (int kk = 0; kk < 4; kk++) {
            int j0 = kk * 2, j1 = kk * 2 + 1;
            uint32_t pa[4];
            pa[0] = pack_half2(s[j0][0], s[j0][1]);
            pa[1] = pack_half2(s[j0][2], s[j0][3]);
            pa[2] = pack_half2(s[j1][0], s[j1][1]);
            pa[3] = pack_half2(s[j1][2], s[j1][3]);
            uint32_t vb[4][4];
            #pragma unroll
            for (int np = 0; np < 4; np++) {
                int i = lane >> 3, jj = lane & 7;
                int tok = kk * 16 + (i & 1) * 8 + jj;
                int ch = np * 2 + (i >> 1);
                uint32_t so = (uint32_t)(tok * 128 + ((ch ^ (tok & 7)) * 16));
                ldsm_x4t(base + 8192 + so, vb[np]);
            }
            #pragma unroll
            for (int j = 0; j < 8; j++)
                mma_f16(accO[j], pa, vb[j >> 1][(j & 1) * 2], vb[j >> 1][(j & 1) * 2 + 1]);
        }
        __syncthreads();

        if (kt + 1 < NKT) load_bm(kt + 1);
        if (kt + 2 < NKT) load_kv(kt + 2);
    }

    // ---- epilogue: normalize + fp16 write ----
    #pragma unroll
    for (int hh = 0; hh < 2; hh++) {
        float inv = 1.0f / lsum[hh];
        size_t row = qrow0 + w * 16 + (lane >> 2) + hh * 8;
        #pragma unroll
        for (int j = 0; j < 8; j++) {
            int col = hd * HDIM + j * 8 + (lane & 3) * 2;
            *(uint32_t*)(out16 + row * D + col) =
                pack_half2(accO[j][hh*2+0] * inv, accO[j][hh*2+1] * inv);
        }
    }
}

// ---------------- host launcher --------------------------------------------------
extern "C" void kernel_launch(void* const* d_in, const int* in_sizes, int n_in,
                              void* d_out, int out_size) {
    const float* x     = (const float*)d_in[0];
    const float* bias  = (const float*)d_in[1];
    const int*   mask  = (const int*)d_in[2];
    const float* ln1_w = (const float*)d_in[3];
    const float* ln1_b = (const float*)d_in[4];
    const float* wq    = (const float*)d_in[5];
    const float* bq    = (const float*)d_in[6];
    const float* wk    = (const float*)d_in[7];
    const float* bk    = (const float*)d_in[8];
    const float* wv    = (const float*)d_in[9];
    const float* bv    = (const float*)d_in[10];
    const float* wo    = (const float*)d_in[11];
    const float* bo    = (const float*)d_in[12];
    const float* ln2_w = (const float*)d_in[13];
    const float* ln2_b = (const float*)d_in[14];
    const float* w1    = (const float*)d_in[15];
    const float* b1    = (const float*)d_in[16];
    const float* w2    = (const float*)d_in[17];
    const float* b2    = (const float*)d_in[18];
    float* out = (float*)d_out;

    float *xmid;
    __half *xn16, *q16, *k16, *v16, *a16, *h16, *wt16;
    unsigned char* mask8;
    cudaGetSymbolAddress((void**)&xmid, g_xmid);
    cudaGetSymbolAddress((void**)&xn16, g_xn16);
    cudaGetSymbolAddress((void**)&q16,  g_q16);
    cudaGetSymbolAddress((void**)&k16,  g_k16);
    cudaGetSymbolAddress((void**)&v16,  g_v16);
    cudaGetSymbolAddress((void**)&a16,  g_a16);
    cudaGetSymbolAddress((void**)&h16,  g_h16);
    cudaGetSymbolAddress((void**)&wt16, g_wt16);
    cudaGetSymbolAddress((void**)&mask8, g_mask8);

    cudaFuncSetAttribute(hmma_gemm, cudaFuncAttributeMaxDynamicSharedMemorySize, GSMEM);
    cudaFuncSetAttribute(qkv_gemm,  cudaFuncAttributeMaxDynamicSharedMemorySize, GSMEM);
    cudaFuncSetAttribute(attn_mma,  cudaFuncAttributeMaxDynamicSharedMemorySize, ASMEM);

    dim3 tgrid(24, 24, 6), tblk(32, 8);
    transpose6<<<tgrid, tblk>>>(wq, wk, wv, wo, w1, w2, wt16);
    mask_pack<<<(BATCH*SEQ*SEQ/4 + 255)/256, 256>>>(mask, mask8, BATCH*SEQ*SEQ/4);

    dim3 ggrid(D / NT, NROWS / MT);     // (6, 32) = 192
    dim3 qgrid(3 * D / NT, NROWS / MT); // (18, 32) = 576

    // LN1 -> fp16
    ln_f16<<<NROWS, 256>>>(x, ln1_w, ln1_b, xn16);
    // merged QKV projections
    qkv_gemm<<<qgrid, 256, GSMEM>>>(xn16, wt16, bq, bk, bv, q16, k16, v16);
    // attention (fp16 tensor-core flash, fully cp.async-pipelined)
    dim3 attn_grid(SEQ / 128, NHEADS * BATCH);  // (16, 24)
    attn_mma<<<attn_grid, 256, ASMEM>>>(q16, k16, v16, bias, mask8, a16);
    // out-proj + residual(x) -> xmid (fp32)
    hmma_gemm<<<ggrid, 256, GSMEM>>>(a16, wt16 + 3*(size_t)D*D, bo, x, xmid, nullptr, 0);
    // LN2 -> fp16
    ln_f16<<<NROWS, 256>>>(xmid, ln2_w, ln2_b, xn16);
    // MLP up + ReLU -> fp16 hidden
    hmma_gemm<<<ggrid, 256, GSMEM>>>(xn16, wt16 + 4*(size_t)D*D, b1, nullptr,
                                     nullptr, h16, 1);
    // MLP down + residual(xmid) -> out (fp32)
    hmma_gemm<<<ggrid, 256, GSMEM>>>(h16, wt16 + 5*(size_t)D*D, b2, xmid,
                                     out, nullptr, 0);
}